// round 12
// baseline (speedup 1.0000x reference)
#include <cuda_runtime.h>
#include <cuda_bf16.h>
#include <cuda_fp16.h>
#include <math.h>
#include <math_constants.h>
#include <stdint.h>

// Problem constants
#define BSZ   2
#define TSEQ  2048
#define DIM   2048
#define NH    16
#define NHKV  4
#define HD    128
#define KVDIM (NHKV*HD)     // 512
#define GROUP (NH/NHKV)     // 4
#define RANK  16
#define BT    (BSZ*TSEQ)    // 4096
#define QKVD  (DIM + 2*KVDIM)   // 3072
#define KOFF  DIM               // 2048
#define VOFF  (DIM + KVDIM)     // 2560

// ---------------- scratch (device globals; no allocation allowed) ----------
__device__ __nv_bfloat16 g_WqkvTh[QKVD*DIM], g_WqkvTl[QKVD*DIM];  // [3072][2048]
__device__ __nv_bfloat16 g_WpTh[DIM*DIM],    g_WpTl[DIM*DIM];
__device__ __nv_bfloat16 g_xh[BT*DIM],  g_xl[BT*DIM];
__device__ __nv_bfloat16 g_yh[BT*DIM],  g_yl[BT*DIM];
__device__ float  g_qkv[BT*QKVD];
__device__ float  g_y[BT*DIM];
__device__ __half g_qh[BT*DIM];                    // fp16 q (normed+rope+gain)
__device__ __half g_kh[BT*KVDIM];                  // fp16 k (normed+rope)
__device__ __half g_vth[BSZ*NHKV*HD*TSEQ];         // fp16 V transposed [b][kh][hd][t]

// ---- effective weights pair (W + A@B), transposed + split (2 per launch) --
__global__ void effw_pair_kernel(
    const float* __restrict__ W0, const float* __restrict__ A0, const float* __restrict__ B0,
    __nv_bfloat16* __restrict__ H0, __nv_bfloat16* __restrict__ L0, int N0,
    const float* __restrict__ W1, const float* __restrict__ A1, const float* __restrict__ B1,
    __nv_bfloat16* __restrict__ H1, __nv_bfloat16* __restrict__ L1, int N1)
{
    __shared__ float tile[32][33];
    const float *W, *A, *Bm;
    __nv_bfloat16 *H, *L;
    int N;
    if (blockIdx.z == 0) { W=W0; A=A0; Bm=B0; H=H0; L=L0; N=N0; }
    else                 { W=W1; A=A1; Bm=B1; H=H1; L=L1; N=N1; }
    int tn = blockIdx.x * 32;
    if (tn >= N) return;
    int tk = blockIdx.y * 32;
    int tx = threadIdx.x, ty = threadIdx.y;   // 32 x 8

    #pragma unroll
    for (int i = 0; i < 4; i++) {
        int k = tk + ty + i*8;
        int n = tn + tx;
        float s = W[(size_t)k * N + n];
        #pragma unroll
        for (int r = 0; r < RANK; r++)
            s += A[k*RANK + r] * Bm[r*N + n];
        tile[ty + i*8][tx] = s;
    }
    __syncthreads();
    #pragma unroll
    for (int i = 0; i < 4; i++) {
        int n = tn + ty + i*8;
        int k = tk + tx;
        float s = tile[tx][ty + i*8];
        __nv_bfloat16 h = __float2bfloat16_rn(s);
        H[(size_t)n * DIM + k] = h;
        L[(size_t)n * DIM + k] = __float2bfloat16_rn(s - __bfloat162float(h));
    }
}

// ---- split fp32 activation into bf16 hi/lo (vectorized) --------------------
__global__ void split_kernel(const float* __restrict__ X, int count4,
                             __nv_bfloat16* __restrict__ H,
                             __nv_bfloat16* __restrict__ L)
{
    int idx = blockIdx.x * blockDim.x + threadIdx.x;
    if (idx >= count4) return;
    float4 v = ((const float4*)X)[idx];
    __nv_bfloat16 h0 = __float2bfloat16_rn(v.x), h1 = __float2bfloat16_rn(v.y);
    __nv_bfloat16 h2 = __float2bfloat16_rn(v.z), h3 = __float2bfloat16_rn(v.w);
    __nv_bfloat162 hh0 = {h0, h1}, hh1 = {h2, h3};
    __nv_bfloat162 ll0 = {__float2bfloat16_rn(v.x - __bfloat162float(h0)),
                          __float2bfloat16_rn(v.y - __bfloat162float(h1))};
    __nv_bfloat162 ll1 = {__float2bfloat16_rn(v.z - __bfloat162float(h2)),
                          __float2bfloat16_rn(v.w - __bfloat162float(h3))};
    ((__nv_bfloat162*)H)[idx*2]   = hh0;
    ((__nv_bfloat162*)H)[idx*2+1] = hh1;
    ((__nv_bfloat162*)L)[idx*2]   = ll0;
    ((__nv_bfloat162*)L)[idx*2+1] = ll1;
}

// ---------------- bf16x3 tensor-core GEMM (256 threads, 8 warps) -----------
#define TBM 128
#define TBN 128
#define TBK 32
#define STR 40

__device__ __forceinline__ void cpa16(uint32_t dst, const void* src) {
    asm volatile("cp.async.cg.shared.global [%0], [%1], 16;\n" :: "r"(dst), "l"(src));
}
__device__ __forceinline__ void cpa_commit() {
    asm volatile("cp.async.commit_group;\n");
}
__device__ __forceinline__ void cpa_wait0() {
    asm volatile("cp.async.wait_group 0;\n");
}
__device__ __forceinline__ void mma_bf16(float& d0, float& d1, float& d2, float& d3,
                                         uint32_t a0, uint32_t a1, uint32_t a2, uint32_t a3,
                                         uint32_t b0, uint32_t b1) {
    asm volatile(
        "mma.sync.aligned.m16n8k16.row.col.f32.bf16.bf16.f32 "
        "{%0,%1,%2,%3}, {%4,%5,%6,%7}, {%8,%9}, {%0,%1,%2,%3};\n"
        : "+f"(d0), "+f"(d1), "+f"(d2), "+f"(d3)
        : "r"(a0), "r"(a1), "r"(a2), "r"(a3), "r"(b0), "r"(b1));
}
__device__ __forceinline__ void mma_f16(float& d0, float& d1, float& d2, float& d3,
                                        uint32_t a0, uint32_t a1, uint32_t a2, uint32_t a3,
                                        uint32_t b0, uint32_t b1) {
    asm volatile(
        "mma.sync.aligned.m16n8k16.row.col.f32.f16.f16.f32 "
        "{%0,%1,%2,%3}, {%4,%5,%6,%7}, {%8,%9}, {%0,%1,%2,%3};\n"
        : "+f"(d0), "+f"(d1), "+f"(d2), "+f"(d3)
        : "r"(a0), "r"(a1), "r"(a2), "r"(a3), "r"(b0), "r"(b1));
}

template<int N, int K>
__global__ __launch_bounds__(256, 2)
void bf16x3gemm_kernel(const __nv_bfloat16* __restrict__ Ah,
                       const __nv_bfloat16* __restrict__ Al,
                       const __nv_bfloat16* __restrict__ Bh,   // [N][K]
                       const __nv_bfloat16* __restrict__ Bl,
                       float* __restrict__ C)
{
    extern __shared__ __nv_bfloat16 smem[];
    __nv_bfloat16* sAh = smem;
    __nv_bfloat16* sAl = sAh + 2*TBM*STR;
    __nv_bfloat16* sBh = sAl + 2*TBM*STR;
    __nv_bfloat16* sBl = sBh + 2*TBN*STR;

    int tid  = threadIdx.x;
    int warp = tid >> 5, lane = tid & 31;
    int warpM = warp >> 2, warpN = warp & 3;    // 2 x 4 warp grid
    int gid = lane >> 2, tig = lane & 3;

    const __nv_bfloat16* Ahb = Ah + (size_t)blockIdx.y * TBM * K;
    const __nv_bfloat16* Alb = Al + (size_t)blockIdx.y * TBM * K;
    const __nv_bfloat16* Bhb = Bh + (size_t)blockIdx.x * TBN * K;
    const __nv_bfloat16* Blb = Bl + (size_t)blockIdx.x * TBN * K;
    float* Cb = C + (size_t)blockIdx.y * TBM * N + (size_t)blockIdx.x * TBN;

    int srow = tid >> 2;            // 0..63
    int scol = (tid & 3) * 8;

    uint32_t uAh = (uint32_t)__cvta_generic_to_shared(sAh);
    uint32_t uAl = (uint32_t)__cvta_generic_to_shared(sAl);
    uint32_t uBh = (uint32_t)__cvta_generic_to_shared(sBh);
    uint32_t uBl = (uint32_t)__cvta_generic_to_shared(sBl);

    float acc[4][4][4];
    #pragma unroll
    for (int m = 0; m < 4; m++)
        #pragma unroll
        for (int n = 0; n < 4; n++)
            #pragma unroll
            for (int i = 0; i < 4; i++) acc[m][n][i] = 0.0f;

    constexpr int ntiles = K / TBK;

    auto issue = [&](int buf, int kt) {
        uint32_t bofs = (uint32_t)(buf * TBM * STR * 2);
        #pragma unroll
        for (int i = 0; i < 2; i++) {
            int r = srow + i * 64;
            uint32_t dofs = (uint32_t)((r * STR + scol) * 2);
            size_t gofs = (size_t)r * K + (size_t)kt * TBK + scol;
            cpa16(uAh + bofs + dofs, Ahb + gofs);
            cpa16(uAl + bofs + dofs, Alb + gofs);
            cpa16(uBh + bofs + dofs, Bhb + gofs);
            cpa16(uBl + bofs + dofs, Blb + gofs);
        }
        cpa_commit();
    };

    issue(0, 0);
    int buf = 0;

    for (int kt = 0; kt < ntiles; kt++) {
        cpa_wait0();
        __syncthreads();
        if (kt + 1 < ntiles) issue(buf ^ 1, kt + 1);

        const __nv_bfloat16* Ahs = sAh + buf * TBM * STR;
        const __nv_bfloat16* Als = sAl + buf * TBM * STR;
        const __nv_bfloat16* Bhs = sBh + buf * TBN * STR;
        const __nv_bfloat16* Bls = sBl + buf * TBN * STR;

        #pragma unroll
        for (int ks = 0; ks < TBK; ks += 16) {
            uint32_t afh[4][4], afl[4][4];
            #pragma unroll
            for (int mt = 0; mt < 4; mt++) {
                int r0 = warpM*64 + mt*16;
                const __nv_bfloat16* ah = Ahs + (size_t)r0 * STR + ks;
                const __nv_bfloat16* al = Als + (size_t)r0 * STR + ks;
                afh[mt][0] = *(const uint32_t*)(ah + (size_t) gid      * STR + 2*tig);
                afh[mt][1] = *(const uint32_t*)(ah + (size_t)(gid + 8) * STR + 2*tig);
                afh[mt][2] = *(const uint32_t*)(ah + (size_t) gid      * STR + 2*tig + 8);
                afh[mt][3] = *(const uint32_t*)(ah + (size_t)(gid + 8) * STR + 2*tig + 8);
                afl[mt][0] = *(const uint32_t*)(al + (size_t) gid      * STR + 2*tig);
                afl[mt][1] = *(const uint32_t*)(al + (size_t)(gid + 8) * STR + 2*tig);
                afl[mt][2] = *(const uint32_t*)(al + (size_t) gid      * STR + 2*tig + 8);
                afl[mt][3] = *(const uint32_t*)(al + (size_t)(gid + 8) * STR + 2*tig + 8);
            }
            uint32_t bfh[4][2], bfl[4][2];
            #pragma unroll
            for (int nt = 0; nt < 4; nt++) {
                int n0 = warpN*32 + nt*8 + gid;
                const __nv_bfloat16* bh = Bhs + (size_t)n0 * STR + ks;
                const __nv_bfloat16* bl = Bls + (size_t)n0 * STR + ks;
                bfh[nt][0] = *(const uint32_t*)(bh + 2*tig);
                bfh[nt][1] = *(const uint32_t*)(bh + 2*tig + 8);
                bfl[nt][0] = *(const uint32_t*)(bl + 2*tig);
                bfl[nt][1] = *(const uint32_t*)(bl + 2*tig + 8);
            }
            #pragma unroll
            for (int mt = 0; mt < 4; mt++)
                #pragma unroll
                for (int nt = 0; nt < 4; nt++) {
                    mma_bf16(acc[mt][nt][0], acc[mt][nt][1], acc[mt][nt][2], acc[mt][nt][3],
                             afh[mt][0], afh[mt][1], afh[mt][2], afh[mt][3],
                             bfh[nt][0], bfh[nt][1]);
                    mma_bf16(acc[mt][nt][0], acc[mt][nt][1], acc[mt][nt][2], acc[mt][nt][3],
                             afh[mt][0], afh[mt][1], afh[mt][2], afh[mt][3],
                             bfl[nt][0], bfl[nt][1]);
                    mma_bf16(acc[mt][nt][0], acc[mt][nt][1], acc[mt][nt][2], acc[mt][nt][3],
                             afl[mt][0], afl[mt][1], afl[mt][2], afl[mt][3],
                             bfh[nt][0], bfh[nt][1]);
                }
        }
        __syncthreads();
        buf ^= 1;
    }

    #pragma unroll
    for (int mt = 0; mt < 4; mt++) {
        int r0 = warpM*64 + mt*16 + gid;
        #pragma unroll
        for (int nt = 0; nt < 4; nt++) {
            int c0 = warpN*32 + nt*8 + tig*2;
            *(float2*)(Cb + (size_t) r0      * N + c0) = make_float2(acc[mt][nt][0], acc[mt][nt][1]);
            *(float2*)(Cb + (size_t)(r0 + 8) * N + c0) = make_float2(acc[mt][nt][2], acc[mt][nt][3]);
        }
    }
}

// ---- RMSnorm + RoPE (+gain), q and k fused, fp16 output --------------------
__global__ void normrope_h_kernel(const float* __restrict__ QKV,
                                  const float* __restrict__ gain,
                                  __half* __restrict__ Qh,
                                  __half* __restrict__ Kh)
{
    int gthr = blockIdx.x * blockDim.x + threadIdx.x;
    int w    = gthr >> 5;
    int lane = gthr & 31;
    int total = BT * (NH + NHKV);
    if (w >= total) return;

    const float* src;
    __half* dst;
    float g = 1.0f;
    int bt;
    if (w < BT * NH) {
        bt = w / NH;
        int hh = w % NH;
        src = QKV + (size_t)bt * QKVD + hh * HD;
        dst = Qh  + (size_t)bt * DIM  + hh * HD;
        g = gain[hh];
    } else {
        int w2 = w - BT * NH;
        bt = w2 / NHKV;
        int hh = w2 % NHKV;
        src = QKV + (size_t)bt * QKVD + KOFF + hh * HD;
        dst = Kh  + (size_t)bt * KVDIM + hh * HD;
    }
    int t = bt % TSEQ;

    float v0 = src[lane], v1 = src[lane+32], v2 = src[lane+64], v3 = src[lane+96];
    float ss = v0*v0 + v1*v1 + v2*v2 + v3*v3;
    #pragma unroll
    for (int o = 16; o; o >>= 1) ss += __shfl_xor_sync(0xffffffffu, ss, o);

    float f = rsqrtf(ss * (1.0f/128.0f) + 1.1920929e-7f) * g;

    float invfreq = powf(10000.0f, -(float)lane * (1.0f/32.0f));
    float ang = (float)t * invfreq;
    float s, c;
    sincosf(ang, &s, &c);

    dst[lane]    = __float2half(( v0*c + v1*s) * f);
    dst[lane+32] = __float2half((-v0*s + v1*c) * f);
    dst[lane+64] = __float2half(v2 * f);
    dst[lane+96] = __float2half(v3 * f);
}

// ---- V transpose to fp16: Vt[b][kh][hd][t] ---------------------------------
__global__ void vtrans_kernel(const float* __restrict__ QKV,
                              __half* __restrict__ Vt)
{
    __shared__ float tile[32][33];
    int bk = blockIdx.z;                 // b*NHKV + kh
    int b  = bk / NHKV, kh = bk % NHKV;
    int t0 = blockIdx.x * 32;
    int c0 = blockIdx.y * 32;
    int tx = threadIdx.x, ty = threadIdx.y;   // 32 x 8

    #pragma unroll
    for (int i = 0; i < 4; i++) {
        int t = t0 + ty + i*8;
        tile[ty + i*8][tx] = QKV[(size_t)(b*TSEQ + t) * QKVD + VOFF + kh*HD + c0 + tx];
    }
    __syncthreads();
    #pragma unroll
    for (int i = 0; i < 4; i++) {
        int c = c0 + ty + i*8;
        Vt[((size_t)bk * HD + c) * TSEQ + t0 + tx] = __float2half(tile[tx][ty + i*8]);
    }
}

// ---------------- fp16 tensor-core causal flash attention (v2) -------------
#define AQ   128
#define AK   64
#define QSTR 136
#define KSTR 136
#define VSTR 72
#define K_TILE_B  (AK*KSTR*2)   // 17408
#define V_TILE_B  (HD*VSTR*2)   // 18432
#define ATT_SMEM_H (AQ*QSTR*2 + 2*K_TILE_B + 2*V_TILE_B)   // 106496 bytes

__global__ __launch_bounds__(256)
void attn_mma_kernel(const __half* __restrict__ Qh,
                     const __half* __restrict__ Kh,
                     const __half* __restrict__ Vth,
                     float* __restrict__ Y)
{
    extern __shared__ __half smh[];
    __half* Qs  = smh;                    // [AQ][QSTR]
    __half* Ksm = Qs + AQ*QSTR;           // 2 x [AK][KSTR]
    __half* Vsm = Ksm + 2*AK*KSTR;        // 2 x [HD][VSTR]

    int qt = blockIdx.x, h = blockIdx.y, b = blockIdx.z;
    int kh = h / GROUP;
    int q0 = qt * AQ;
    int tid = threadIdx.x;
    int warp = tid >> 5, lane = tid & 31;
    int gid = lane >> 2, tig = lane & 3;
    int wr = warp * 16;

    const float scale = 0.08838834764831845f;  // 128^-0.5

    uint32_t uK = (uint32_t)__cvta_generic_to_shared(Ksm);
    uint32_t uV = (uint32_t)__cvta_generic_to_shared(Vsm);

    for (int e = tid; e < AQ*16; e += 256) {
        int r = e >> 4, c = e & 15;
        *(uint4*)(Qs + r*QSTR + c*8) =
            *(const uint4*)(Qh + (size_t)(b*TSEQ + q0 + r)*DIM + h*HD + c*8);
    }

    const __half* Kbase = Kh  + (size_t)(b*TSEQ)*KVDIM + kh*HD;
    const __half* Vbase = Vth + ((size_t)(b*NHKV + kh))*HD*TSEQ;

    int kr  = tid >> 2;
    int kcb = (tid & 3) * 4;
    int vr  = tid >> 1;
    int vcb = (tid & 1) * 4;
    auto prefetch = [&](int s, int kt) {
        int s0 = kt * AK;
        uint32_t kd = uK + (uint32_t)s * K_TILE_B;
        const __half* ksrc = Kbase + (size_t)(s0 + kr) * KVDIM;
        #pragma unroll
        for (int j = 0; j < 4; j++)
            cpa16(kd + (uint32_t)(kr*KSTR + (kcb+j)*8)*2, ksrc + (kcb+j)*8);
        uint32_t vd = uV + (uint32_t)s * V_TILE_B;
        const __half* vsrc = Vbase + (size_t)vr * TSEQ + s0;
        #pragma unroll
        for (int j = 0; j < 4; j++)
            cpa16(vd + (uint32_t)(vr*VSTR + (vcb+j)*8)*2, vsrc + (vcb+j)*8);
        cpa_commit();
    };

    float m0 = -CUDART_INF_F, m1 = -CUDART_INF_F;
    float l0 = 0.0f, l1 = 0.0f;
    float o[16][4];
    #pragma unroll
    for (int on = 0; on < 16; on++)
        #pragma unroll
        for (int i = 0; i < 4; i++) o[on][i] = 0.0f;

    int nkt = 2*qt + 2;
    prefetch(0, 0);

    for (int kt = 0; kt < nkt; kt++) {
        int s0 = kt * AK;
        cpa_wait0();
        __syncthreads();
        if (kt + 1 < nkt) prefetch((kt + 1) & 1, kt + 1);

        const __half* Ks = Ksm + (kt & 1) * AK*KSTR;
        const __half* Vt = Vsm + (kt & 1) * HD*VSTR;

        float sacc[8][4];
        #pragma unroll
        for (int nt = 0; nt < 8; nt++)
            #pragma unroll
            for (int i = 0; i < 4; i++) sacc[nt][i] = 0.0f;

        #pragma unroll
        for (int ks = 0; ks < 8; ks++) {
            const __half* qb = Qs + (wr + gid)*QSTR + ks*16 + 2*tig;
            uint32_t a0 = *(const uint32_t*)(qb);
            uint32_t a1 = *(const uint32_t*)(qb + 8*QSTR);
            uint32_t a2 = *(const uint32_t*)(qb + 8);
            uint32_t a3 = *(const uint32_t*)(qb + 8*QSTR + 8);
            #pragma unroll
            for (int nt = 0; nt < 8; nt++) {
                const __half* kb = Ks + (nt*8 + gid)*KSTR + ks*16 + 2*tig;
                uint32_t b0 = *(const uint32_t*)(kb);
                uint32_t b1 = *(const uint32_t*)(kb + 8);
                mma_f16(sacc[nt][0], sacc[nt][1], sacc[nt][2], sacc[nt][3],
                        a0, a1, a2, a3, b0, b1);
            }
        }

        #pragma unroll
        for (int nt = 0; nt < 8; nt++)
            #pragma unroll
            for (int i = 0; i < 4; i++) sacc[nt][i] *= scale;

        if (s0 + AK - 1 > q0 + wr) {
            int r0g = q0 + wr + gid;
            #pragma unroll
            for (int nt = 0; nt < 8; nt++) {
                int sb = s0 + nt*8 + 2*tig;
                if (sb     > r0g)     sacc[nt][0] = -CUDART_INF_F;
                if (sb + 1 > r0g)     sacc[nt][1] = -CUDART_INF_F;
                if (sb     > r0g + 8) sacc[nt][2] = -CUDART_INF_F;
                if (sb + 1 > r0g + 8) sacc[nt][3] = -CUDART_INF_F;
            }
        }

        float mx0 = -CUDART_INF_F, mx1 = -CUDART_INF_F;
        #pragma unroll
        for (int nt = 0; nt < 8; nt++) {
            mx0 = fmaxf(mx0, fmaxf(sacc[nt][0], sacc[nt][1]));
            mx1 = fmaxf(mx1, fmaxf(sacc[nt][2], sacc[nt][3]));
        }
        #pragma unroll
        for (int off = 1; off <= 2; off <<= 1) {
            mx0 = fmaxf(mx0, __shfl_xor_sync(0xffffffffu, mx0, off));
            mx1 = fmaxf(mx1, __shfl_xor_sync(0xffffffffu, mx1, off));
        }
        float mn0 = fmaxf(m0, mx0), mn1 = fmaxf(m1, mx1);
        float corr0 = __expf(m0 - mn0), corr1 = __expf(m1 - mn1);
        m0 = mn0; m1 = mn1;

        float sum0 = 0.0f, sum1 = 0.0f;
        #pragma unroll
        for (int nt = 0; nt < 8; nt++) {
            sacc[nt][0] = __expf(sacc[nt][0] - mn0);
            sacc[nt][1] = __expf(sacc[nt][1] - mn0);
            sacc[nt][2] = __expf(sacc[nt][2] - mn1);
            sacc[nt][3] = __expf(sacc[nt][3] - mn1);
            sum0 += sacc[nt][0] + sacc[nt][1];
            sum1 += sacc[nt][2] + sacc[nt][3];
        }
        #pragma unroll
        for (int off = 1; off <= 2; off <<= 1) {
            sum0 += __shfl_xor_sync(0xffffffffu, sum0, off);
            sum1 += __shfl_xor_sync(0xffffffffu, sum1, off);
        }
        l0 = l0 * corr0 + sum0;
        l1 = l1 * corr1 + sum1;

        #pragma unroll
        for (int on = 0; on < 16; on++) {
            o[on][0] *= corr0; o[on][1] *= corr0;
            o[on][2] *= corr1; o[on][3] *= corr1;
        }

        #pragma unroll
        for (int ks2 = 0; ks2 < 4; ks2++) {
            __half2 pa0 = __floats2half2_rn(sacc[2*ks2][0],   sacc[2*ks2][1]);
            __half2 pa1 = __floats2half2_rn(sacc[2*ks2][2],   sacc[2*ks2][3]);
            __half2 pa2 = __floats2half2_rn(sacc[2*ks2+1][0], sacc[2*ks2+1][1]);
            __half2 pa3 = __floats2half2_rn(sacc[2*ks2+1][2], sacc[2*ks2+1][3]);
            uint32_t a0 = *reinterpret_cast<uint32_t*>(&pa0);
            uint32_t a1 = *reinterpret_cast<uint32_t*>(&pa1);
            uint32_t a2 = *reinterpret_cast<uint32_t*>(&pa2);
            uint32_t a3 = *reinterpret_cast<uint32_t*>(&pa3);
            #pragma unroll
            for (int on = 0; on < 16; on++) {
                const __half* vb = Vt + (on*8 + gid)*VSTR + ks2*16 + 2*tig;
                uint32_t b0 = *(const uint32_t*)(vb);
                uint32_t b1 = *(const uint32_t*)(vb + 8);
                mma_f16(o[on][0], o[on][1], o[on][2], o[on][3],
                        a0, a1, a2, a3, b0, b1);
            }
        }
    }

    float il0 = 1.0f / l0, il1 = 1.0f / l1;
    int r0 = q0 + wr + gid;
    #pragma unroll
    for (int on = 0; on < 16; on++) {
        int c0 = h*HD + on*8 + 2*tig;
        *(float2*)(Y + (size_t)(b*TSEQ + r0)     * DIM + c0) = make_float2(o[on][0]*il0, o[on][1]*il0);
        *(float2*)(Y + (size_t)(b*TSEQ + r0 + 8) * DIM + c0) = make_float2(o[on][2]*il1, o[on][3]*il1);
    }
}

// ---- v-direction projection removal, fused with bf16 hi/lo split ----------
__global__ void vproj_split_kernel(const float* __restrict__ V, int vstride,
                                   const float* __restrict__ Yin,
                                   __nv_bfloat16* __restrict__ YH,
                                   __nv_bfloat16* __restrict__ YL)
{
    int gthr = blockIdx.x * blockDim.x + threadIdx.x;
    int w    = gthr >> 5;
    int lane = gthr & 31;
    if (w >= BT * NHKV) return;
    int bt = w / NHKV, kh = w % NHKV;

    const float* vrow = V + (size_t)bt * vstride + kh * HD;
    float v0 = vrow[lane], v1 = vrow[lane+32], v2 = vrow[lane+64], v3 = vrow[lane+96];
    float ss = v0*v0 + v1*v1 + v2*v2 + v3*v3;
    #pragma unroll
    for (int o = 16; o; o >>= 1) ss += __shfl_xor_sync(0xffffffffu, ss, o);
    float norm = sqrtf(ss);
    float inv = 1.0f / fmaxf(norm, 1e-12f);
    float n0 = v0*inv, n1 = v1*inv, n2 = v2*inv, n3 = v3*inv;

    #pragma unroll
    for (int g = 0; g < GROUP; g++) {
        int hh = kh * GROUP + g;
        size_t base = (size_t)bt * DIM + hh * HD;
        const float* yrow = Yin + base;
        float y0 = yrow[lane], y1 = yrow[lane+32], y2 = yrow[lane+64], y3 = yrow[lane+96];
        float d = y0*n0 + y1*n1 + y2*n2 + y3*n3;
        #pragma unroll
        for (int o = 16; o; o >>= 1) d += __shfl_xor_sync(0xffffffffu, d, o);
        float r0 = y0 - d*n0, r1 = y1 - d*n1, r2 = y2 - d*n2, r3 = y3 - d*n3;

        __nv_bfloat16 h0 = __float2bfloat16_rn(r0), h1 = __float2bfloat16_rn(r1);
        __nv_bfloat16 h2 = __float2bfloat16_rn(r2), h3 = __float2bfloat16_rn(r3);
        YH[base + lane]    = h0;  YL[base + lane]    = __float2bfloat16_rn(r0 - __bfloat162float(h0));
        YH[base + lane+32] = h1;  YL[base + lane+32] = __float2bfloat16_rn(r1 - __bfloat162float(h1));
        YH[base + lane+64] = h2;  YL[base + lane+64] = __float2bfloat16_rn(r2 - __bfloat162float(h2));
        YH[base + lane+96] = h3;  YL[base + lane+96] = __float2bfloat16_rn(r3 - __bfloat162float(h3));
    }
}

// ---------------- launcher --------------------------------------------------
extern "C" void kernel_launch(void* const* d_in, const int* in_sizes, int n_in,
                              void* d_out, int out_size)
{
    const float* x     = (const float*)d_in[0];
    const float* Wq    = (const float*)d_in[1];
    const float* Wk    = (const float*)d_in[2];
    const float* Wv    = (const float*)d_in[3];
    const float* Wp    = (const float*)d_in[4];
    const float* qgain = (const float*)d_in[5];
    const float* qA    = (const float*)d_in[6];
    const float* qB    = (const float*)d_in[7];
    const float* kA    = (const float*)d_in[8];
    const float* kB    = (const float*)d_in[9];
    const float* vA    = (const float*)d_in[10];
    const float* vB    = (const float*)d_in[11];
    const float* pA    = (const float*)d_in[12];
    const float* pB    = (const float*)d_in[13];
    float* out = (float*)d_out;

    __nv_bfloat16 *wh, *wl, *wph, *wpl, *xh, *xl, *yh, *yl;
    float *qkv, *y;
    __half *qh, *kh2, *vth;
    cudaGetSymbolAddress((void**)&wh,  g_WqkvTh); cudaGetSymbolAddress((void**)&wl,  g_WqkvTl);
    cudaGetSymbolAddress((void**)&wph, g_WpTh);   cudaGetSymbolAddress((void**)&wpl, g_WpTl);
    cudaGetSymbolAddress((void**)&xh,  g_xh);     cudaGetSymbolAddress((void**)&xl,  g_xl);
    cudaGetSymbolAddress((void**)&yh,  g_yh);     cudaGetSymbolAddress((void**)&yl,  g_yl);
    cudaGetSymbolAddress((void**)&qkv, g_qkv);
    cudaGetSymbolAddress((void**)&y,   g_y);
    cudaGetSymbolAddress((void**)&qh,  g_qh);
    cudaGetSymbolAddress((void**)&kh2, g_kh);
    cudaGetSymbolAddress((void**)&vth, g_vth);

    const int GSMEM = (8*TBM*STR) * (int)sizeof(__nv_bfloat16);
    cudaFuncSetAttribute(bf16x3gemm_kernel<QKVD, DIM>, cudaFuncAttributeMaxDynamicSharedMemorySize, GSMEM);
    cudaFuncSetAttribute(bf16x3gemm_kernel<DIM, DIM>,  cudaFuncAttributeMaxDynamicSharedMemorySize, GSMEM);
    cudaFuncSetAttribute(attn_mma_kernel, cudaFuncAttributeMaxDynamicSharedMemorySize, ATT_SMEM_H);

    // launch 0: effective weights q,k
    dim3 tb(32, 8);
    effw_pair_kernel<<<dim3(DIM/32, DIM/32, 2), tb>>>(
        Wq, qA, qB, wh,                    wl,                    DIM,
        Wk, kA, kB, wh + (size_t)KOFF*DIM, wl + (size_t)KOFF*DIM, KVDIM);
    // launch 1: effective weights v,p
    effw_pair_kernel<<<dim3(DIM/32, DIM/32, 2), tb>>>(
        Wv, vA, vB, wh + (size_t)VOFF*DIM, wl + (size_t)VOFF*DIM, KVDIM,
        Wp, pA, pB, wph,                   wpl,                   DIM);

    // launch 2: split x
    split_kernel<<<(BT*DIM/4 + 255)/256, 256>>>(x, BT*DIM/4, xh, xl);

    // launch 3 (profiled): fused qkv projection (bf16x3, 256 thr), N = 3072
    dim3 gqkv(QKVD/TBN, BT/TBM);
    bf16x3gemm_kernel<QKVD, DIM><<<gqkv, 256, GSMEM>>>(xh, xl, wh, wl, qkv);

    // launch 4: fused per-head RMSnorm + RoPE -> fp16 q/k
    {
        int wn = BT * (NH + NHKV);
        normrope_h_kernel<<<(wn*32 + 255)/256, 256>>>(qkv, qgain, qh, kh2);
    }

    // launch 5: V transpose -> fp16 Vt[b][kh][hd][t]
    vtrans_kernel<<<dim3(TSEQ/32, HD/32, BSZ*NHKV), tb>>>(qkv, vth);

    // launch 6: causal flash attention
    {
        dim3 ga(TSEQ/AQ, NH, BSZ);
        attn_mma_kernel<<<ga, 256, ATT_SMEM_H>>>(qh, kh2, vth, y);
    }

    // launch 7: v-projection removal + bf16 split
    {
        int wv_n = BT * NHKV;
        vproj_split_kernel<<<(wv_n*32 + 255)/256, 256>>>(qkv + VOFF, QKVD, y, yh, yl);
    }

    // launch 8: output projection (bf16x3, 256 thr)
    dim3 gp(DIM/TBN, BT/TBM);
    bf16x3gemm_kernel<DIM, DIM><<<gp, 256, GSMEM>>>(yh, yl, wph, wpl, out);
}

// round 13
// speedup vs baseline: 1.0721x; 1.0721x over previous
#include <cuda_runtime.h>
#include <cuda_bf16.h>
#include <cuda_fp16.h>
#include <math.h>
#include <math_constants.h>
#include <stdint.h>

// Problem constants
#define BSZ   2
#define TSEQ  2048
#define DIM   2048
#define NH    16
#define NHKV  4
#define HD    128
#define KVDIM (NHKV*HD)     // 512
#define GROUP (NH/NHKV)     // 4
#define RANK  16
#define BT    (BSZ*TSEQ)    // 4096
#define QKVD  (DIM + 2*KVDIM)   // 3072
#define KOFF  DIM               // 2048
#define VOFF  (DIM + KVDIM)     // 2560

// ---------------- scratch (device globals; no allocation allowed) ----------
__device__ __nv_bfloat16 g_WqkvTh[QKVD*DIM], g_WqkvTl[QKVD*DIM];  // [3072][2048]
__device__ __nv_bfloat16 g_WpTh[DIM*DIM],    g_WpTl[DIM*DIM];
__device__ __nv_bfloat16 g_xh[BT*DIM],  g_xl[BT*DIM];
__device__ __nv_bfloat16 g_yh[BT*DIM],  g_yl[BT*DIM];
__device__ float  g_qkv[BT*QKVD];
__device__ float  g_y[BT*DIM];
__device__ __half g_qh[BT*DIM];                    // fp16 q (normed+rope+gain)
__device__ __half g_kh[BT*KVDIM];                  // fp16 k (normed+rope)
__device__ __half g_vth[BSZ*NHKV*HD*TSEQ];         // fp16 V transposed [b][kh][hd][t]

// ---- effective weights pair (W + A@B), transposed + split (2 per launch) --
__global__ void effw_pair_kernel(
    const float* __restrict__ W0, const float* __restrict__ A0, const float* __restrict__ B0,
    __nv_bfloat16* __restrict__ H0, __nv_bfloat16* __restrict__ L0, int N0,
    const float* __restrict__ W1, const float* __restrict__ A1, const float* __restrict__ B1,
    __nv_bfloat16* __restrict__ H1, __nv_bfloat16* __restrict__ L1, int N1)
{
    __shared__ float tile[32][33];
    const float *W, *A, *Bm;
    __nv_bfloat16 *H, *L;
    int N;
    if (blockIdx.z == 0) { W=W0; A=A0; Bm=B0; H=H0; L=L0; N=N0; }
    else                 { W=W1; A=A1; Bm=B1; H=H1; L=L1; N=N1; }
    int tn = blockIdx.x * 32;
    if (tn >= N) return;
    int tk = blockIdx.y * 32;
    int tx = threadIdx.x, ty = threadIdx.y;   // 32 x 8

    #pragma unroll
    for (int i = 0; i < 4; i++) {
        int k = tk + ty + i*8;
        int n = tn + tx;
        float s = W[(size_t)k * N + n];
        #pragma unroll
        for (int r = 0; r < RANK; r++)
            s += A[k*RANK + r] * Bm[r*N + n];
        tile[ty + i*8][tx] = s;
    }
    __syncthreads();
    #pragma unroll
    for (int i = 0; i < 4; i++) {
        int n = tn + ty + i*8;
        int k = tk + tx;
        float s = tile[tx][ty + i*8];
        __nv_bfloat16 h = __float2bfloat16_rn(s);
        H[(size_t)n * DIM + k] = h;
        L[(size_t)n * DIM + k] = __float2bfloat16_rn(s - __bfloat162float(h));
    }
}

// ---- split fp32 activation into bf16 hi/lo (vectorized) --------------------
__global__ void split_kernel(const float* __restrict__ X, int count4,
                             __nv_bfloat16* __restrict__ H,
                             __nv_bfloat16* __restrict__ L)
{
    int idx = blockIdx.x * blockDim.x + threadIdx.x;
    if (idx >= count4) return;
    float4 v = ((const float4*)X)[idx];
    __nv_bfloat16 h0 = __float2bfloat16_rn(v.x), h1 = __float2bfloat16_rn(v.y);
    __nv_bfloat16 h2 = __float2bfloat16_rn(v.z), h3 = __float2bfloat16_rn(v.w);
    __nv_bfloat162 hh0 = {h0, h1}, hh1 = {h2, h3};
    __nv_bfloat162 ll0 = {__float2bfloat16_rn(v.x - __bfloat162float(h0)),
                          __float2bfloat16_rn(v.y - __bfloat162float(h1))};
    __nv_bfloat162 ll1 = {__float2bfloat16_rn(v.z - __bfloat162float(h2)),
                          __float2bfloat16_rn(v.w - __bfloat162float(h3))};
    ((__nv_bfloat162*)H)[idx*2]   = hh0;
    ((__nv_bfloat162*)H)[idx*2+1] = hh1;
    ((__nv_bfloat162*)L)[idx*2]   = ll0;
    ((__nv_bfloat162*)L)[idx*2+1] = ll1;
}

// ---------------- bf16x3 tensor-core GEMM (128 thr + ldmatrix) -------------
#define TBM 128
#define TBN 128
#define TBK 32
#define STR 40

__device__ __forceinline__ void cpa16(uint32_t dst, const void* src) {
    asm volatile("cp.async.cg.shared.global [%0], [%1], 16;\n" :: "r"(dst), "l"(src));
}
__device__ __forceinline__ void cpa_commit() {
    asm volatile("cp.async.commit_group;\n");
}
__device__ __forceinline__ void cpa_wait0() {
    asm volatile("cp.async.wait_group 0;\n");
}
__device__ __forceinline__ void ldsm_x4(uint32_t& r0, uint32_t& r1, uint32_t& r2, uint32_t& r3,
                                        uint32_t addr) {
    asm volatile("ldmatrix.sync.aligned.m8n8.x4.shared.b16 {%0,%1,%2,%3}, [%4];"
                 : "=r"(r0), "=r"(r1), "=r"(r2), "=r"(r3) : "r"(addr));
}
__device__ __forceinline__ void mma_bf16(float& d0, float& d1, float& d2, float& d3,
                                         uint32_t a0, uint32_t a1, uint32_t a2, uint32_t a3,
                                         uint32_t b0, uint32_t b1) {
    asm volatile(
        "mma.sync.aligned.m16n8k16.row.col.f32.bf16.bf16.f32 "
        "{%0,%1,%2,%3}, {%4,%5,%6,%7}, {%8,%9}, {%0,%1,%2,%3};\n"
        : "+f"(d0), "+f"(d1), "+f"(d2), "+f"(d3)
        : "r"(a0), "r"(a1), "r"(a2), "r"(a3), "r"(b0), "r"(b1));
}
__device__ __forceinline__ void mma_f16(float& d0, float& d1, float& d2, float& d3,
                                        uint32_t a0, uint32_t a1, uint32_t a2, uint32_t a3,
                                        uint32_t b0, uint32_t b1) {
    asm volatile(
        "mma.sync.aligned.m16n8k16.row.col.f32.f16.f16.f32 "
        "{%0,%1,%2,%3}, {%4,%5,%6,%7}, {%8,%9}, {%0,%1,%2,%3};\n"
        : "+f"(d0), "+f"(d1), "+f"(d2), "+f"(d3)
        : "r"(a0), "r"(a1), "r"(a2), "r"(a3), "r"(b0), "r"(b1));
}

template<int N, int K>
__global__ __launch_bounds__(128)
void bf16x3gemm_kernel(const __nv_bfloat16* __restrict__ Ah,
                       const __nv_bfloat16* __restrict__ Al,
                       const __nv_bfloat16* __restrict__ Bh,   // [N][K]
                       const __nv_bfloat16* __restrict__ Bl,
                       float* __restrict__ C)
{
    extern __shared__ __nv_bfloat16 smem[];
    __nv_bfloat16* sAh = smem;
    __nv_bfloat16* sAl = sAh + 2*TBM*STR;
    __nv_bfloat16* sBh = sAl + 2*TBM*STR;
    __nv_bfloat16* sBl = sBh + 2*TBN*STR;

    int tid  = threadIdx.x;
    int warp = tid >> 5, lane = tid & 31;
    int warpM = warp >> 1, warpN = warp & 1;    // 2x2 warp grid
    int gid = lane >> 2, tig = lane & 3;

    const __nv_bfloat16* Ahb = Ah + (size_t)blockIdx.y * TBM * K;
    const __nv_bfloat16* Alb = Al + (size_t)blockIdx.y * TBM * K;
    const __nv_bfloat16* Bhb = Bh + (size_t)blockIdx.x * TBN * K;
    const __nv_bfloat16* Blb = Bl + (size_t)blockIdx.x * TBN * K;
    float* Cb = C + (size_t)blockIdx.y * TBM * N + (size_t)blockIdx.x * TBN;

    int srow = tid >> 2;
    int scol = (tid & 3) * 8;

    uint32_t uAh = (uint32_t)__cvta_generic_to_shared(sAh);
    uint32_t uAl = (uint32_t)__cvta_generic_to_shared(sAl);
    uint32_t uBh = (uint32_t)__cvta_generic_to_shared(sBh);
    uint32_t uBl = (uint32_t)__cvta_generic_to_shared(sBl);

    // ldmatrix lane byte-offsets
    // A (x4 = M0..M3): lanes 0-15 rows 0-15 (col half 0), lanes 16-31 same rows col half 1
    uint32_t laneA = (uint32_t)(((lane & 15) * STR + (lane >> 4) * 8) * 2);
    // B (x4 = {nt:k0,k8, nt+1:k0,k8}): lanes0-7 n0-7/k0, 8-15 n0-7/k8, 16-23 n8-15/k0, 24-31 n8-15/k8
    uint32_t laneB = (uint32_t)((((lane & 7) + ((lane >> 4) << 3)) * STR) * 2 + ((lane >> 3) & 1) * 16);

    float acc[4][8][4];
    #pragma unroll
    for (int m = 0; m < 4; m++)
        #pragma unroll
        for (int n = 0; n < 8; n++)
            #pragma unroll
            for (int i = 0; i < 4; i++) acc[m][n][i] = 0.0f;

    constexpr int ntiles = K / TBK;

    auto issue = [&](int buf, int kt) {
        uint32_t bofs = (uint32_t)(buf * TBM * STR * 2);
        #pragma unroll
        for (int i = 0; i < 4; i++) {
            int r = srow + i * 32;
            uint32_t dofs = (uint32_t)((r * STR + scol) * 2);
            size_t gofs = (size_t)r * K + (size_t)kt * TBK + scol;
            cpa16(uAh + bofs + dofs, Ahb + gofs);
            cpa16(uAl + bofs + dofs, Alb + gofs);
            cpa16(uBh + bofs + dofs, Bhb + gofs);
            cpa16(uBl + bofs + dofs, Blb + gofs);
        }
        cpa_commit();
    };

    issue(0, 0);
    int buf = 0;

    for (int kt = 0; kt < ntiles; kt++) {
        cpa_wait0();
        __syncthreads();
        if (kt + 1 < ntiles) issue(buf ^ 1, kt + 1);

        uint32_t bufofs = (uint32_t)(buf * TBM * STR * 2);
        uint32_t aH = uAh + bufofs, aL = uAl + bufofs;
        uint32_t bH = uBh + bufofs, bL = uBl + bufofs;

        #pragma unroll
        for (int ks = 0; ks < TBK; ks += 16) {
            uint32_t afh[4][4], afl[4][4];
            #pragma unroll
            for (int mt = 0; mt < 4; mt++) {
                uint32_t ofs = (uint32_t)(((warpM*64 + mt*16) * STR + ks) * 2) + laneA;
                ldsm_x4(afh[mt][0], afh[mt][1], afh[mt][2], afh[mt][3], aH + ofs);
                ldsm_x4(afl[mt][0], afl[mt][1], afl[mt][2], afl[mt][3], aL + ofs);
            }
            uint32_t bfh[8][2], bfl[8][2];
            #pragma unroll
            for (int np = 0; np < 4; np++) {
                uint32_t ofs = (uint32_t)(((warpN*64 + np*16) * STR + ks) * 2) + laneB;
                ldsm_x4(bfh[2*np][0], bfh[2*np][1], bfh[2*np+1][0], bfh[2*np+1][1], bH + ofs);
                ldsm_x4(bfl[2*np][0], bfl[2*np][1], bfl[2*np+1][0], bfl[2*np+1][1], bL + ofs);
            }
            #pragma unroll
            for (int mt = 0; mt < 4; mt++)
                #pragma unroll
                for (int nt = 0; nt < 8; nt++) {
                    mma_bf16(acc[mt][nt][0], acc[mt][nt][1], acc[mt][nt][2], acc[mt][nt][3],
                             afh[mt][0], afh[mt][1], afh[mt][2], afh[mt][3],
                             bfh[nt][0], bfh[nt][1]);
                    mma_bf16(acc[mt][nt][0], acc[mt][nt][1], acc[mt][nt][2], acc[mt][nt][3],
                             afh[mt][0], afh[mt][1], afh[mt][2], afh[mt][3],
                             bfl[nt][0], bfl[nt][1]);
                    mma_bf16(acc[mt][nt][0], acc[mt][nt][1], acc[mt][nt][2], acc[mt][nt][3],
                             afl[mt][0], afl[mt][1], afl[mt][2], afl[mt][3],
                             bfh[nt][0], bfh[nt][1]);
                }
        }
        __syncthreads();
        buf ^= 1;
    }

    #pragma unroll
    for (int mt = 0; mt < 4; mt++) {
        int r0 = warpM*64 + mt*16 + gid;
        #pragma unroll
        for (int nt = 0; nt < 8; nt++) {
            int c0 = warpN*64 + nt*8 + tig*2;
            *(float2*)(Cb + (size_t) r0      * N + c0) = make_float2(acc[mt][nt][0], acc[mt][nt][1]);
            *(float2*)(Cb + (size_t)(r0 + 8) * N + c0) = make_float2(acc[mt][nt][2], acc[mt][nt][3]);
        }
    }
}

// ---- RMSnorm + RoPE (+gain), q and k fused, fp16 output --------------------
__global__ void normrope_h_kernel(const float* __restrict__ QKV,
                                  const float* __restrict__ gain,
                                  __half* __restrict__ Qh,
                                  __half* __restrict__ Kh)
{
    int gthr = blockIdx.x * blockDim.x + threadIdx.x;
    int w    = gthr >> 5;
    int lane = gthr & 31;
    int total = BT * (NH + NHKV);
    if (w >= total) return;

    const float* src;
    __half* dst;
    float g = 1.0f;
    int bt;
    if (w < BT * NH) {
        bt = w / NH;
        int hh = w % NH;
        src = QKV + (size_t)bt * QKVD + hh * HD;
        dst = Qh  + (size_t)bt * DIM  + hh * HD;
        g = gain[hh];
    } else {
        int w2 = w - BT * NH;
        bt = w2 / NHKV;
        int hh = w2 % NHKV;
        src = QKV + (size_t)bt * QKVD + KOFF + hh * HD;
        dst = Kh  + (size_t)bt * KVDIM + hh * HD;
    }
    int t = bt % TSEQ;

    float v0 = src[lane], v1 = src[lane+32], v2 = src[lane+64], v3 = src[lane+96];
    float ss = v0*v0 + v1*v1 + v2*v2 + v3*v3;
    #pragma unroll
    for (int o = 16; o; o >>= 1) ss += __shfl_xor_sync(0xffffffffu, ss, o);

    float f = rsqrtf(ss * (1.0f/128.0f) + 1.1920929e-7f) * g;

    float invfreq = powf(10000.0f, -(float)lane * (1.0f/32.0f));
    float ang = (float)t * invfreq;
    float s, c;
    sincosf(ang, &s, &c);

    dst[lane]    = __float2half(( v0*c + v1*s) * f);
    dst[lane+32] = __float2half((-v0*s + v1*c) * f);
    dst[lane+64] = __float2half(v2 * f);
    dst[lane+96] = __float2half(v3 * f);
}

// ---- V transpose to fp16: Vt[b][kh][hd][t] ---------------------------------
__global__ void vtrans_kernel(const float* __restrict__ QKV,
                              __half* __restrict__ Vt)
{
    __shared__ float tile[32][33];
    int bk = blockIdx.z;                 // b*NHKV + kh
    int b  = bk / NHKV, kh = bk % NHKV;
    int t0 = blockIdx.x * 32;
    int c0 = blockIdx.y * 32;
    int tx = threadIdx.x, ty = threadIdx.y;   // 32 x 8

    #pragma unroll
    for (int i = 0; i < 4; i++) {
        int t = t0 + ty + i*8;
        tile[ty + i*8][tx] = QKV[(size_t)(b*TSEQ + t) * QKVD + VOFF + kh*HD + c0 + tx];
    }
    __syncthreads();
    #pragma unroll
    for (int i = 0; i < 4; i++) {
        int c = c0 + ty + i*8;
        Vt[((size_t)bk * HD + c) * TSEQ + t0 + tx] = __float2half(tile[tx][ty + i*8]);
    }
}

// ---------------- fp16 tensor-core causal flash attention (v2) -------------
#define AQ   128
#define AK   64
#define QSTR 136
#define KSTR 136
#define VSTR 72
#define K_TILE_B  (AK*KSTR*2)   // 17408
#define V_TILE_B  (HD*VSTR*2)   // 18432
#define ATT_SMEM_H (AQ*QSTR*2 + 2*K_TILE_B + 2*V_TILE_B)   // 106496 bytes

__global__ __launch_bounds__(256)
void attn_mma_kernel(const __half* __restrict__ Qh,
                     const __half* __restrict__ Kh,
                     const __half* __restrict__ Vth,
                     float* __restrict__ Y)
{
    extern __shared__ __half smh[];
    __half* Qs  = smh;                    // [AQ][QSTR]
    __half* Ksm = Qs + AQ*QSTR;           // 2 x [AK][KSTR]
    __half* Vsm = Ksm + 2*AK*KSTR;        // 2 x [HD][VSTR]

    int qt = blockIdx.x, h = blockIdx.y, b = blockIdx.z;
    int kh = h / GROUP;
    int q0 = qt * AQ;
    int tid = threadIdx.x;
    int warp = tid >> 5, lane = tid & 31;
    int gid = lane >> 2, tig = lane & 3;
    int wr = warp * 16;

    const float scale = 0.08838834764831845f;  // 128^-0.5

    uint32_t uK = (uint32_t)__cvta_generic_to_shared(Ksm);
    uint32_t uV = (uint32_t)__cvta_generic_to_shared(Vsm);

    for (int e = tid; e < AQ*16; e += 256) {
        int r = e >> 4, c = e & 15;
        *(uint4*)(Qs + r*QSTR + c*8) =
            *(const uint4*)(Qh + (size_t)(b*TSEQ + q0 + r)*DIM + h*HD + c*8);
    }

    const __half* Kbase = Kh  + (size_t)(b*TSEQ)*KVDIM + kh*HD;
    const __half* Vbase = Vth + ((size_t)(b*NHKV + kh))*HD*TSEQ;

    int kr  = tid >> 2;
    int kcb = (tid & 3) * 4;
    int vr  = tid >> 1;
    int vcb = (tid & 1) * 4;
    auto prefetch = [&](int s, int kt) {
        int s0 = kt * AK;
        uint32_t kd = uK + (uint32_t)s * K_TILE_B;
        const __half* ksrc = Kbase + (size_t)(s0 + kr) * KVDIM;
        #pragma unroll
        for (int j = 0; j < 4; j++)
            cpa16(kd + (uint32_t)(kr*KSTR + (kcb+j)*8)*2, ksrc + (kcb+j)*8);
        uint32_t vd = uV + (uint32_t)s * V_TILE_B;
        const __half* vsrc = Vbase + (size_t)vr * TSEQ + s0;
        #pragma unroll
        for (int j = 0; j < 4; j++)
            cpa16(vd + (uint32_t)(vr*VSTR + (vcb+j)*8)*2, vsrc + (vcb+j)*8);
        cpa_commit();
    };

    float m0 = -CUDART_INF_F, m1 = -CUDART_INF_F;
    float l0 = 0.0f, l1 = 0.0f;
    float o[16][4];
    #pragma unroll
    for (int on = 0; on < 16; on++)
        #pragma unroll
        for (int i = 0; i < 4; i++) o[on][i] = 0.0f;

    int nkt = 2*qt + 2;
    prefetch(0, 0);

    for (int kt = 0; kt < nkt; kt++) {
        int s0 = kt * AK;
        cpa_wait0();
        __syncthreads();
        if (kt + 1 < nkt) prefetch((kt + 1) & 1, kt + 1);

        const __half* Ks = Ksm + (kt & 1) * AK*KSTR;
        const __half* Vt = Vsm + (kt & 1) * HD*VSTR;

        float sacc[8][4];
        #pragma unroll
        for (int nt = 0; nt < 8; nt++)
            #pragma unroll
            for (int i = 0; i < 4; i++) sacc[nt][i] = 0.0f;

        #pragma unroll
        for (int ks = 0; ks < 8; ks++) {
            const __half* qb = Qs + (wr + gid)*QSTR + ks*16 + 2*tig;
            uint32_t a0 = *(const uint32_t*)(qb);
            uint32_t a1 = *(const uint32_t*)(qb + 8*QSTR);
            uint32_t a2 = *(const uint32_t*)(qb + 8);
            uint32_t a3 = *(const uint32_t*)(qb + 8*QSTR + 8);
            #pragma unroll
            for (int nt = 0; nt < 8; nt++) {
                const __half* kb = Ks + (nt*8 + gid)*KSTR + ks*16 + 2*tig;
                uint32_t b0 = *(const uint32_t*)(kb);
                uint32_t b1 = *(const uint32_t*)(kb + 8);
                mma_f16(sacc[nt][0], sacc[nt][1], sacc[nt][2], sacc[nt][3],
                        a0, a1, a2, a3, b0, b1);
            }
        }

        #pragma unroll
        for (int nt = 0; nt < 8; nt++)
            #pragma unroll
            for (int i = 0; i < 4; i++) sacc[nt][i] *= scale;

        if (s0 + AK - 1 > q0 + wr) {
            int r0g = q0 + wr + gid;
            #pragma unroll
            for (int nt = 0; nt < 8; nt++) {
                int sb = s0 + nt*8 + 2*tig;
                if (sb     > r0g)     sacc[nt][0] = -CUDART_INF_F;
                if (sb + 1 > r0g)     sacc[nt][1] = -CUDART_INF_F;
                if (sb     > r0g + 8) sacc[nt][2] = -CUDART_INF_F;
                if (sb + 1 > r0g + 8) sacc[nt][3] = -CUDART_INF_F;
            }
        }

        float mx0 = -CUDART_INF_F, mx1 = -CUDART_INF_F;
        #pragma unroll
        for (int nt = 0; nt < 8; nt++) {
            mx0 = fmaxf(mx0, fmaxf(sacc[nt][0], sacc[nt][1]));
            mx1 = fmaxf(mx1, fmaxf(sacc[nt][2], sacc[nt][3]));
        }
        #pragma unroll
        for (int off = 1; off <= 2; off <<= 1) {
            mx0 = fmaxf(mx0, __shfl_xor_sync(0xffffffffu, mx0, off));
            mx1 = fmaxf(mx1, __shfl_xor_sync(0xffffffffu, mx1, off));
        }
        float mn0 = fmaxf(m0, mx0), mn1 = fmaxf(m1, mx1);
        float corr0 = __expf(m0 - mn0), corr1 = __expf(m1 - mn1);
        m0 = mn0; m1 = mn1;

        float sum0 = 0.0f, sum1 = 0.0f;
        #pragma unroll
        for (int nt = 0; nt < 8; nt++) {
            sacc[nt][0] = __expf(sacc[nt][0] - mn0);
            sacc[nt][1] = __expf(sacc[nt][1] - mn0);
            sacc[nt][2] = __expf(sacc[nt][2] - mn1);
            sacc[nt][3] = __expf(sacc[nt][3] - mn1);
            sum0 += sacc[nt][0] + sacc[nt][1];
            sum1 += sacc[nt][2] + sacc[nt][3];
        }
        #pragma unroll
        for (int off = 1; off <= 2; off <<= 1) {
            sum0 += __shfl_xor_sync(0xffffffffu, sum0, off);
            sum1 += __shfl_xor_sync(0xffffffffu, sum1, off);
        }
        l0 = l0 * corr0 + sum0;
        l1 = l1 * corr1 + sum1;

        #pragma unroll
        for (int on = 0; on < 16; on++) {
            o[on][0] *= corr0; o[on][1] *= corr0;
            o[on][2] *= corr1; o[on][3] *= corr1;
        }

        #pragma unroll
        for (int ks2 = 0; ks2 < 4; ks2++) {
            __half2 pa0 = __floats2half2_rn(sacc[2*ks2][0],   sacc[2*ks2][1]);
            __half2 pa1 = __floats2half2_rn(sacc[2*ks2][2],   sacc[2*ks2][3]);
            __half2 pa2 = __floats2half2_rn(sacc[2*ks2+1][0], sacc[2*ks2+1][1]);
            __half2 pa3 = __floats2half2_rn(sacc[2*ks2+1][2], sacc[2*ks2+1][3]);
            uint32_t a0 = *reinterpret_cast<uint32_t*>(&pa0);
            uint32_t a1 = *reinterpret_cast<uint32_t*>(&pa1);
            uint32_t a2 = *reinterpret_cast<uint32_t*>(&pa2);
            uint32_t a3 = *reinterpret_cast<uint32_t*>(&pa3);
            #pragma unroll
            for (int on = 0; on < 16; on++) {
                const __half* vb = Vt + (on*8 + gid)*VSTR + ks2*16 + 2*tig;
                uint32_t b0 = *(const uint32_t*)(vb);
                uint32_t b1 = *(const uint32_t*)(vb + 8);
                mma_f16(o[on][0], o[on][1], o[on][2], o[on][3],
                        a0, a1, a2, a3, b0, b1);
            }
        }
    }

    float il0 = 1.0f / l0, il1 = 1.0f / l1;
    int r0 = q0 + wr + gid;
    #pragma unroll
    for (int on = 0; on < 16; on++) {
        int c0 = h*HD + on*8 + 2*tig;
        *(float2*)(Y + (size_t)(b*TSEQ + r0)     * DIM + c0) = make_float2(o[on][0]*il0, o[on][1]*il0);
        *(float2*)(Y + (size_t)(b*TSEQ + r0 + 8) * DIM + c0) = make_float2(o[on][2]*il1, o[on][3]*il1);
    }
}

// ---- v-direction projection removal, fused with bf16 hi/lo split ----------
__global__ void vproj_split_kernel(const float* __restrict__ V, int vstride,
                                   const float* __restrict__ Yin,
                                   __nv_bfloat16* __restrict__ YH,
                                   __nv_bfloat16* __restrict__ YL)
{
    int gthr = blockIdx.x * blockDim.x + threadIdx.x;
    int w    = gthr >> 5;
    int lane = gthr & 31;
    if (w >= BT * NHKV) return;
    int bt = w / NHKV, kh = w % NHKV;

    const float* vrow = V + (size_t)bt * vstride + kh * HD;
    float v0 = vrow[lane], v1 = vrow[lane+32], v2 = vrow[lane+64], v3 = vrow[lane+96];
    float ss = v0*v0 + v1*v1 + v2*v2 + v3*v3;
    #pragma unroll
    for (int o = 16; o; o >>= 1) ss += __shfl_xor_sync(0xffffffffu, ss, o);
    float norm = sqrtf(ss);
    float inv = 1.0f / fmaxf(norm, 1e-12f);
    float n0 = v0*inv, n1 = v1*inv, n2 = v2*inv, n3 = v3*inv;

    #pragma unroll
    for (int g = 0; g < GROUP; g++) {
        int hh = kh * GROUP + g;
        size_t base = (size_t)bt * DIM + hh * HD;
        const float* yrow = Yin + base;
        float y0 = yrow[lane], y1 = yrow[lane+32], y2 = yrow[lane+64], y3 = yrow[lane+96];
        float d = y0*n0 + y1*n1 + y2*n2 + y3*n3;
        #pragma unroll
        for (int o = 16; o; o >>= 1) d += __shfl_xor_sync(0xffffffffu, d, o);
        float r0 = y0 - d*n0, r1 = y1 - d*n1, r2 = y2 - d*n2, r3 = y3 - d*n3;

        __nv_bfloat16 h0 = __float2bfloat16_rn(r0), h1 = __float2bfloat16_rn(r1);
        __nv_bfloat16 h2 = __float2bfloat16_rn(r2), h3 = __float2bfloat16_rn(r3);
        YH[base + lane]    = h0;  YL[base + lane]    = __float2bfloat16_rn(r0 - __bfloat162float(h0));
        YH[base + lane+32] = h1;  YL[base + lane+32] = __float2bfloat16_rn(r1 - __bfloat162float(h1));
        YH[base + lane+64] = h2;  YL[base + lane+64] = __float2bfloat16_rn(r2 - __bfloat162float(h2));
        YH[base + lane+96] = h3;  YL[base + lane+96] = __float2bfloat16_rn(r3 - __bfloat162float(h3));
    }
}

// ---------------- launcher --------------------------------------------------
extern "C" void kernel_launch(void* const* d_in, const int* in_sizes, int n_in,
                              void* d_out, int out_size)
{
    const float* x     = (const float*)d_in[0];
    const float* Wq    = (const float*)d_in[1];
    const float* Wk    = (const float*)d_in[2];
    const float* Wv    = (const float*)d_in[3];
    const float* Wp    = (const float*)d_in[4];
    const float* qgain = (const float*)d_in[5];
    const float* qA    = (const float*)d_in[6];
    const float* qB    = (const float*)d_in[7];
    const float* kA    = (const float*)d_in[8];
    const float* kB    = (const float*)d_in[9];
    const float* vA    = (const float*)d_in[10];
    const float* vB    = (const float*)d_in[11];
    const float* pA    = (const float*)d_in[12];
    const float* pB    = (const float*)d_in[13];
    float* out = (float*)d_out;

    __nv_bfloat16 *wh, *wl, *wph, *wpl, *xh, *xl, *yh, *yl;
    float *qkv, *y;
    __half *qh, *kh2, *vth;
    cudaGetSymbolAddress((void**)&wh,  g_WqkvTh); cudaGetSymbolAddress((void**)&wl,  g_WqkvTl);
    cudaGetSymbolAddress((void**)&wph, g_WpTh);   cudaGetSymbolAddress((void**)&wpl, g_WpTl);
    cudaGetSymbolAddress((void**)&xh,  g_xh);     cudaGetSymbolAddress((void**)&xl,  g_xl);
    cudaGetSymbolAddress((void**)&yh,  g_yh);     cudaGetSymbolAddress((void**)&yl,  g_yl);
    cudaGetSymbolAddress((void**)&qkv, g_qkv);
    cudaGetSymbolAddress((void**)&y,   g_y);
    cudaGetSymbolAddress((void**)&qh,  g_qh);
    cudaGetSymbolAddress((void**)&kh2, g_kh);
    cudaGetSymbolAddress((void**)&vth, g_vth);

    const int GSMEM = (8*TBM*STR) * (int)sizeof(__nv_bfloat16);
    cudaFuncSetAttribute(bf16x3gemm_kernel<QKVD, DIM>, cudaFuncAttributeMaxDynamicSharedMemorySize, GSMEM);
    cudaFuncSetAttribute(bf16x3gemm_kernel<DIM, DIM>,  cudaFuncAttributeMaxDynamicSharedMemorySize, GSMEM);
    cudaFuncSetAttribute(attn_mma_kernel, cudaFuncAttributeMaxDynamicSharedMemorySize, ATT_SMEM_H);

    // launch 0: effective weights q,k
    dim3 tb(32, 8);
    effw_pair_kernel<<<dim3(DIM/32, DIM/32, 2), tb>>>(
        Wq, qA, qB, wh,                    wl,                    DIM,
        Wk, kA, kB, wh + (size_t)KOFF*DIM, wl + (size_t)KOFF*DIM, KVDIM);
    // launch 1: effective weights v,p
    effw_pair_kernel<<<dim3(DIM/32, DIM/32, 2), tb>>>(
        Wv, vA, vB, wh + (size_t)VOFF*DIM, wl + (size_t)VOFF*DIM, KVDIM,
        Wp, pA, pB, wph,                   wpl,                   DIM);

    // launch 2: split x
    split_kernel<<<(BT*DIM/4 + 255)/256, 256>>>(x, BT*DIM/4, xh, xl);

    // launch 3 (profiled): fused qkv projection (bf16x3 + ldmatrix), N = 3072
    dim3 gqkv(QKVD/TBN, BT/TBM);
    bf16x3gemm_kernel<QKVD, DIM><<<gqkv, 128, GSMEM>>>(xh, xl, wh, wl, qkv);

    // launch 4: fused per-head RMSnorm + RoPE -> fp16 q/k
    {
        int wn = BT * (NH + NHKV);
        normrope_h_kernel<<<(wn*32 + 255)/256, 256>>>(qkv, qgain, qh, kh2);
    }

    // launch 5: V transpose -> fp16 Vt[b][kh][hd][t]
    vtrans_kernel<<<dim3(TSEQ/32, HD/32, BSZ*NHKV), tb>>>(qkv, vth);

    // launch 6: causal flash attention
    {
        dim3 ga(TSEQ/AQ, NH, BSZ);
        attn_mma_kernel<<<ga, 256, ATT_SMEM_H>>>(qh, kh2, vth, y);
    }

    // launch 7: v-projection removal + bf16 split
    {
        int wv_n = BT * NHKV;
        vproj_split_kernel<<<(wv_n*32 + 255)/256, 256>>>(qkv + VOFF, QKVD, y, yh, yl);
    }

    // launch 8: output projection (bf16x3 + ldmatrix)
    dim3 gp(DIM/TBN, BT/TBM);
    bf16x3gemm_kernel<DIM, DIM><<<gp, 128, GSMEM>>>(yh, yl, wph, wpl, out);
}

// round 14
// speedup vs baseline: 1.0782x; 1.0057x over previous
#include <cuda_runtime.h>
#include <cuda_bf16.h>
#include <cuda_fp16.h>
#include <math.h>
#include <math_constants.h>
#include <stdint.h>

// Problem constants
#define BSZ   2
#define TSEQ  2048
#define DIM   2048
#define NH    16
#define NHKV  4
#define HD    128
#define KVDIM (NHKV*HD)     // 512
#define GROUP (NH/NHKV)     // 4
#define RANK  16
#define BT    (BSZ*TSEQ)    // 4096
#define QKVD  (DIM + 2*KVDIM)   // 3072
#define KOFF  DIM               // 2048
#define VOFF  (DIM + KVDIM)     // 2560

// ---------------- scratch (device globals; no allocation allowed) ----------
__device__ __nv_bfloat16 g_WqkvTh[QKVD*DIM], g_WqkvTl[QKVD*DIM];  // [3072][2048]
__device__ __nv_bfloat16 g_WpTh[DIM*DIM],    g_WpTl[DIM*DIM];
__device__ __nv_bfloat16 g_xh[BT*DIM],  g_xl[BT*DIM];
__device__ __nv_bfloat16 g_yh[BT*DIM],  g_yl[BT*DIM];
__device__ float  g_qkv[BT*QKVD];
__device__ float  g_y[BT*DIM];
__device__ __half g_qh[BT*DIM];                    // fp16 q (normed+rope+gain)
__device__ __half g_kh[BT*KVDIM];                  // fp16 k (normed+rope)
__device__ __half g_vth[BSZ*NHKV*HD*TSEQ];         // fp16 V transposed [b][kh][hd][t]

// ---- effective weights pair (W + A@B), transposed + split (2 per launch) --
__global__ void effw_pair_kernel(
    const float* __restrict__ W0, const float* __restrict__ A0, const float* __restrict__ B0,
    __nv_bfloat16* __restrict__ H0, __nv_bfloat16* __restrict__ L0, int N0,
    const float* __restrict__ W1, const float* __restrict__ A1, const float* __restrict__ B1,
    __nv_bfloat16* __restrict__ H1, __nv_bfloat16* __restrict__ L1, int N1)
{
    __shared__ float tile[32][33];
    const float *W, *A, *Bm;
    __nv_bfloat16 *H, *L;
    int N;
    if (blockIdx.z == 0) { W=W0; A=A0; Bm=B0; H=H0; L=L0; N=N0; }
    else                 { W=W1; A=A1; Bm=B1; H=H1; L=L1; N=N1; }
    int tn = blockIdx.x * 32;
    if (tn >= N) return;
    int tk = blockIdx.y * 32;
    int tx = threadIdx.x, ty = threadIdx.y;   // 32 x 8

    #pragma unroll
    for (int i = 0; i < 4; i++) {
        int k = tk + ty + i*8;
        int n = tn + tx;
        float s = W[(size_t)k * N + n];
        #pragma unroll
        for (int r = 0; r < RANK; r++)
            s += A[k*RANK + r] * Bm[r*N + n];
        tile[ty + i*8][tx] = s;
    }
    __syncthreads();
    #pragma unroll
    for (int i = 0; i < 4; i++) {
        int n = tn + ty + i*8;
        int k = tk + tx;
        float s = tile[tx][ty + i*8];
        __nv_bfloat16 h = __float2bfloat16_rn(s);
        H[(size_t)n * DIM + k] = h;
        L[(size_t)n * DIM + k] = __float2bfloat16_rn(s - __bfloat162float(h));
    }
}

// ---- split fp32 activation into bf16 hi/lo (vectorized) --------------------
__global__ void split_kernel(const float* __restrict__ X, int count4,
                             __nv_bfloat16* __restrict__ H,
                             __nv_bfloat16* __restrict__ L)
{
    int idx = blockIdx.x * blockDim.x + threadIdx.x;
    if (idx >= count4) return;
    float4 v = ((const float4*)X)[idx];
    __nv_bfloat16 h0 = __float2bfloat16_rn(v.x), h1 = __float2bfloat16_rn(v.y);
    __nv_bfloat16 h2 = __float2bfloat16_rn(v.z), h3 = __float2bfloat16_rn(v.w);
    __nv_bfloat162 hh0 = {h0, h1}, hh1 = {h2, h3};
    __nv_bfloat162 ll0 = {__float2bfloat16_rn(v.x - __bfloat162float(h0)),
                          __float2bfloat16_rn(v.y - __bfloat162float(h1))};
    __nv_bfloat162 ll1 = {__float2bfloat16_rn(v.z - __bfloat162float(h2)),
                          __float2bfloat16_rn(v.w - __bfloat162float(h3))};
    ((__nv_bfloat162*)H)[idx*2]   = hh0;
    ((__nv_bfloat162*)H)[idx*2+1] = hh1;
    ((__nv_bfloat162*)L)[idx*2]   = ll0;
    ((__nv_bfloat162*)L)[idx*2+1] = ll1;
}

// ---------------- bf16x3 tensor-core GEMM (ldmatrix, term-major) -----------
#define TBM 128
#define TBN 128
#define TBK 32
#define STR 40

__device__ __forceinline__ void cpa16(uint32_t dst, const void* src) {
    asm volatile("cp.async.cg.shared.global [%0], [%1], 16;\n" :: "r"(dst), "l"(src));
}
__device__ __forceinline__ void cpa_commit() {
    asm volatile("cp.async.commit_group;\n");
}
__device__ __forceinline__ void cpa_wait0() {
    asm volatile("cp.async.wait_group 0;\n");
}
__device__ __forceinline__ void ldsm_x4(uint32_t& r0, uint32_t& r1, uint32_t& r2, uint32_t& r3,
                                        uint32_t addr) {
    asm volatile("ldmatrix.sync.aligned.m8n8.x4.shared.b16 {%0,%1,%2,%3}, [%4];"
                 : "=r"(r0), "=r"(r1), "=r"(r2), "=r"(r3) : "r"(addr));
}
__device__ __forceinline__ void mma_bf16(float& d0, float& d1, float& d2, float& d3,
                                         uint32_t a0, uint32_t a1, uint32_t a2, uint32_t a3,
                                         uint32_t b0, uint32_t b1) {
    asm volatile(
        "mma.sync.aligned.m16n8k16.row.col.f32.bf16.bf16.f32 "
        "{%0,%1,%2,%3}, {%4,%5,%6,%7}, {%8,%9}, {%0,%1,%2,%3};\n"
        : "+f"(d0), "+f"(d1), "+f"(d2), "+f"(d3)
        : "r"(a0), "r"(a1), "r"(a2), "r"(a3), "r"(b0), "r"(b1));
}
__device__ __forceinline__ void mma_f16(float& d0, float& d1, float& d2, float& d3,
                                        uint32_t a0, uint32_t a1, uint32_t a2, uint32_t a3,
                                        uint32_t b0, uint32_t b1) {
    asm volatile(
        "mma.sync.aligned.m16n8k16.row.col.f32.f16.f16.f32 "
        "{%0,%1,%2,%3}, {%4,%5,%6,%7}, {%8,%9}, {%0,%1,%2,%3};\n"
        : "+f"(d0), "+f"(d1), "+f"(d2), "+f"(d3)
        : "r"(a0), "r"(a1), "r"(a2), "r"(a3), "r"(b0), "r"(b1));
}

template<int N, int K>
__global__ __launch_bounds__(128)
void bf16x3gemm_kernel(const __nv_bfloat16* __restrict__ Ah,
                       const __nv_bfloat16* __restrict__ Al,
                       const __nv_bfloat16* __restrict__ Bh,   // [N][K]
                       const __nv_bfloat16* __restrict__ Bl,
                       float* __restrict__ C)
{
    extern __shared__ __nv_bfloat16 smem[];
    __nv_bfloat16* sAh = smem;
    __nv_bfloat16* sAl = sAh + 2*TBM*STR;
    __nv_bfloat16* sBh = sAl + 2*TBM*STR;
    __nv_bfloat16* sBl = sBh + 2*TBN*STR;

    int tid  = threadIdx.x;
    int warp = tid >> 5, lane = tid & 31;
    int warpM = warp >> 1, warpN = warp & 1;    // 2x2 warp grid
    int gid = lane >> 2, tig = lane & 3;

    const __nv_bfloat16* Ahb = Ah + (size_t)blockIdx.y * TBM * K;
    const __nv_bfloat16* Alb = Al + (size_t)blockIdx.y * TBM * K;
    const __nv_bfloat16* Bhb = Bh + (size_t)blockIdx.x * TBN * K;
    const __nv_bfloat16* Blb = Bl + (size_t)blockIdx.x * TBN * K;
    float* Cb = C + (size_t)blockIdx.y * TBM * N + (size_t)blockIdx.x * TBN;

    int srow = tid >> 2;
    int scol = (tid & 3) * 8;

    uint32_t uAh = (uint32_t)__cvta_generic_to_shared(sAh);
    uint32_t uAl = (uint32_t)__cvta_generic_to_shared(sAl);
    uint32_t uBh = (uint32_t)__cvta_generic_to_shared(sBh);
    uint32_t uBl = (uint32_t)__cvta_generic_to_shared(sBl);

    // ldmatrix lane byte-offsets
    uint32_t laneA = (uint32_t)(((lane & 15) * STR + (lane >> 4) * 8) * 2);
    uint32_t laneB = (uint32_t)((((lane & 7) + ((lane >> 4) << 3)) * STR) * 2 + ((lane >> 3) & 1) * 16);

    float acc[4][8][4];
    #pragma unroll
    for (int m = 0; m < 4; m++)
        #pragma unroll
        for (int n = 0; n < 8; n++)
            #pragma unroll
            for (int i = 0; i < 4; i++) acc[m][n][i] = 0.0f;

    constexpr int ntiles = K / TBK;

    auto issue = [&](int buf, int kt) {
        uint32_t bofs = (uint32_t)(buf * TBM * STR * 2);
        #pragma unroll
        for (int i = 0; i < 4; i++) {
            int r = srow + i * 32;
            uint32_t dofs = (uint32_t)((r * STR + scol) * 2);
            size_t gofs = (size_t)r * K + (size_t)kt * TBK + scol;
            cpa16(uAh + bofs + dofs, Ahb + gofs);
            cpa16(uAl + bofs + dofs, Alb + gofs);
            cpa16(uBh + bofs + dofs, Bhb + gofs);
            cpa16(uBl + bofs + dofs, Blb + gofs);
        }
        cpa_commit();
    };

    issue(0, 0);
    int buf = 0;

    for (int kt = 0; kt < ntiles; kt++) {
        cpa_wait0();
        __syncthreads();
        if (kt + 1 < ntiles) issue(buf ^ 1, kt + 1);

        uint32_t bufofs = (uint32_t)(buf * TBM * STR * 2);
        uint32_t aH = uAh + bufofs, aL = uAl + bufofs;
        uint32_t bH = uBh + bufofs, bL = uBl + bufofs;

        #pragma unroll
        for (int ks = 0; ks < TBK; ks += 16) {
            uint32_t afh[4][4], afl[4][4];
            #pragma unroll
            for (int mt = 0; mt < 4; mt++) {
                uint32_t ofs = (uint32_t)(((warpM*64 + mt*16) * STR + ks) * 2) + laneA;
                ldsm_x4(afh[mt][0], afh[mt][1], afh[mt][2], afh[mt][3], aH + ofs);
                ldsm_x4(afl[mt][0], afl[mt][1], afl[mt][2], afl[mt][3], aL + ofs);
            }
            uint32_t bfh[8][2], bfl[8][2];
            #pragma unroll
            for (int np = 0; np < 4; np++) {
                uint32_t ofs = (uint32_t)(((warpN*64 + np*16) * STR + ks) * 2) + laneB;
                ldsm_x4(bfh[2*np][0], bfh[2*np][1], bfh[2*np+1][0], bfh[2*np+1][1], bH + ofs);
                ldsm_x4(bfl[2*np][0], bfl[2*np][1], bfl[2*np+1][0], bfl[2*np+1][1], bL + ofs);
            }
            // term-major ordering: same-accumulator reuse distance = 32 MMAs
            #pragma unroll
            for (int mt = 0; mt < 4; mt++)
                #pragma unroll
                for (int nt = 0; nt < 8; nt++)
                    mma_bf16(acc[mt][nt][0], acc[mt][nt][1], acc[mt][nt][2], acc[mt][nt][3],
                             afh[mt][0], afh[mt][1], afh[mt][2], afh[mt][3],
                             bfh[nt][0], bfh[nt][1]);
            #pragma unroll
            for (int mt = 0; mt < 4; mt++)
                #pragma unroll
                for (int nt = 0; nt < 8; nt++)
                    mma_bf16(acc[mt][nt][0], acc[mt][nt][1], acc[mt][nt][2], acc[mt][nt][3],
                             afh[mt][0], afh[mt][1], afh[mt][2], afh[mt][3],
                             bfl[nt][0], bfl[nt][1]);
            #pragma unroll
            for (int mt = 0; mt < 4; mt++)
                #pragma unroll
                for (int nt = 0; nt < 8; nt++)
                    mma_bf16(acc[mt][nt][0], acc[mt][nt][1], acc[mt][nt][2], acc[mt][nt][3],
                             afl[mt][0], afl[mt][1], afl[mt][2], afl[mt][3],
                             bfh[nt][0], bfh[nt][1]);
        }
        __syncthreads();
        buf ^= 1;
    }

    #pragma unroll
    for (int mt = 0; mt < 4; mt++) {
        int r0 = warpM*64 + mt*16 + gid;
        #pragma unroll
        for (int nt = 0; nt < 8; nt++) {
            int c0 = warpN*64 + nt*8 + tig*2;
            *(float2*)(Cb + (size_t) r0      * N + c0) = make_float2(acc[mt][nt][0], acc[mt][nt][1]);
            *(float2*)(Cb + (size_t)(r0 + 8) * N + c0) = make_float2(acc[mt][nt][2], acc[mt][nt][3]);
        }
    }
}

// ---- RMSnorm + RoPE (+gain), q and k fused, fp16 output --------------------
__global__ void normrope_h_kernel(const float* __restrict__ QKV,
                                  const float* __restrict__ gain,
                                  __half* __restrict__ Qh,
                                  __half* __restrict__ Kh)
{
    int gthr = blockIdx.x * blockDim.x + threadIdx.x;
    int w    = gthr >> 5;
    int lane = gthr & 31;
    int total = BT * (NH + NHKV);
    if (w >= total) return;

    const float* src;
    __half* dst;
    float g = 1.0f;
    int bt;
    if (w < BT * NH) {
        bt = w / NH;
        int hh = w % NH;
        src = QKV + (size_t)bt * QKVD + hh * HD;
        dst = Qh  + (size_t)bt * DIM  + hh * HD;
        g = gain[hh];
    } else {
        int w2 = w - BT * NH;
        bt = w2 / NHKV;
        int hh = w2 % NHKV;
        src = QKV + (size_t)bt * QKVD + KOFF + hh * HD;
        dst = Kh  + (size_t)bt * KVDIM + hh * HD;
    }
    int t = bt % TSEQ;

    float v0 = src[lane], v1 = src[lane+32], v2 = src[lane+64], v3 = src[lane+96];
    float ss = v0*v0 + v1*v1 + v2*v2 + v3*v3;
    #pragma unroll
    for (int o = 16; o; o >>= 1) ss += __shfl_xor_sync(0xffffffffu, ss, o);

    float f = rsqrtf(ss * (1.0f/128.0f) + 1.1920929e-7f) * g;

    float invfreq = powf(10000.0f, -(float)lane * (1.0f/32.0f));
    float ang = (float)t * invfreq;
    float s, c;
    sincosf(ang, &s, &c);

    dst[lane]    = __float2half(( v0*c + v1*s) * f);
    dst[lane+32] = __float2half((-v0*s + v1*c) * f);
    dst[lane+64] = __float2half(v2 * f);
    dst[lane+96] = __float2half(v3 * f);
}

// ---- V transpose to fp16: Vt[b][kh][hd][t] ---------------------------------
__global__ void vtrans_kernel(const float* __restrict__ QKV,
                              __half* __restrict__ Vt)
{
    __shared__ float tile[32][33];
    int bk = blockIdx.z;                 // b*NHKV + kh
    int b  = bk / NHKV, kh = bk % NHKV;
    int t0 = blockIdx.x * 32;
    int c0 = blockIdx.y * 32;
    int tx = threadIdx.x, ty = threadIdx.y;   // 32 x 8

    #pragma unroll
    for (int i = 0; i < 4; i++) {
        int t = t0 + ty + i*8;
        tile[ty + i*8][tx] = QKV[(size_t)(b*TSEQ + t) * QKVD + VOFF + kh*HD + c0 + tx];
    }
    __syncthreads();
    #pragma unroll
    for (int i = 0; i < 4; i++) {
        int c = c0 + ty + i*8;
        Vt[((size_t)bk * HD + c) * TSEQ + t0 + tx] = __float2half(tile[tx][ty + i*8]);
    }
}

// ---------------- fp16 tensor-core causal flash attention (v2) -------------
#define AQ   128
#define AK   64
#define QSTR 136
#define KSTR 136
#define VSTR 72
#define K_TILE_B  (AK*KSTR*2)   // 17408
#define V_TILE_B  (HD*VSTR*2)   // 18432
#define ATT_SMEM_H (AQ*QSTR*2 + 2*K_TILE_B + 2*V_TILE_B)   // 106496 bytes

__global__ __launch_bounds__(256)
void attn_mma_kernel(const __half* __restrict__ Qh,
                     const __half* __restrict__ Kh,
                     const __half* __restrict__ Vth,
                     float* __restrict__ Y)
{
    extern __shared__ __half smh[];
    __half* Qs  = smh;                    // [AQ][QSTR]
    __half* Ksm = Qs + AQ*QSTR;           // 2 x [AK][KSTR]
    __half* Vsm = Ksm + 2*AK*KSTR;        // 2 x [HD][VSTR]

    int qt = blockIdx.x, h = blockIdx.y, b = blockIdx.z;
    int kh = h / GROUP;
    int q0 = qt * AQ;
    int tid = threadIdx.x;
    int warp = tid >> 5, lane = tid & 31;
    int gid = lane >> 2, tig = lane & 3;
    int wr = warp * 16;

    const float scale = 0.08838834764831845f;  // 128^-0.5

    uint32_t uK = (uint32_t)__cvta_generic_to_shared(Ksm);
    uint32_t uV = (uint32_t)__cvta_generic_to_shared(Vsm);

    for (int e = tid; e < AQ*16; e += 256) {
        int r = e >> 4, c = e & 15;
        *(uint4*)(Qs + r*QSTR + c*8) =
            *(const uint4*)(Qh + (size_t)(b*TSEQ + q0 + r)*DIM + h*HD + c*8);
    }

    const __half* Kbase = Kh  + (size_t)(b*TSEQ)*KVDIM + kh*HD;
    const __half* Vbase = Vth + ((size_t)(b*NHKV + kh))*HD*TSEQ;

    int kr  = tid >> 2;
    int kcb = (tid & 3) * 4;
    int vr  = tid >> 1;
    int vcb = (tid & 1) * 4;
    auto prefetch = [&](int s, int kt) {
        int s0 = kt * AK;
        uint32_t kd = uK + (uint32_t)s * K_TILE_B;
        const __half* ksrc = Kbase + (size_t)(s0 + kr) * KVDIM;
        #pragma unroll
        for (int j = 0; j < 4; j++)
            cpa16(kd + (uint32_t)(kr*KSTR + (kcb+j)*8)*2, ksrc + (kcb+j)*8);
        uint32_t vd = uV + (uint32_t)s * V_TILE_B;
        const __half* vsrc = Vbase + (size_t)vr * TSEQ + s0;
        #pragma unroll
        for (int j = 0; j < 4; j++)
            cpa16(vd + (uint32_t)(vr*VSTR + (vcb+j)*8)*2, vsrc + (vcb+j)*8);
        cpa_commit();
    };

    float m0 = -CUDART_INF_F, m1 = -CUDART_INF_F;
    float l0 = 0.0f, l1 = 0.0f;
    float o[16][4];
    #pragma unroll
    for (int on = 0; on < 16; on++)
        #pragma unroll
        for (int i = 0; i < 4; i++) o[on][i] = 0.0f;

    int nkt = 2*qt + 2;
    prefetch(0, 0);

    for (int kt = 0; kt < nkt; kt++) {
        int s0 = kt * AK;
        cpa_wait0();
        __syncthreads();
        if (kt + 1 < nkt) prefetch((kt + 1) & 1, kt + 1);

        const __half* Ks = Ksm + (kt & 1) * AK*KSTR;
        const __half* Vt = Vsm + (kt & 1) * HD*VSTR;

        float sacc[8][4];
        #pragma unroll
        for (int nt = 0; nt < 8; nt++)
            #pragma unroll
            for (int i = 0; i < 4; i++) sacc[nt][i] = 0.0f;

        #pragma unroll
        for (int ks = 0; ks < 8; ks++) {
            const __half* qb = Qs + (wr + gid)*QSTR + ks*16 + 2*tig;
            uint32_t a0 = *(const uint32_t*)(qb);
            uint32_t a1 = *(const uint32_t*)(qb + 8*QSTR);
            uint32_t a2 = *(const uint32_t*)(qb + 8);
            uint32_t a3 = *(const uint32_t*)(qb + 8*QSTR + 8);
            #pragma unroll
            for (int nt = 0; nt < 8; nt++) {
                const __half* kb = Ks + (nt*8 + gid)*KSTR + ks*16 + 2*tig;
                uint32_t b0 = *(const uint32_t*)(kb);
                uint32_t b1 = *(const uint32_t*)(kb + 8);
                mma_f16(sacc[nt][0], sacc[nt][1], sacc[nt][2], sacc[nt][3],
                        a0, a1, a2, a3, b0, b1);
            }
        }

        #pragma unroll
        for (int nt = 0; nt < 8; nt++)
            #pragma unroll
            for (int i = 0; i < 4; i++) sacc[nt][i] *= scale;

        if (s0 + AK - 1 > q0 + wr) {
            int r0g = q0 + wr + gid;
            #pragma unroll
            for (int nt = 0; nt < 8; nt++) {
                int sb = s0 + nt*8 + 2*tig;
                if (sb     > r0g)     sacc[nt][0] = -CUDART_INF_F;
                if (sb + 1 > r0g)     sacc[nt][1] = -CUDART_INF_F;
                if (sb     > r0g + 8) sacc[nt][2] = -CUDART_INF_F;
                if (sb + 1 > r0g + 8) sacc[nt][3] = -CUDART_INF_F;
            }
        }

        float mx0 = -CUDART_INF_F, mx1 = -CUDART_INF_F;
        #pragma unroll
        for (int nt = 0; nt < 8; nt++) {
            mx0 = fmaxf(mx0, fmaxf(sacc[nt][0], sacc[nt][1]));
            mx1 = fmaxf(mx1, fmaxf(sacc[nt][2], sacc[nt][3]));
        }
        #pragma unroll
        for (int off = 1; off <= 2; off <<= 1) {
            mx0 = fmaxf(mx0, __shfl_xor_sync(0xffffffffu, mx0, off));
            mx1 = fmaxf(mx1, __shfl_xor_sync(0xffffffffu, mx1, off));
        }
        float mn0 = fmaxf(m0, mx0), mn1 = fmaxf(m1, mx1);
        float corr0 = __expf(m0 - mn0), corr1 = __expf(m1 - mn1);
        m0 = mn0; m1 = mn1;

        float sum0 = 0.0f, sum1 = 0.0f;
        #pragma unroll
        for (int nt = 0; nt < 8; nt++) {
            sacc[nt][0] = __expf(sacc[nt][0] - mn0);
            sacc[nt][1] = __expf(sacc[nt][1] - mn0);
            sacc[nt][2] = __expf(sacc[nt][2] - mn1);
            sacc[nt][3] = __expf(sacc[nt][3] - mn1);
            sum0 += sacc[nt][0] + sacc[nt][1];
            sum1 += sacc[nt][2] + sacc[nt][3];
        }
        #pragma unroll
        for (int off = 1; off <= 2; off <<= 1) {
            sum0 += __shfl_xor_sync(0xffffffffu, sum0, off);
            sum1 += __shfl_xor_sync(0xffffffffu, sum1, off);
        }
        l0 = l0 * corr0 + sum0;
        l1 = l1 * corr1 + sum1;

        #pragma unroll
        for (int on = 0; on < 16; on++) {
            o[on][0] *= corr0; o[on][1] *= corr0;
            o[on][2] *= corr1; o[on][3] *= corr1;
        }

        #pragma unroll
        for (int ks2 = 0; ks2 < 4; ks2++) {
            __half2 pa0 = __floats2half2_rn(sacc[2*ks2][0],   sacc[2*ks2][1]);
            __half2 pa1 = __floats2half2_rn(sacc[2*ks2][2],   sacc[2*ks2][3]);
            __half2 pa2 = __floats2half2_rn(sacc[2*ks2+1][0], sacc[2*ks2+1][1]);
            __half2 pa3 = __floats2half2_rn(sacc[2*ks2+1][2], sacc[2*ks2+1][3]);
            uint32_t a0 = *reinterpret_cast<uint32_t*>(&pa0);
            uint32_t a1 = *reinterpret_cast<uint32_t*>(&pa1);
            uint32_t a2 = *reinterpret_cast<uint32_t*>(&pa2);
            uint32_t a3 = *reinterpret_cast<uint32_t*>(&pa3);
            #pragma unroll
            for (int on = 0; on < 16; on++) {
                const __half* vb = Vt + (on*8 + gid)*VSTR + ks2*16 + 2*tig;
                uint32_t b0 = *(const uint32_t*)(vb);
                uint32_t b1 = *(const uint32_t*)(vb + 8);
                mma_f16(o[on][0], o[on][1], o[on][2], o[on][3],
                        a0, a1, a2, a3, b0, b1);
            }
        }
    }

    float il0 = 1.0f / l0, il1 = 1.0f / l1;
    int r0 = q0 + wr + gid;
    #pragma unroll
    for (int on = 0; on < 16; on++) {
        int c0 = h*HD + on*8 + 2*tig;
        *(float2*)(Y + (size_t)(b*TSEQ + r0)     * DIM + c0) = make_float2(o[on][0]*il0, o[on][1]*il0);
        *(float2*)(Y + (size_t)(b*TSEQ + r0 + 8) * DIM + c0) = make_float2(o[on][2]*il1, o[on][3]*il1);
    }
}

// ---- v-direction projection removal, fused with bf16 hi/lo split ----------
__global__ void vproj_split_kernel(const float* __restrict__ V, int vstride,
                                   const float* __restrict__ Yin,
                                   __nv_bfloat16* __restrict__ YH,
                                   __nv_bfloat16* __restrict__ YL)
{
    int gthr = blockIdx.x * blockDim.x + threadIdx.x;
    int w    = gthr >> 5;
    int lane = gthr & 31;
    if (w >= BT * NHKV) return;
    int bt = w / NHKV, kh = w % NHKV;

    const float* vrow = V + (size_t)bt * vstride + kh * HD;
    float v0 = vrow[lane], v1 = vrow[lane+32], v2 = vrow[lane+64], v3 = vrow[lane+96];
    float ss = v0*v0 + v1*v1 + v2*v2 + v3*v3;
    #pragma unroll
    for (int o = 16; o; o >>= 1) ss += __shfl_xor_sync(0xffffffffu, ss, o);
    float norm = sqrtf(ss);
    float inv = 1.0f / fmaxf(norm, 1e-12f);
    float n0 = v0*inv, n1 = v1*inv, n2 = v2*inv, n3 = v3*inv;

    #pragma unroll
    for (int g = 0; g < GROUP; g++) {
        int hh = kh * GROUP + g;
        size_t base = (size_t)bt * DIM + hh * HD;
        const float* yrow = Yin + base;
        float y0 = yrow[lane], y1 = yrow[lane+32], y2 = yrow[lane+64], y3 = yrow[lane+96];
        float d = y0*n0 + y1*n1 + y2*n2 + y3*n3;
        #pragma unroll
        for (int o = 16; o; o >>= 1) d += __shfl_xor_sync(0xffffffffu, d, o);
        float r0 = y0 - d*n0, r1 = y1 - d*n1, r2 = y2 - d*n2, r3 = y3 - d*n3;

        __nv_bfloat16 h0 = __float2bfloat16_rn(r0), h1 = __float2bfloat16_rn(r1);
        __nv_bfloat16 h2 = __float2bfloat16_rn(r2), h3 = __float2bfloat16_rn(r3);
        YH[base + lane]    = h0;  YL[base + lane]    = __float2bfloat16_rn(r0 - __bfloat162float(h0));
        YH[base + lane+32] = h1;  YL[base + lane+32] = __float2bfloat16_rn(r1 - __bfloat162float(h1));
        YH[base + lane+64] = h2;  YL[base + lane+64] = __float2bfloat16_rn(r2 - __bfloat162float(h2));
        YH[base + lane+96] = h3;  YL[base + lane+96] = __float2bfloat16_rn(r3 - __bfloat162float(h3));
    }
}

// ---------------- launcher --------------------------------------------------
extern "C" void kernel_launch(void* const* d_in, const int* in_sizes, int n_in,
                              void* d_out, int out_size)
{
    const float* x     = (const float*)d_in[0];
    const float* Wq    = (const float*)d_in[1];
    const float* Wk    = (const float*)d_in[2];
    const float* Wv    = (const float*)d_in[3];
    const float* Wp    = (const float*)d_in[4];
    const float* qgain = (const float*)d_in[5];
    const float* qA    = (const float*)d_in[6];
    const float* qB    = (const float*)d_in[7];
    const float* kA    = (const float*)d_in[8];
    const float* kB    = (const float*)d_in[9];
    const float* vA    = (const float*)d_in[10];
    const float* vB    = (const float*)d_in[11];
    const float* pA    = (const float*)d_in[12];
    const float* pB    = (const float*)d_in[13];
    float* out = (float*)d_out;

    __nv_bfloat16 *wh, *wl, *wph, *wpl, *xh, *xl, *yh, *yl;
    float *qkv, *y;
    __half *qh, *kh2, *vth;
    cudaGetSymbolAddress((void**)&wh,  g_WqkvTh); cudaGetSymbolAddress((void**)&wl,  g_WqkvTl);
    cudaGetSymbolAddress((void**)&wph, g_WpTh);   cudaGetSymbolAddress((void**)&wpl, g_WpTl);
    cudaGetSymbolAddress((void**)&xh,  g_xh);     cudaGetSymbolAddress((void**)&xl,  g_xl);
    cudaGetSymbolAddress((void**)&yh,  g_yh);     cudaGetSymbolAddress((void**)&yl,  g_yl);
    cudaGetSymbolAddress((void**)&qkv, g_qkv);
    cudaGetSymbolAddress((void**)&y,   g_y);
    cudaGetSymbolAddress((void**)&qh,  g_qh);
    cudaGetSymbolAddress((void**)&kh2, g_kh);
    cudaGetSymbolAddress((void**)&vth, g_vth);

    const int GSMEM = (8*TBM*STR) * (int)sizeof(__nv_bfloat16);
    cudaFuncSetAttribute(bf16x3gemm_kernel<QKVD, DIM>, cudaFuncAttributeMaxDynamicSharedMemorySize, GSMEM);
    cudaFuncSetAttribute(bf16x3gemm_kernel<DIM, DIM>,  cudaFuncAttributeMaxDynamicSharedMemorySize, GSMEM);
    cudaFuncSetAttribute(attn_mma_kernel, cudaFuncAttributeMaxDynamicSharedMemorySize, ATT_SMEM_H);

    // launch 0: effective weights q,k
    dim3 tb(32, 8);
    effw_pair_kernel<<<dim3(DIM/32, DIM/32, 2), tb>>>(
        Wq, qA, qB, wh,                    wl,                    DIM,
        Wk, kA, kB, wh + (size_t)KOFF*DIM, wl + (size_t)KOFF*DIM, KVDIM);
    // launch 1: effective weights v,p
    effw_pair_kernel<<<dim3(DIM/32, DIM/32, 2), tb>>>(
        Wv, vA, vB, wh + (size_t)VOFF*DIM, wl + (size_t)VOFF*DIM, KVDIM,
        Wp, pA, pB, wph,                   wpl,                   DIM);

    // launch 2: split x
    split_kernel<<<(BT*DIM/4 + 255)/256, 256>>>(x, BT*DIM/4, xh, xl);

    // launch 3 (profiled): fused qkv projection (term-major bf16x3)
    dim3 gqkv(QKVD/TBN, BT/TBM);
    bf16x3gemm_kernel<QKVD, DIM><<<gqkv, 128, GSMEM>>>(xh, xl, wh, wl, qkv);

    // launch 4: fused per-head RMSnorm + RoPE -> fp16 q/k
    {
        int wn = BT * (NH + NHKV);
        normrope_h_kernel<<<(wn*32 + 255)/256, 256>>>(qkv, qgain, qh, kh2);
    }

    // launch 5: V transpose -> fp16 Vt[b][kh][hd][t]
    vtrans_kernel<<<dim3(TSEQ/32, HD/32, BSZ*NHKV), tb>>>(qkv, vth);

    // launch 6: causal flash attention
    {
        dim3 ga(TSEQ/AQ, NH, BSZ);
        attn_mma_kernel<<<ga, 256, ATT_SMEM_H>>>(qh, kh2, vth, y);
    }

    // launch 7: v-projection removal + bf16 split
    {
        int wv_n = BT * NHKV;
        vproj_split_kernel<<<(wv_n*32 + 255)/256, 256>>>(qkv + VOFF, QKVD, y, yh, yl);
    }

    // launch 8: output projection (term-major bf16x3)
    dim3 gp(DIM/TBN, BT/TBM);
    bf16x3gemm_kernel<DIM, DIM><<<gp, 128, GSMEM>>>(yh, yl, wph, wpl, out);
}

// round 15
// speedup vs baseline: 1.0918x; 1.0126x over previous
#include <cuda_runtime.h>
#include <cuda_bf16.h>
#include <cuda_fp16.h>
#include <math.h>
#include <math_constants.h>
#include <stdint.h>

// Problem constants
#define BSZ   2
#define TSEQ  2048
#define DIM   2048
#define NH    16
#define NHKV  4
#define HD    128
#define KVDIM (NHKV*HD)     // 512
#define GROUP (NH/NHKV)     // 4
#define RANK  16
#define BT    (BSZ*TSEQ)    // 4096
#define QKVD  (DIM + 2*KVDIM)   // 3072
#define KOFF  DIM               // 2048
#define VOFF  (DIM + KVDIM)     // 2560

// ---------------- scratch (device globals; no allocation allowed) ----------
__device__ __nv_bfloat16 g_WqkvTh[QKVD*DIM], g_WqkvTl[QKVD*DIM];  // [3072][2048]
__device__ __nv_bfloat16 g_WpTh[DIM*DIM],    g_WpTl[DIM*DIM];
__device__ __nv_bfloat16 g_xh[BT*DIM],  g_xl[BT*DIM];
__device__ __nv_bfloat16 g_yh[BT*DIM],  g_yl[BT*DIM];
__device__ float  g_qkv[BT*QKVD];
__device__ float  g_y[BT*DIM];
__device__ __half g_qh[BT*DIM];
__device__ __half g_kh[BT*KVDIM];
__device__ __half g_vth[BSZ*NHKV*HD*TSEQ];         // fp16 V transposed [b][kh][hd][t]

__device__ __forceinline__ float fexp2(float x) {
    float y;
    asm("ex2.approx.f32 %0, %1;" : "=f"(y) : "f"(x));
    return y;
}

// ---- fused prologue: 4x effw (transpose+LoRA+split) and x-split, one grid --
// blocks [0,4096): Wq  [4096,5120): Wk  [5120,6144): Wv  [6144,10240): Wp
// blocks [10240, 18432): split x (8192 blocks)
#define PRO_EFFW   10240
#define PRO_TOTAL  18432

__global__ __launch_bounds__(256)
void prologue_kernel(const float* __restrict__ x,
                     const float* __restrict__ Wq, const float* __restrict__ qA, const float* __restrict__ qB,
                     const float* __restrict__ Wk, const float* __restrict__ kA, const float* __restrict__ kB,
                     const float* __restrict__ Wv, const float* __restrict__ vA, const float* __restrict__ vB,
                     const float* __restrict__ Wp, const float* __restrict__ pA, const float* __restrict__ pB,
                     __nv_bfloat16* __restrict__ wh,  __nv_bfloat16* __restrict__ wl,
                     __nv_bfloat16* __restrict__ wph, __nv_bfloat16* __restrict__ wpl,
                     __nv_bfloat16* __restrict__ xh,  __nv_bfloat16* __restrict__ xl)
{
    __shared__ float tile[32][33];
    int bid = blockIdx.x;
    int tid = threadIdx.x;

    if (bid < PRO_EFFW) {
        const float *W, *A, *Bm;
        __nv_bfloat16 *H, *L;
        int N, local;
        if (bid < 4096)      { W=Wq; A=qA; Bm=qB; H=wh;                     L=wl;                     N=DIM;   local=bid; }
        else if (bid < 5120) { W=Wk; A=kA; Bm=kB; H=wh+(size_t)KOFF*DIM;    L=wl+(size_t)KOFF*DIM;    N=KVDIM; local=bid-4096; }
        else if (bid < 6144) { W=Wv; A=vA; Bm=vB; H=wh+(size_t)VOFF*DIM;    L=wl+(size_t)VOFF*DIM;    N=KVDIM; local=bid-5120; }
        else                 { W=Wp; A=pA; Bm=pB; H=wph;                    L=wpl;                    N=DIM;   local=bid-6144; }
        int nbx = N >> 5;
        int tn = (local % nbx) * 32;
        int tk = (local / nbx) * 32;
        int tx = tid & 31, ty = tid >> 5;   // 32 x 8

        #pragma unroll
        for (int i = 0; i < 4; i++) {
            int k = tk + ty + i*8;
            int n = tn + tx;
            float s = W[(size_t)k * N + n];
            #pragma unroll
            for (int r = 0; r < RANK; r++)
                s += A[k*RANK + r] * Bm[r*N + n];
            tile[ty + i*8][tx] = s;
        }
        __syncthreads();
        #pragma unroll
        for (int i = 0; i < 4; i++) {
            int n = tn + ty + i*8;
            int k = tk + tx;
            float s = tile[tx][ty + i*8];
            __nv_bfloat16 h = __float2bfloat16_rn(s);
            H[(size_t)n * DIM + k] = h;
            L[(size_t)n * DIM + k] = __float2bfloat16_rn(s - __bfloat162float(h));
        }
    } else {
        int idx = (bid - PRO_EFFW) * 256 + tid;   // < BT*DIM/4
        float4 v = ((const float4*)x)[idx];
        __nv_bfloat16 h0 = __float2bfloat16_rn(v.x), h1 = __float2bfloat16_rn(v.y);
        __nv_bfloat16 h2 = __float2bfloat16_rn(v.z), h3 = __float2bfloat16_rn(v.w);
        __nv_bfloat162 hh0 = {h0, h1}, hh1 = {h2, h3};
        __nv_bfloat162 ll0 = {__float2bfloat16_rn(v.x - __bfloat162float(h0)),
                              __float2bfloat16_rn(v.y - __bfloat162float(h1))};
        __nv_bfloat162 ll1 = {__float2bfloat16_rn(v.z - __bfloat162float(h2)),
                              __float2bfloat16_rn(v.w - __bfloat162float(h3))};
        ((__nv_bfloat162*)xh)[idx*2]   = hh0;
        ((__nv_bfloat162*)xh)[idx*2+1] = hh1;
        ((__nv_bfloat162*)xl)[idx*2]   = ll0;
        ((__nv_bfloat162*)xl)[idx*2+1] = ll1;
    }
}

// ---------------- bf16x3 tensor-core GEMM (ldmatrix, term-major) -----------
#define TBM 128
#define TBN 128
#define TBK 32
#define STR 40

__device__ __forceinline__ void cpa16(uint32_t dst, const void* src) {
    asm volatile("cp.async.cg.shared.global [%0], [%1], 16;\n" :: "r"(dst), "l"(src));
}
__device__ __forceinline__ void cpa_commit() {
    asm volatile("cp.async.commit_group;\n");
}
__device__ __forceinline__ void cpa_wait0() {
    asm volatile("cp.async.wait_group 0;\n");
}
__device__ __forceinline__ void ldsm_x4(uint32_t& r0, uint32_t& r1, uint32_t& r2, uint32_t& r3,
                                        uint32_t addr) {
    asm volatile("ldmatrix.sync.aligned.m8n8.x4.shared.b16 {%0,%1,%2,%3}, [%4];"
                 : "=r"(r0), "=r"(r1), "=r"(r2), "=r"(r3) : "r"(addr));
}
__device__ __forceinline__ void mma_bf16(float& d0, float& d1, float& d2, float& d3,
                                         uint32_t a0, uint32_t a1, uint32_t a2, uint32_t a3,
                                         uint32_t b0, uint32_t b1) {
    asm volatile(
        "mma.sync.aligned.m16n8k16.row.col.f32.bf16.bf16.f32 "
        "{%0,%1,%2,%3}, {%4,%5,%6,%7}, {%8,%9}, {%0,%1,%2,%3};\n"
        : "+f"(d0), "+f"(d1), "+f"(d2), "+f"(d3)
        : "r"(a0), "r"(a1), "r"(a2), "r"(a3), "r"(b0), "r"(b1));
}
__device__ __forceinline__ void mma_f16(float& d0, float& d1, float& d2, float& d3,
                                        uint32_t a0, uint32_t a1, uint32_t a2, uint32_t a3,
                                        uint32_t b0, uint32_t b1) {
    asm volatile(
        "mma.sync.aligned.m16n8k16.row.col.f32.f16.f16.f32 "
        "{%0,%1,%2,%3}, {%4,%5,%6,%7}, {%8,%9}, {%0,%1,%2,%3};\n"
        : "+f"(d0), "+f"(d1), "+f"(d2), "+f"(d3)
        : "r"(a0), "r"(a1), "r"(a2), "r"(a3), "r"(b0), "r"(b1));
}

template<int N, int K>
__global__ __launch_bounds__(128)
void bf16x3gemm_kernel(const __nv_bfloat16* __restrict__ Ah,
                       const __nv_bfloat16* __restrict__ Al,
                       const __nv_bfloat16* __restrict__ Bh,   // [N][K]
                       const __nv_bfloat16* __restrict__ Bl,
                       float* __restrict__ C)
{
    extern __shared__ __nv_bfloat16 smem[];
    __nv_bfloat16* sAh = smem;
    __nv_bfloat16* sAl = sAh + 2*TBM*STR;
    __nv_bfloat16* sBh = sAl + 2*TBM*STR;
    __nv_bfloat16* sBl = sBh + 2*TBN*STR;

    int tid  = threadIdx.x;
    int warp = tid >> 5, lane = tid & 31;
    int warpM = warp >> 1, warpN = warp & 1;
    int gid = lane >> 2, tig = lane & 3;

    const __nv_bfloat16* Ahb = Ah + (size_t)blockIdx.y * TBM * K;
    const __nv_bfloat16* Alb = Al + (size_t)blockIdx.y * TBM * K;
    const __nv_bfloat16* Bhb = Bh + (size_t)blockIdx.x * TBN * K;
    const __nv_bfloat16* Blb = Bl + (size_t)blockIdx.x * TBN * K;
    float* Cb = C + (size_t)blockIdx.y * TBM * N + (size_t)blockIdx.x * TBN;

    int srow = tid >> 2;
    int scol = (tid & 3) * 8;

    uint32_t uAh = (uint32_t)__cvta_generic_to_shared(sAh);
    uint32_t uAl = (uint32_t)__cvta_generic_to_shared(sAl);
    uint32_t uBh = (uint32_t)__cvta_generic_to_shared(sBh);
    uint32_t uBl = (uint32_t)__cvta_generic_to_shared(sBl);

    uint32_t laneA = (uint32_t)(((lane & 15) * STR + (lane >> 4) * 8) * 2);
    uint32_t laneB = (uint32_t)((((lane & 7) + ((lane >> 4) << 3)) * STR) * 2 + ((lane >> 3) & 1) * 16);

    float acc[4][8][4];
    #pragma unroll
    for (int m = 0; m < 4; m++)
        #pragma unroll
        for (int n = 0; n < 8; n++)
            #pragma unroll
            for (int i = 0; i < 4; i++) acc[m][n][i] = 0.0f;

    constexpr int ntiles = K / TBK;

    auto issue = [&](int buf, int kt) {
        uint32_t bofs = (uint32_t)(buf * TBM * STR * 2);
        #pragma unroll
        for (int i = 0; i < 4; i++) {
            int r = srow + i * 32;
            uint32_t dofs = (uint32_t)((r * STR + scol) * 2);
            size_t gofs = (size_t)r * K + (size_t)kt * TBK + scol;
            cpa16(uAh + bofs + dofs, Ahb + gofs);
            cpa16(uAl + bofs + dofs, Alb + gofs);
            cpa16(uBh + bofs + dofs, Bhb + gofs);
            cpa16(uBl + bofs + dofs, Blb + gofs);
        }
        cpa_commit();
    };

    issue(0, 0);
    int buf = 0;

    for (int kt = 0; kt < ntiles; kt++) {
        cpa_wait0();
        __syncthreads();
        if (kt + 1 < ntiles) issue(buf ^ 1, kt + 1);

        uint32_t bufofs = (uint32_t)(buf * TBM * STR * 2);
        uint32_t aH = uAh + bufofs, aL = uAl + bufofs;
        uint32_t bH = uBh + bufofs, bL = uBl + bufofs;

        #pragma unroll
        for (int ks = 0; ks < TBK; ks += 16) {
            uint32_t afh[4][4], afl[4][4];
            #pragma unroll
            for (int mt = 0; mt < 4; mt++) {
                uint32_t ofs = (uint32_t)(((warpM*64 + mt*16) * STR + ks) * 2) + laneA;
                ldsm_x4(afh[mt][0], afh[mt][1], afh[mt][2], afh[mt][3], aH + ofs);
                ldsm_x4(afl[mt][0], afl[mt][1], afl[mt][2], afl[mt][3], aL + ofs);
            }
            uint32_t bfh[8][2], bfl[8][2];
            #pragma unroll
            for (int np = 0; np < 4; np++) {
                uint32_t ofs = (uint32_t)(((warpN*64 + np*16) * STR + ks) * 2) + laneB;
                ldsm_x4(bfh[2*np][0], bfh[2*np][1], bfh[2*np+1][0], bfh[2*np+1][1], bH + ofs);
                ldsm_x4(bfl[2*np][0], bfl[2*np][1], bfl[2*np+1][0], bfl[2*np+1][1], bL + ofs);
            }
            #pragma unroll
            for (int mt = 0; mt < 4; mt++)
                #pragma unroll
                for (int nt = 0; nt < 8; nt++)
                    mma_bf16(acc[mt][nt][0], acc[mt][nt][1], acc[mt][nt][2], acc[mt][nt][3],
                             afh[mt][0], afh[mt][1], afh[mt][2], afh[mt][3],
                             bfh[nt][0], bfh[nt][1]);
            #pragma unroll
            for (int mt = 0; mt < 4; mt++)
                #pragma unroll
                for (int nt = 0; nt < 8; nt++)
                    mma_bf16(acc[mt][nt][0], acc[mt][nt][1], acc[mt][nt][2], acc[mt][nt][3],
                             afh[mt][0], afh[mt][1], afh[mt][2], afh[mt][3],
                             bfl[nt][0], bfl[nt][1]);
            #pragma unroll
            for (int mt = 0; mt < 4; mt++)
                #pragma unroll
                for (int nt = 0; nt < 8; nt++)
                    mma_bf16(acc[mt][nt][0], acc[mt][nt][1], acc[mt][nt][2], acc[mt][nt][3],
                             afl[mt][0], afl[mt][1], afl[mt][2], afl[mt][3],
                             bfh[nt][0], bfh[nt][1]);
        }
        __syncthreads();
        buf ^= 1;
    }

    #pragma unroll
    for (int mt = 0; mt < 4; mt++) {
        int r0 = warpM*64 + mt*16 + gid;
        #pragma unroll
        for (int nt = 0; nt < 8; nt++) {
            int c0 = warpN*64 + nt*8 + tig*2;
            *(float2*)(Cb + (size_t) r0      * N + c0) = make_float2(acc[mt][nt][0], acc[mt][nt][1]);
            *(float2*)(Cb + (size_t)(r0 + 8) * N + c0) = make_float2(acc[mt][nt][2], acc[mt][nt][3]);
        }
    }
}

// ---- fused mid: normrope (fp16 q/k) + V transpose, one grid ---------------
// blocks [0, 10240): normrope warps; [10240, 12288): vtrans tiles
#define MID_NR    10240
#define MID_TOTAL 12288

__global__ __launch_bounds__(256)
void mid_kernel(const float* __restrict__ QKV,
                const float* __restrict__ gain,
                __half* __restrict__ Qh,
                __half* __restrict__ Kh,
                __half* __restrict__ Vt)
{
    __shared__ float tile[32][33];
    int bid = blockIdx.x;
    int tid = threadIdx.x;

    if (bid < MID_NR) {
        int gthr = bid * 256 + tid;
        int w    = gthr >> 5;
        int lane = gthr & 31;

        const float* src;
        __half* dst;
        float g = 1.0f;
        int bt;
        if (w < BT * NH) {
            bt = w / NH;
            int hh = w % NH;
            src = QKV + (size_t)bt * QKVD + hh * HD;
            dst = Qh  + (size_t)bt * DIM  + hh * HD;
            g = gain[hh];
        } else {
            int w2 = w - BT * NH;
            bt = w2 / NHKV;
            int hh = w2 % NHKV;
            src = QKV + (size_t)bt * QKVD + KOFF + hh * HD;
            dst = Kh  + (size_t)bt * KVDIM + hh * HD;
        }
        int t = bt % TSEQ;

        float v0 = src[lane], v1 = src[lane+32], v2 = src[lane+64], v3 = src[lane+96];
        float ss = v0*v0 + v1*v1 + v2*v2 + v3*v3;
        #pragma unroll
        for (int o = 16; o; o >>= 1) ss += __shfl_xor_sync(0xffffffffu, ss, o);

        float f = rsqrtf(ss * (1.0f/128.0f) + 1.1920929e-7f) * g;

        float invfreq = powf(10000.0f, -(float)lane * (1.0f/32.0f));
        float ang = (float)t * invfreq;
        float s, c;
        sincosf(ang, &s, &c);

        dst[lane]    = __float2half(( v0*c + v1*s) * f);
        dst[lane+32] = __float2half((-v0*s + v1*c) * f);
        dst[lane+64] = __float2half(v2 * f);
        dst[lane+96] = __float2half(v3 * f);
    } else {
        int local = bid - MID_NR;           // 0..2047 = 64 x 4 x 8
        int t0 = (local & 63) * 32;
        int c0 = ((local >> 6) & 3) * 32;
        int bk = local >> 8;                // b*NHKV + kh
        int b  = bk / NHKV, kh = bk % NHKV;
        int tx = tid & 31, ty = tid >> 5;   // 32 x 8

        #pragma unroll
        for (int i = 0; i < 4; i++) {
            int t = t0 + ty + i*8;
            tile[ty + i*8][tx] = QKV[(size_t)(b*TSEQ + t) * QKVD + VOFF + kh*HD + c0 + tx];
        }
        __syncthreads();
        #pragma unroll
        for (int i = 0; i < 4; i++) {
            int c = c0 + ty + i*8;
            Vt[((size_t)bk * HD + c) * TSEQ + t0 + tx] = __float2half(tile[tx][ty + i*8]);
        }
    }
}

// ---------------- fp16 tensor-core causal flash attention (exp2) -----------
#define AQ   128
#define AK   64
#define QSTR 136
#define KSTR 136
#define VSTR 72
#define K_TILE_B  (AK*KSTR*2)   // 17408
#define V_TILE_B  (HD*VSTR*2)   // 18432
#define ATT_SMEM_H (AQ*QSTR*2 + 2*K_TILE_B + 2*V_TILE_B)   // 106496 bytes

__global__ __launch_bounds__(256)
void attn_mma_kernel(const __half* __restrict__ Qh,
                     const __half* __restrict__ Kh,
                     const __half* __restrict__ Vth,
                     float* __restrict__ Y)
{
    extern __shared__ __half smh[];
    __half* Qs  = smh;                    // [AQ][QSTR]
    __half* Ksm = Qs + AQ*QSTR;           // 2 x [AK][KSTR]
    __half* Vsm = Ksm + 2*AK*KSTR;        // 2 x [HD][VSTR]

    int qt = blockIdx.x, h = blockIdx.y, b = blockIdx.z;
    int kh = h / GROUP;
    int q0 = qt * AQ;
    int tid = threadIdx.x;
    int warp = tid >> 5, lane = tid & 31;
    int gid = lane >> 2, tig = lane & 3;
    int wr = warp * 16;

    // scale in log2 units: 128^-0.5 * log2(e)
    const float scale = 0.08838834764831845f * 1.4426950408889634f;

    uint32_t uK = (uint32_t)__cvta_generic_to_shared(Ksm);
    uint32_t uV = (uint32_t)__cvta_generic_to_shared(Vsm);

    for (int e = tid; e < AQ*16; e += 256) {
        int r = e >> 4, c = e & 15;
        *(uint4*)(Qs + r*QSTR + c*8) =
            *(const uint4*)(Qh + (size_t)(b*TSEQ + q0 + r)*DIM + h*HD + c*8);
    }

    const __half* Kbase = Kh  + (size_t)(b*TSEQ)*KVDIM + kh*HD;
    const __half* Vbase = Vth + ((size_t)(b*NHKV + kh))*HD*TSEQ;

    int kr  = tid >> 2;
    int kcb = (tid & 3) * 4;
    int vr  = tid >> 1;
    int vcb = (tid & 1) * 4;
    auto prefetch = [&](int s, int kt) {
        int s0 = kt * AK;
        uint32_t kd = uK + (uint32_t)s * K_TILE_B;
        const __half* ksrc = Kbase + (size_t)(s0 + kr) * KVDIM;
        #pragma unroll
        for (int j = 0; j < 4; j++)
            cpa16(kd + (uint32_t)(kr*KSTR + (kcb+j)*8)*2, ksrc + (kcb+j)*8);
        uint32_t vd = uV + (uint32_t)s * V_TILE_B;
        const __half* vsrc = Vbase + (size_t)vr * TSEQ + s0;
        #pragma unroll
        for (int j = 0; j < 4; j++)
            cpa16(vd + (uint32_t)(vr*VSTR + (vcb+j)*8)*2, vsrc + (vcb+j)*8);
        cpa_commit();
    };

    float m0 = -CUDART_INF_F, m1 = -CUDART_INF_F;
    float l0 = 0.0f, l1 = 0.0f;
    float o[16][4];
    #pragma unroll
    for (int on = 0; on < 16; on++)
        #pragma unroll
        for (int i = 0; i < 4; i++) o[on][i] = 0.0f;

    int nkt = 2*qt + 2;
    prefetch(0, 0);

    for (int kt = 0; kt < nkt; kt++) {
        int s0 = kt * AK;
        cpa_wait0();
        __syncthreads();
        if (kt + 1 < nkt) prefetch((kt + 1) & 1, kt + 1);

        const __half* Ks = Ksm + (kt & 1) * AK*KSTR;
        const __half* Vt = Vsm + (kt & 1) * HD*VSTR;

        float sacc[8][4];
        #pragma unroll
        for (int nt = 0; nt < 8; nt++)
            #pragma unroll
            for (int i = 0; i < 4; i++) sacc[nt][i] = 0.0f;

        #pragma unroll
        for (int ks = 0; ks < 8; ks++) {
            const __half* qb = Qs + (wr + gid)*QSTR + ks*16 + 2*tig;
            uint32_t a0 = *(const uint32_t*)(qb);
            uint32_t a1 = *(const uint32_t*)(qb + 8*QSTR);
            uint32_t a2 = *(const uint32_t*)(qb + 8);
            uint32_t a3 = *(const uint32_t*)(qb + 8*QSTR + 8);
            #pragma unroll
            for (int nt = 0; nt < 8; nt++) {
                const __half* kb = Ks + (nt*8 + gid)*KSTR + ks*16 + 2*tig;
                uint32_t b0 = *(const uint32_t*)(kb);
                uint32_t b1 = *(const uint32_t*)(kb + 8);
                mma_f16(sacc[nt][0], sacc[nt][1], sacc[nt][2], sacc[nt][3],
                        a0, a1, a2, a3, b0, b1);
            }
        }

        #pragma unroll
        for (int nt = 0; nt < 8; nt++)
            #pragma unroll
            for (int i = 0; i < 4; i++) sacc[nt][i] *= scale;

        if (s0 + AK - 1 > q0 + wr) {
            int r0g = q0 + wr + gid;
            #pragma unroll
            for (int nt = 0; nt < 8; nt++) {
                int sb = s0 + nt*8 + 2*tig;
                if (sb     > r0g)     sacc[nt][0] = -CUDART_INF_F;
                if (sb + 1 > r0g)     sacc[nt][1] = -CUDART_INF_F;
                if (sb     > r0g + 8) sacc[nt][2] = -CUDART_INF_F;
                if (sb + 1 > r0g + 8) sacc[nt][3] = -CUDART_INF_F;
            }
        }

        float mx0 = -CUDART_INF_F, mx1 = -CUDART_INF_F;
        #pragma unroll
        for (int nt = 0; nt < 8; nt++) {
            mx0 = fmaxf(mx0, fmaxf(sacc[nt][0], sacc[nt][1]));
            mx1 = fmaxf(mx1, fmaxf(sacc[nt][2], sacc[nt][3]));
        }
        #pragma unroll
        for (int off = 1; off <= 2; off <<= 1) {
            mx0 = fmaxf(mx0, __shfl_xor_sync(0xffffffffu, mx0, off));
            mx1 = fmaxf(mx1, __shfl_xor_sync(0xffffffffu, mx1, off));
        }
        float mn0 = fmaxf(m0, mx0), mn1 = fmaxf(m1, mx1);
        float corr0 = fexp2(m0 - mn0), corr1 = fexp2(m1 - mn1);
        m0 = mn0; m1 = mn1;

        float sum0 = 0.0f, sum1 = 0.0f;
        #pragma unroll
        for (int nt = 0; nt < 8; nt++) {
            sacc[nt][0] = fexp2(sacc[nt][0] - mn0);
            sacc[nt][1] = fexp2(sacc[nt][1] - mn0);
            sacc[nt][2] = fexp2(sacc[nt][2] - mn1);
            sacc[nt][3] = fexp2(sacc[nt][3] - mn1);
            sum0 += sacc[nt][0] + sacc[nt][1];
            sum1 += sacc[nt][2] + sacc[nt][3];
        }
        #pragma unroll
        for (int off = 1; off <= 2; off <<= 1) {
            sum0 += __shfl_xor_sync(0xffffffffu, sum0, off);
            sum1 += __shfl_xor_sync(0xffffffffu, sum1, off);
        }
        l0 = l0 * corr0 + sum0;
        l1 = l1 * corr1 + sum1;

        #pragma unroll
        for (int on = 0; on < 16; on++) {
            o[on][0] *= corr0; o[on][1] *= corr0;
            o[on][2] *= corr1; o[on][3] *= corr1;
        }

        #pragma unroll
        for (int ks2 = 0; ks2 < 4; ks2++) {
            __half2 pa0 = __floats2half2_rn(sacc[2*ks2][0],   sacc[2*ks2][1]);
            __half2 pa1 = __floats2half2_rn(sacc[2*ks2][2],   sacc[2*ks2][3]);
            __half2 pa2 = __floats2half2_rn(sacc[2*ks2+1][0], sacc[2*ks2+1][1]);
            __half2 pa3 = __floats2half2_rn(sacc[2*ks2+1][2], sacc[2*ks2+1][3]);
            uint32_t a0 = *reinterpret_cast<uint32_t*>(&pa0);
            uint32_t a1 = *reinterpret_cast<uint32_t*>(&pa1);
            uint32_t a2 = *reinterpret_cast<uint32_t*>(&pa2);
            uint32_t a3 = *reinterpret_cast<uint32_t*>(&pa3);
            #pragma unroll
            for (int on = 0; on < 16; on++) {
                const __half* vb = Vt + (on*8 + gid)*VSTR + ks2*16 + 2*tig;
                uint32_t b0 = *(const uint32_t*)(vb);
                uint32_t b1 = *(const uint32_t*)(vb + 8);
                mma_f16(o[on][0], o[on][1], o[on][2], o[on][3],
                        a0, a1, a2, a3, b0, b1);
            }
        }
    }

    float il0 = 1.0f / l0, il1 = 1.0f / l1;
    int r0 = q0 + wr + gid;
    #pragma unroll
    for (int on = 0; on < 16; on++) {
        int c0 = h*HD + on*8 + 2*tig;
        *(float2*)(Y + (size_t)(b*TSEQ + r0)     * DIM + c0) = make_float2(o[on][0]*il0, o[on][1]*il0);
        *(float2*)(Y + (size_t)(b*TSEQ + r0 + 8) * DIM + c0) = make_float2(o[on][2]*il1, o[on][3]*il1);
    }
}

// ---- v-direction projection removal, fused with bf16 hi/lo split ----------
__global__ void vproj_split_kernel(const float* __restrict__ V, int vstride,
                                   const float* __restrict__ Yin,
                                   __nv_bfloat16* __restrict__ YH,
                                   __nv_bfloat16* __restrict__ YL)
{
    int gthr = blockIdx.x * blockDim.x + threadIdx.x;
    int w    = gthr >> 5;
    int lane = gthr & 31;
    if (w >= BT * NHKV) return;
    int bt = w / NHKV, kh = w % NHKV;

    const float* vrow = V + (size_t)bt * vstride + kh * HD;
    float v0 = vrow[lane], v1 = vrow[lane+32], v2 = vrow[lane+64], v3 = vrow[lane+96];
    float ss = v0*v0 + v1*v1 + v2*v2 + v3*v3;
    #pragma unroll
    for (int o = 16; o; o >>= 1) ss += __shfl_xor_sync(0xffffffffu, ss, o);
    float norm = sqrtf(ss);
    float inv = 1.0f / fmaxf(norm, 1e-12f);
    float n0 = v0*inv, n1 = v1*inv, n2 = v2*inv, n3 = v3*inv;

    #pragma unroll
    for (int g = 0; g < GROUP; g++) {
        int hh = kh * GROUP + g;
        size_t base = (size_t)bt * DIM + hh * HD;
        const float* yrow = Yin + base;
        float y0 = yrow[lane], y1 = yrow[lane+32], y2 = yrow[lane+64], y3 = yrow[lane+96];
        float d = y0*n0 + y1*n1 + y2*n2 + y3*n3;
        #pragma unroll
        for (int o = 16; o; o >>= 1) d += __shfl_xor_sync(0xffffffffu, d, o);
        float r0 = y0 - d*n0, r1 = y1 - d*n1, r2 = y2 - d*n2, r3 = y3 - d*n3;

        __nv_bfloat16 h0 = __float2bfloat16_rn(r0), h1 = __float2bfloat16_rn(r1);
        __nv_bfloat16 h2 = __float2bfloat16_rn(r2), h3 = __float2bfloat16_rn(r3);
        YH[base + lane]    = h0;  YL[base + lane]    = __float2bfloat16_rn(r0 - __bfloat162float(h0));
        YH[base + lane+32] = h1;  YL[base + lane+32] = __float2bfloat16_rn(r1 - __bfloat162float(h1));
        YH[base + lane+64] = h2;  YL[base + lane+64] = __float2bfloat16_rn(r2 - __bfloat162float(h2));
        YH[base + lane+96] = h3;  YL[base + lane+96] = __float2bfloat16_rn(r3 - __bfloat162float(h3));
    }
}

// ---------------- launcher --------------------------------------------------
extern "C" void kernel_launch(void* const* d_in, const int* in_sizes, int n_in,
                              void* d_out, int out_size)
{
    const float* x     = (const float*)d_in[0];
    const float* Wq    = (const float*)d_in[1];
    const float* Wk    = (const float*)d_in[2];
    const float* Wv    = (const float*)d_in[3];
    const float* Wp    = (const float*)d_in[4];
    const float* qgain = (const float*)d_in[5];
    const float* qA    = (const float*)d_in[6];
    const float* qB    = (const float*)d_in[7];
    const float* kA    = (const float*)d_in[8];
    const float* kB    = (const float*)d_in[9];
    const float* vA    = (const float*)d_in[10];
    const float* vB    = (const float*)d_in[11];
    const float* pA    = (const float*)d_in[12];
    const float* pB    = (const float*)d_in[13];
    float* out = (float*)d_out;

    __nv_bfloat16 *wh, *wl, *wph, *wpl, *xh, *xl, *yh, *yl;
    float *qkv, *y;
    __half *qh, *kh2, *vth;
    cudaGetSymbolAddress((void**)&wh,  g_WqkvTh); cudaGetSymbolAddress((void**)&wl,  g_WqkvTl);
    cudaGetSymbolAddress((void**)&wph, g_WpTh);   cudaGetSymbolAddress((void**)&wpl, g_WpTl);
    cudaGetSymbolAddress((void**)&xh,  g_xh);     cudaGetSymbolAddress((void**)&xl,  g_xl);
    cudaGetSymbolAddress((void**)&yh,  g_yh);     cudaGetSymbolAddress((void**)&yl,  g_yl);
    cudaGetSymbolAddress((void**)&qkv, g_qkv);
    cudaGetSymbolAddress((void**)&y,   g_y);
    cudaGetSymbolAddress((void**)&qh,  g_qh);
    cudaGetSymbolAddress((void**)&kh2, g_kh);
    cudaGetSymbolAddress((void**)&vth, g_vth);

    const int GSMEM = (8*TBM*STR) * (int)sizeof(__nv_bfloat16);
    cudaFuncSetAttribute(bf16x3gemm_kernel<QKVD, DIM>, cudaFuncAttributeMaxDynamicSharedMemorySize, GSMEM);
    cudaFuncSetAttribute(bf16x3gemm_kernel<DIM, DIM>,  cudaFuncAttributeMaxDynamicSharedMemorySize, GSMEM);
    cudaFuncSetAttribute(attn_mma_kernel, cudaFuncAttributeMaxDynamicSharedMemorySize, ATT_SMEM_H);

    // launch 0: fused prologue (4x effw + x-split, concurrent regions)
    prologue_kernel<<<PRO_TOTAL, 256>>>(
        x,
        Wq, qA, qB,  Wk, kA, kB,  Wv, vA, vB,  Wp, pA, pB,
        wh, wl, wph, wpl, xh, xl);

    // launch 1: fused qkv projection (bf16x3 + ldmatrix), N = 3072
    dim3 gqkv(QKVD/TBN, BT/TBM);
    bf16x3gemm_kernel<QKVD, DIM><<<gqkv, 128, GSMEM>>>(xh, xl, wh, wl, qkv);

    // launch 2: fused normrope->fp16 + V transpose
    mid_kernel<<<MID_TOTAL, 256>>>(qkv, qgain, qh, kh2, vth);

    // launch 3: causal flash attention (fp16 MMA, fp32 exp2 softmax)
    {
        dim3 ga(TSEQ/AQ, NH, BSZ);
        attn_mma_kernel<<<ga, 256, ATT_SMEM_H>>>(qh, kh2, vth, y);
    }

    // launch 4: v-projection removal + bf16 split
    {
        int wv_n = BT * NHKV;
        vproj_split_kernel<<<(wv_n*32 + 255)/256, 256>>>(qkv + VOFF, QKVD, y, yh, yl);
    }

    // launch 5: output projection (bf16x3 + ldmatrix)
    dim3 gp(DIM/TBN, BT/TBM);
    bf16x3gemm_kernel<DIM, DIM><<<gp, 128, GSMEM>>>(yh, yl, wph, wpl, out);
}

// round 16
// speedup vs baseline: 1.1072x; 1.0141x over previous
#include <cuda_runtime.h>
#include <cuda_bf16.h>
#include <cuda_fp16.h>
#include <math.h>
#include <math_constants.h>
#include <stdint.h>

// Problem constants
#define BSZ   2
#define TSEQ  2048
#define DIM   2048
#define NH    16
#define NHKV  4
#define HD    128
#define KVDIM (NHKV*HD)     // 512
#define GROUP (NH/NHKV)     // 4
#define RANK  16
#define BT    (BSZ*TSEQ)    // 4096
#define QKVD  (DIM + 2*KVDIM)   // 3072
#define KOFF  DIM               // 2048
#define VOFF  (DIM + KVDIM)     // 2560

// ---------------- scratch (device globals; no allocation allowed) ----------
__device__ __nv_bfloat16 g_WqkvTh[QKVD*DIM], g_WqkvTl[QKVD*DIM];  // [3072][2048]
__device__ __nv_bfloat16 g_WpTh[DIM*DIM],    g_WpTl[DIM*DIM];
__device__ __nv_bfloat16 g_xh[BT*DIM],  g_xl[BT*DIM];
__device__ __nv_bfloat16 g_yh[BT*DIM],  g_yl[BT*DIM];
__device__ float  g_qkv[BT*QKVD];
__device__ float  g_y[BT*DIM];
__device__ __half g_qh[BT*DIM];
__device__ __half g_kh[BT*KVDIM];
__device__ __half g_vth[BSZ*NHKV*HD*TSEQ];         // fp16 V transposed [b][kh][hd][t]

__device__ __forceinline__ float fexp2(float x) {
    float y;
    asm("ex2.approx.f32 %0, %1;" : "=f"(y) : "f"(x));
    return y;
}

// ---- fused prologue: 4x effw (transpose+LoRA+split) and x-split, one grid --
#define PRO_EFFW   10240
#define PRO_TOTAL  18432

__global__ __launch_bounds__(256)
void prologue_kernel(const float* __restrict__ x,
                     const float* __restrict__ Wq, const float* __restrict__ qA, const float* __restrict__ qB,
                     const float* __restrict__ Wk, const float* __restrict__ kA, const float* __restrict__ kB,
                     const float* __restrict__ Wv, const float* __restrict__ vA, const float* __restrict__ vB,
                     const float* __restrict__ Wp, const float* __restrict__ pA, const float* __restrict__ pB,
                     __nv_bfloat16* __restrict__ wh,  __nv_bfloat16* __restrict__ wl,
                     __nv_bfloat16* __restrict__ wph, __nv_bfloat16* __restrict__ wpl,
                     __nv_bfloat16* __restrict__ xh,  __nv_bfloat16* __restrict__ xl)
{
    __shared__ float tile[32][33];
    int bid = blockIdx.x;
    int tid = threadIdx.x;

    if (bid < PRO_EFFW) {
        const float *W, *A, *Bm;
        __nv_bfloat16 *H, *L;
        int N, local;
        if (bid < 4096)      { W=Wq; A=qA; Bm=qB; H=wh;                     L=wl;                     N=DIM;   local=bid; }
        else if (bid < 5120) { W=Wk; A=kA; Bm=kB; H=wh+(size_t)KOFF*DIM;    L=wl+(size_t)KOFF*DIM;    N=KVDIM; local=bid-4096; }
        else if (bid < 6144) { W=Wv; A=vA; Bm=vB; H=wh+(size_t)VOFF*DIM;    L=wl+(size_t)VOFF*DIM;    N=KVDIM; local=bid-5120; }
        else                 { W=Wp; A=pA; Bm=pB; H=wph;                    L=wpl;                    N=DIM;   local=bid-6144; }
        int nbx = N >> 5;
        int tn = (local % nbx) * 32;
        int tk = (local / nbx) * 32;
        int tx = tid & 31, ty = tid >> 5;   // 32 x 8

        #pragma unroll
        for (int i = 0; i < 4; i++) {
            int k = tk + ty + i*8;
            int n = tn + tx;
            float s = W[(size_t)k * N + n];
            #pragma unroll
            for (int r = 0; r < RANK; r++)
                s += A[k*RANK + r] * Bm[r*N + n];
            tile[ty + i*8][tx] = s;
        }
        __syncthreads();
        #pragma unroll
        for (int i = 0; i < 4; i++) {
            int n = tn + ty + i*8;
            int k = tk + tx;
            float s = tile[tx][ty + i*8];
            __nv_bfloat16 h = __float2bfloat16_rn(s);
            H[(size_t)n * DIM + k] = h;
            L[(size_t)n * DIM + k] = __float2bfloat16_rn(s - __bfloat162float(h));
        }
    } else {
        int idx = (bid - PRO_EFFW) * 256 + tid;
        float4 v = ((const float4*)x)[idx];
        __nv_bfloat16 h0 = __float2bfloat16_rn(v.x), h1 = __float2bfloat16_rn(v.y);
        __nv_bfloat16 h2 = __float2bfloat16_rn(v.z), h3 = __float2bfloat16_rn(v.w);
        __nv_bfloat162 hh0 = {h0, h1}, hh1 = {h2, h3};
        __nv_bfloat162 ll0 = {__float2bfloat16_rn(v.x - __bfloat162float(h0)),
                              __float2bfloat16_rn(v.y - __bfloat162float(h1))};
        __nv_bfloat162 ll1 = {__float2bfloat16_rn(v.z - __bfloat162float(h2)),
                              __float2bfloat16_rn(v.w - __bfloat162float(h3))};
        ((__nv_bfloat162*)xh)[idx*2]   = hh0;
        ((__nv_bfloat162*)xh)[idx*2+1] = hh1;
        ((__nv_bfloat162*)xl)[idx*2]   = ll0;
        ((__nv_bfloat162*)xl)[idx*2+1] = ll1;
    }
}

// ---------------- bf16x3 tensor-core GEMM (ldmatrix, term-major) -----------
#define TBM 128
#define TBN 128
#define TBK 32
#define STR 40

__device__ __forceinline__ void cpa16(uint32_t dst, const void* src) {
    asm volatile("cp.async.cg.shared.global [%0], [%1], 16;\n" :: "r"(dst), "l"(src));
}
__device__ __forceinline__ void cpa_commit() {
    asm volatile("cp.async.commit_group;\n");
}
__device__ __forceinline__ void cpa_wait0() {
    asm volatile("cp.async.wait_group 0;\n");
}
__device__ __forceinline__ void ldsm_x4(uint32_t& r0, uint32_t& r1, uint32_t& r2, uint32_t& r3,
                                        uint32_t addr) {
    asm volatile("ldmatrix.sync.aligned.m8n8.x4.shared.b16 {%0,%1,%2,%3}, [%4];"
                 : "=r"(r0), "=r"(r1), "=r"(r2), "=r"(r3) : "r"(addr));
}
__device__ __forceinline__ void mma_bf16(float& d0, float& d1, float& d2, float& d3,
                                         uint32_t a0, uint32_t a1, uint32_t a2, uint32_t a3,
                                         uint32_t b0, uint32_t b1) {
    asm volatile(
        "mma.sync.aligned.m16n8k16.row.col.f32.bf16.bf16.f32 "
        "{%0,%1,%2,%3}, {%4,%5,%6,%7}, {%8,%9}, {%0,%1,%2,%3};\n"
        : "+f"(d0), "+f"(d1), "+f"(d2), "+f"(d3)
        : "r"(a0), "r"(a1), "r"(a2), "r"(a3), "r"(b0), "r"(b1));
}
__device__ __forceinline__ void mma_f16(float& d0, float& d1, float& d2, float& d3,
                                        uint32_t a0, uint32_t a1, uint32_t a2, uint32_t a3,
                                        uint32_t b0, uint32_t b1) {
    asm volatile(
        "mma.sync.aligned.m16n8k16.row.col.f32.f16.f16.f32 "
        "{%0,%1,%2,%3}, {%4,%5,%6,%7}, {%8,%9}, {%0,%1,%2,%3};\n"
        : "+f"(d0), "+f"(d1), "+f"(d2), "+f"(d3)
        : "r"(a0), "r"(a1), "r"(a2), "r"(a3), "r"(b0), "r"(b1));
}

template<int N, int K>
__global__ __launch_bounds__(128)
void bf16x3gemm_kernel(const __nv_bfloat16* __restrict__ Ah,
                       const __nv_bfloat16* __restrict__ Al,
                       const __nv_bfloat16* __restrict__ Bh,   // [N][K]
                       const __nv_bfloat16* __restrict__ Bl,
                       float* __restrict__ C)
{
    extern __shared__ __nv_bfloat16 smem[];
    __nv_bfloat16* sAh = smem;
    __nv_bfloat16* sAl = sAh + 2*TBM*STR;
    __nv_bfloat16* sBh = sAl + 2*TBM*STR;
    __nv_bfloat16* sBl = sBh + 2*TBN*STR;

    int tid  = threadIdx.x;
    int warp = tid >> 5, lane = tid & 31;
    int warpM = warp >> 1, warpN = warp & 1;
    int gid = lane >> 2, tig = lane & 3;

    const __nv_bfloat16* Ahb = Ah + (size_t)blockIdx.y * TBM * K;
    const __nv_bfloat16* Alb = Al + (size_t)blockIdx.y * TBM * K;
    const __nv_bfloat16* Bhb = Bh + (size_t)blockIdx.x * TBN * K;
    const __nv_bfloat16* Blb = Bl + (size_t)blockIdx.x * TBN * K;
    float* Cb = C + (size_t)blockIdx.y * TBM * N + (size_t)blockIdx.x * TBN;

    int srow = tid >> 2;
    int scol = (tid & 3) * 8;

    uint32_t uAh = (uint32_t)__cvta_generic_to_shared(sAh);
    uint32_t uAl = (uint32_t)__cvta_generic_to_shared(sAl);
    uint32_t uBh = (uint32_t)__cvta_generic_to_shared(sBh);
    uint32_t uBl = (uint32_t)__cvta_generic_to_shared(sBl);

    uint32_t laneA = (uint32_t)(((lane & 15) * STR + (lane >> 4) * 8) * 2);
    uint32_t laneB = (uint32_t)((((lane & 7) + ((lane >> 4) << 3)) * STR) * 2 + ((lane >> 3) & 1) * 16);

    float acc[4][8][4];
    #pragma unroll
    for (int m = 0; m < 4; m++)
        #pragma unroll
        for (int n = 0; n < 8; n++)
            #pragma unroll
            for (int i = 0; i < 4; i++) acc[m][n][i] = 0.0f;

    constexpr int ntiles = K / TBK;

    auto issue = [&](int buf, int kt) {
        uint32_t bofs = (uint32_t)(buf * TBM * STR * 2);
        #pragma unroll
        for (int i = 0; i < 4; i++) {
            int r = srow + i * 32;
            uint32_t dofs = (uint32_t)((r * STR + scol) * 2);
            size_t gofs = (size_t)r * K + (size_t)kt * TBK + scol;
            cpa16(uAh + bofs + dofs, Ahb + gofs);
            cpa16(uAl + bofs + dofs, Alb + gofs);
            cpa16(uBh + bofs + dofs, Bhb + gofs);
            cpa16(uBl + bofs + dofs, Blb + gofs);
        }
        cpa_commit();
    };

    issue(0, 0);
    int buf = 0;

    for (int kt = 0; kt < ntiles; kt++) {
        cpa_wait0();
        __syncthreads();
        if (kt + 1 < ntiles) issue(buf ^ 1, kt + 1);

        uint32_t bufofs = (uint32_t)(buf * TBM * STR * 2);
        uint32_t aH = uAh + bufofs, aL = uAl + bufofs;
        uint32_t bH = uBh + bufofs, bL = uBl + bufofs;

        #pragma unroll
        for (int ks = 0; ks < TBK; ks += 16) {
            uint32_t afh[4][4], afl[4][4];
            #pragma unroll
            for (int mt = 0; mt < 4; mt++) {
                uint32_t ofs = (uint32_t)(((warpM*64 + mt*16) * STR + ks) * 2) + laneA;
                ldsm_x4(afh[mt][0], afh[mt][1], afh[mt][2], afh[mt][3], aH + ofs);
                ldsm_x4(afl[mt][0], afl[mt][1], afl[mt][2], afl[mt][3], aL + ofs);
            }
            uint32_t bfh[8][2], bfl[8][2];
            #pragma unroll
            for (int np = 0; np < 4; np++) {
                uint32_t ofs = (uint32_t)(((warpN*64 + np*16) * STR + ks) * 2) + laneB;
                ldsm_x4(bfh[2*np][0], bfh[2*np][1], bfh[2*np+1][0], bfh[2*np+1][1], bH + ofs);
                ldsm_x4(bfl[2*np][0], bfl[2*np][1], bfl[2*np+1][0], bfl[2*np+1][1], bL + ofs);
            }
            #pragma unroll
            for (int mt = 0; mt < 4; mt++)
                #pragma unroll
                for (int nt = 0; nt < 8; nt++)
                    mma_bf16(acc[mt][nt][0], acc[mt][nt][1], acc[mt][nt][2], acc[mt][nt][3],
                             afh[mt][0], afh[mt][1], afh[mt][2], afh[mt][3],
                             bfh[nt][0], bfh[nt][1]);
            #pragma unroll
            for (int mt = 0; mt < 4; mt++)
                #pragma unroll
                for (int nt = 0; nt < 8; nt++)
                    mma_bf16(acc[mt][nt][0], acc[mt][nt][1], acc[mt][nt][2], acc[mt][nt][3],
                             afh[mt][0], afh[mt][1], afh[mt][2], afh[mt][3],
                             bfl[nt][0], bfl[nt][1]);
            #pragma unroll
            for (int mt = 0; mt < 4; mt++)
                #pragma unroll
                for (int nt = 0; nt < 8; nt++)
                    mma_bf16(acc[mt][nt][0], acc[mt][nt][1], acc[mt][nt][2], acc[mt][nt][3],
                             afl[mt][0], afl[mt][1], afl[mt][2], afl[mt][3],
                             bfh[nt][0], bfh[nt][1]);
        }
        __syncthreads();
        buf ^= 1;
    }

    #pragma unroll
    for (int mt = 0; mt < 4; mt++) {
        int r0 = warpM*64 + mt*16 + gid;
        #pragma unroll
        for (int nt = 0; nt < 8; nt++) {
            int c0 = warpN*64 + nt*8 + tig*2;
            *(float2*)(Cb + (size_t) r0      * N + c0) = make_float2(acc[mt][nt][0], acc[mt][nt][1]);
            *(float2*)(Cb + (size_t)(r0 + 8) * N + c0) = make_float2(acc[mt][nt][2], acc[mt][nt][3]);
        }
    }
}

// ---- fused mid: normrope (fp16 q/k) + V transpose, one grid ---------------
#define MID_NR    10240
#define MID_TOTAL 12288

__global__ __launch_bounds__(256)
void mid_kernel(const float* __restrict__ QKV,
                const float* __restrict__ gain,
                __half* __restrict__ Qh,
                __half* __restrict__ Kh,
                __half* __restrict__ Vt)
{
    __shared__ float tile[32][33];
    int bid = blockIdx.x;
    int tid = threadIdx.x;

    if (bid < MID_NR) {
        int gthr = bid * 256 + tid;
        int w    = gthr >> 5;
        int lane = gthr & 31;

        const float* src;
        __half* dst;
        float g = 1.0f;
        int bt;
        if (w < BT * NH) {
            bt = w / NH;
            int hh = w % NH;
            src = QKV + (size_t)bt * QKVD + hh * HD;
            dst = Qh  + (size_t)bt * DIM  + hh * HD;
            g = gain[hh];
        } else {
            int w2 = w - BT * NH;
            bt = w2 / NHKV;
            int hh = w2 % NHKV;
            src = QKV + (size_t)bt * QKVD + KOFF + hh * HD;
            dst = Kh  + (size_t)bt * KVDIM + hh * HD;
        }
        int t = bt % TSEQ;

        float v0 = src[lane], v1 = src[lane+32], v2 = src[lane+64], v3 = src[lane+96];
        float ss = v0*v0 + v1*v1 + v2*v2 + v3*v3;
        #pragma unroll
        for (int o = 16; o; o >>= 1) ss += __shfl_xor_sync(0xffffffffu, ss, o);

        float f = rsqrtf(ss * (1.0f/128.0f) + 1.1920929e-7f) * g;

        float invfreq = powf(10000.0f, -(float)lane * (1.0f/32.0f));
        float ang = (float)t * invfreq;
        float s, c;
        sincosf(ang, &s, &c);

        dst[lane]    = __float2half(( v0*c + v1*s) * f);
        dst[lane+32] = __float2half((-v0*s + v1*c) * f);
        dst[lane+64] = __float2half(v2 * f);
        dst[lane+96] = __float2half(v3 * f);
    } else {
        int local = bid - MID_NR;
        int t0 = (local & 63) * 32;
        int c0 = ((local >> 6) & 3) * 32;
        int bk = local >> 8;
        int b  = bk / NHKV, kh = bk % NHKV;
        int tx = tid & 31, ty = tid >> 5;

        #pragma unroll
        for (int i = 0; i < 4; i++) {
            int t = t0 + ty + i*8;
            tile[ty + i*8][tx] = QKV[(size_t)(b*TSEQ + t) * QKVD + VOFF + kh*HD + c0 + tx];
        }
        __syncthreads();
        #pragma unroll
        for (int i = 0; i < 4; i++) {
            int c = c0 + ty + i*8;
            Vt[((size_t)bk * HD + c) * TSEQ + t0 + tx] = __float2half(tile[tx][ty + i*8]);
        }
    }
}

// -------- fp16 tensor-core causal flash attention (paired q-tiles) ---------
// Each CTA handles q-tiles {bx, NQT-1-bx}: constant 34 k-tile units/CTA,
// grid 256 <= resident slots -> one balanced wave.
#define AQ   128
#define AK   64
#define NQT  (TSEQ/AQ)   // 16
#define QSTR 136
#define KSTR 136
#define VSTR 72
#define K_TILE_B  (AK*KSTR*2)   // 17408
#define V_TILE_B  (HD*VSTR*2)   // 18432
#define ATT_SMEM_H (AQ*QSTR*2 + 2*K_TILE_B + 2*V_TILE_B)   // 106496 bytes

__global__ __launch_bounds__(256)
void attn_mma_kernel(const __half* __restrict__ Qh,
                     const __half* __restrict__ Kh,
                     const __half* __restrict__ Vth,
                     float* __restrict__ Y)
{
    extern __shared__ __half smh[];
    __half* Qs  = smh;                    // [AQ][QSTR]
    __half* Ksm = Qs + AQ*QSTR;           // 2 x [AK][KSTR]
    __half* Vsm = Ksm + 2*AK*KSTR;        // 2 x [HD][VSTR]

    int bx = blockIdx.x, h = blockIdx.y, b = blockIdx.z;
    int kh = h / GROUP;
    int tid = threadIdx.x;
    int warp = tid >> 5, lane = tid & 31;
    int gid = lane >> 2, tig = lane & 3;
    int wr = warp * 16;

    // scale in log2 units: 128^-0.5 * log2(e)
    const float scale = 0.08838834764831845f * 1.4426950408889634f;

    uint32_t uK = (uint32_t)__cvta_generic_to_shared(Ksm);
    uint32_t uV = (uint32_t)__cvta_generic_to_shared(Vsm);

    const __half* Kbase = Kh  + (size_t)(b*TSEQ)*KVDIM + kh*HD;
    const __half* Vbase = Vth + ((size_t)(b*NHKV + kh))*HD*TSEQ;

    int kr  = tid >> 2;
    int kcb = (tid & 3) * 4;
    int vr  = tid >> 1;
    int vcb = (tid & 1) * 4;
    auto prefetch = [&](int s, int kt) {
        int s0 = kt * AK;
        uint32_t kd = uK + (uint32_t)s * K_TILE_B;
        const __half* ksrc = Kbase + (size_t)(s0 + kr) * KVDIM;
        #pragma unroll
        for (int j = 0; j < 4; j++)
            cpa16(kd + (uint32_t)(kr*KSTR + (kcb+j)*8)*2, ksrc + (kcb+j)*8);
        uint32_t vd = uV + (uint32_t)s * V_TILE_B;
        const __half* vsrc = Vbase + (size_t)vr * TSEQ + s0;
        #pragma unroll
        for (int j = 0; j < 4; j++)
            cpa16(vd + (uint32_t)(vr*VSTR + (vcb+j)*8)*2, vsrc + (vcb+j)*8);
        cpa_commit();
    };

    #pragma unroll 1
    for (int sub = 0; sub < 2; sub++) {
        int qt = sub ? (NQT - 1 - bx) : bx;
        int q0 = qt * AQ;

        __syncthreads();   // protect Qs reuse across sub-passes

        // load Q tile (fp16, vectorized)
        for (int e = tid; e < AQ*16; e += 256) {
            int r = e >> 4, c = e & 15;
            *(uint4*)(Qs + r*QSTR + c*8) =
                *(const uint4*)(Qh + (size_t)(b*TSEQ + q0 + r)*DIM + h*HD + c*8);
        }

        float m0 = -CUDART_INF_F, m1 = -CUDART_INF_F;
        float l0 = 0.0f, l1 = 0.0f;
        float o[16][4];
        #pragma unroll
        for (int on = 0; on < 16; on++)
            #pragma unroll
            for (int i = 0; i < 4; i++) o[on][i] = 0.0f;

        int nkt = 2*qt + 2;
        prefetch(0, 0);

        for (int kt = 0; kt < nkt; kt++) {
            int s0 = kt * AK;
            cpa_wait0();
            __syncthreads();
            if (kt + 1 < nkt) prefetch((kt + 1) & 1, kt + 1);

            const __half* Ks = Ksm + (kt & 1) * AK*KSTR;
            const __half* Vt = Vsm + (kt & 1) * HD*VSTR;

            float sacc[8][4];
            #pragma unroll
            for (int nt = 0; nt < 8; nt++)
                #pragma unroll
                for (int i = 0; i < 4; i++) sacc[nt][i] = 0.0f;

            #pragma unroll
            for (int ks = 0; ks < 8; ks++) {
                const __half* qb = Qs + (wr + gid)*QSTR + ks*16 + 2*tig;
                uint32_t a0 = *(const uint32_t*)(qb);
                uint32_t a1 = *(const uint32_t*)(qb + 8*QSTR);
                uint32_t a2 = *(const uint32_t*)(qb + 8);
                uint32_t a3 = *(const uint32_t*)(qb + 8*QSTR + 8);
                #pragma unroll
                for (int nt = 0; nt < 8; nt++) {
                    const __half* kb = Ks + (nt*8 + gid)*KSTR + ks*16 + 2*tig;
                    uint32_t b0 = *(const uint32_t*)(kb);
                    uint32_t b1 = *(const uint32_t*)(kb + 8);
                    mma_f16(sacc[nt][0], sacc[nt][1], sacc[nt][2], sacc[nt][3],
                            a0, a1, a2, a3, b0, b1);
                }
            }

            #pragma unroll
            for (int nt = 0; nt < 8; nt++)
                #pragma unroll
                for (int i = 0; i < 4; i++) sacc[nt][i] *= scale;

            if (s0 + AK - 1 > q0 + wr) {
                int r0g = q0 + wr + gid;
                #pragma unroll
                for (int nt = 0; nt < 8; nt++) {
                    int sb = s0 + nt*8 + 2*tig;
                    if (sb     > r0g)     sacc[nt][0] = -CUDART_INF_F;
                    if (sb + 1 > r0g)     sacc[nt][1] = -CUDART_INF_F;
                    if (sb     > r0g + 8) sacc[nt][2] = -CUDART_INF_F;
                    if (sb + 1 > r0g + 8) sacc[nt][3] = -CUDART_INF_F;
                }
            }

            float mx0 = -CUDART_INF_F, mx1 = -CUDART_INF_F;
            #pragma unroll
            for (int nt = 0; nt < 8; nt++) {
                mx0 = fmaxf(mx0, fmaxf(sacc[nt][0], sacc[nt][1]));
                mx1 = fmaxf(mx1, fmaxf(sacc[nt][2], sacc[nt][3]));
            }
            #pragma unroll
            for (int off = 1; off <= 2; off <<= 1) {
                mx0 = fmaxf(mx0, __shfl_xor_sync(0xffffffffu, mx0, off));
                mx1 = fmaxf(mx1, __shfl_xor_sync(0xffffffffu, mx1, off));
            }
            float mn0 = fmaxf(m0, mx0), mn1 = fmaxf(m1, mx1);
            float corr0 = fexp2(m0 - mn0), corr1 = fexp2(m1 - mn1);
            m0 = mn0; m1 = mn1;

            float sum0 = 0.0f, sum1 = 0.0f;
            #pragma unroll
            for (int nt = 0; nt < 8; nt++) {
                sacc[nt][0] = fexp2(sacc[nt][0] - mn0);
                sacc[nt][1] = fexp2(sacc[nt][1] - mn0);
                sacc[nt][2] = fexp2(sacc[nt][2] - mn1);
                sacc[nt][3] = fexp2(sacc[nt][3] - mn1);
                sum0 += sacc[nt][0] + sacc[nt][1];
                sum1 += sacc[nt][2] + sacc[nt][3];
            }
            #pragma unroll
            for (int off = 1; off <= 2; off <<= 1) {
                sum0 += __shfl_xor_sync(0xffffffffu, sum0, off);
                sum1 += __shfl_xor_sync(0xffffffffu, sum1, off);
            }
            l0 = l0 * corr0 + sum0;
            l1 = l1 * corr1 + sum1;

            #pragma unroll
            for (int on = 0; on < 16; on++) {
                o[on][0] *= corr0; o[on][1] *= corr0;
                o[on][2] *= corr1; o[on][3] *= corr1;
            }

            #pragma unroll
            for (int ks2 = 0; ks2 < 4; ks2++) {
                __half2 pa0 = __floats2half2_rn(sacc[2*ks2][0],   sacc[2*ks2][1]);
                __half2 pa1 = __floats2half2_rn(sacc[2*ks2][2],   sacc[2*ks2][3]);
                __half2 pa2 = __floats2half2_rn(sacc[2*ks2+1][0], sacc[2*ks2+1][1]);
                __half2 pa3 = __floats2half2_rn(sacc[2*ks2+1][2], sacc[2*ks2+1][3]);
                uint32_t a0 = *reinterpret_cast<uint32_t*>(&pa0);
                uint32_t a1 = *reinterpret_cast<uint32_t*>(&pa1);
                uint32_t a2 = *reinterpret_cast<uint32_t*>(&pa2);
                uint32_t a3 = *reinterpret_cast<uint32_t*>(&pa3);
                #pragma unroll
                for (int on = 0; on < 16; on++) {
                    const __half* vb = Vt + (on*8 + gid)*VSTR + ks2*16 + 2*tig;
                    uint32_t b0 = *(const uint32_t*)(vb);
                    uint32_t b1 = *(const uint32_t*)(vb + 8);
                    mma_f16(o[on][0], o[on][1], o[on][2], o[on][3],
                            a0, a1, a2, a3, b0, b1);
                }
            }
        }

        float il0 = 1.0f / l0, il1 = 1.0f / l1;
        int r0 = q0 + wr + gid;
        #pragma unroll
        for (int on = 0; on < 16; on++) {
            int c0 = h*HD + on*8 + 2*tig;
            *(float2*)(Y + (size_t)(b*TSEQ + r0)     * DIM + c0) = make_float2(o[on][0]*il0, o[on][1]*il0);
            *(float2*)(Y + (size_t)(b*TSEQ + r0 + 8) * DIM + c0) = make_float2(o[on][2]*il1, o[on][3]*il1);
        }
    }
}

// ---- v-direction projection removal, fused with bf16 hi/lo split ----------
__global__ void vproj_split_kernel(const float* __restrict__ V, int vstride,
                                   const float* __restrict__ Yin,
                                   __nv_bfloat16* __restrict__ YH,
                                   __nv_bfloat16* __restrict__ YL)
{
    int gthr = blockIdx.x * blockDim.x + threadIdx.x;
    int w    = gthr >> 5;
    int lane = gthr & 31;
    if (w >= BT * NHKV) return;
    int bt = w / NHKV, kh = w % NHKV;

    const float* vrow = V + (size_t)bt * vstride + kh * HD;
    float v0 = vrow[lane], v1 = vrow[lane+32], v2 = vrow[lane+64], v3 = vrow[lane+96];
    float ss = v0*v0 + v1*v1 + v2*v2 + v3*v3;
    #pragma unroll
    for (int o = 16; o; o >>= 1) ss += __shfl_xor_sync(0xffffffffu, ss, o);
    float norm = sqrtf(ss);
    float inv = 1.0f / fmaxf(norm, 1e-12f);
    float n0 = v0*inv, n1 = v1*inv, n2 = v2*inv, n3 = v3*inv;

    #pragma unroll
    for (int g = 0; g < GROUP; g++) {
        int hh = kh * GROUP + g;
        size_t base = (size_t)bt * DIM + hh * HD;
        const float* yrow = Yin + base;
        float y0 = yrow[lane], y1 = yrow[lane+32], y2 = yrow[lane+64], y3 = yrow[lane+96];
        float d = y0*n0 + y1*n1 + y2*n2 + y3*n3;
        #pragma unroll
        for (int o = 16; o; o >>= 1) d += __shfl_xor_sync(0xffffffffu, d, o);
        float r0 = y0 - d*n0, r1 = y1 - d*n1, r2 = y2 - d*n2, r3 = y3 - d*n3;

        __nv_bfloat16 h0 = __float2bfloat16_rn(r0), h1 = __float2bfloat16_rn(r1);
        __nv_bfloat16 h2 = __float2bfloat16_rn(r2), h3 = __float2bfloat16_rn(r3);
        YH[base + lane]    = h0;  YL[base + lane]    = __float2bfloat16_rn(r0 - __bfloat162float(h0));
        YH[base + lane+32] = h1;  YL[base + lane+32] = __float2bfloat16_rn(r1 - __bfloat162float(h1));
        YH[base + lane+64] = h2;  YL[base + lane+64] = __float2bfloat16_rn(r2 - __bfloat162float(h2));
        YH[base + lane+96] = h3;  YL[base + lane+96] = __float2bfloat16_rn(r3 - __bfloat162float(h3));
    }
}

// ---------------- launcher --------------------------------------------------
extern "C" void kernel_launch(void* const* d_in, const int* in_sizes, int n_in,
                              void* d_out, int out_size)
{
    const float* x     = (const float*)d_in[0];
    const float* Wq    = (const float*)d_in[1];
    const float* Wk    = (const float*)d_in[2];
    const float* Wv    = (const float*)d_in[3];
    const float* Wp    = (const float*)d_in[4];
    const float* qgain = (const float*)d_in[5];
    const float* qA    = (const float*)d_in[6];
    const float* qB    = (const float*)d_in[7];
    const float* kA    = (const float*)d_in[8];
    const float* kB    = (const float*)d_in[9];
    const float* vA    = (const float*)d_in[10];
    const float* vB    = (const float*)d_in[11];
    const float* pA    = (const float*)d_in[12];
    const float* pB    = (const float*)d_in[13];
    float* out = (float*)d_out;

    __nv_bfloat16 *wh, *wl, *wph, *wpl, *xh, *xl, *yh, *yl;
    float *qkv, *y;
    __half *qh, *kh2, *vth;
    cudaGetSymbolAddress((void**)&wh,  g_WqkvTh); cudaGetSymbolAddress((void**)&wl,  g_WqkvTl);
    cudaGetSymbolAddress((void**)&wph, g_WpTh);   cudaGetSymbolAddress((void**)&wpl, g_WpTl);
    cudaGetSymbolAddress((void**)&xh,  g_xh);     cudaGetSymbolAddress((void**)&xl,  g_xl);
    cudaGetSymbolAddress((void**)&yh,  g_yh);     cudaGetSymbolAddress((void**)&yl,  g_yl);
    cudaGetSymbolAddress((void**)&qkv, g_qkv);
    cudaGetSymbolAddress((void**)&y,   g_y);
    cudaGetSymbolAddress((void**)&qh,  g_qh);
    cudaGetSymbolAddress((void**)&kh2, g_kh);
    cudaGetSymbolAddress((void**)&vth, g_vth);

    const int GSMEM = (8*TBM*STR) * (int)sizeof(__nv_bfloat16);
    cudaFuncSetAttribute(bf16x3gemm_kernel<QKVD, DIM>, cudaFuncAttributeMaxDynamicSharedMemorySize, GSMEM);
    cudaFuncSetAttribute(bf16x3gemm_kernel<DIM, DIM>,  cudaFuncAttributeMaxDynamicSharedMemorySize, GSMEM);
    cudaFuncSetAttribute(attn_mma_kernel, cudaFuncAttributeMaxDynamicSharedMemorySize, ATT_SMEM_H);

    // launch 0: fused prologue (4x effw + x-split)
    prologue_kernel<<<PRO_TOTAL, 256>>>(
        x,
        Wq, qA, qB,  Wk, kA, kB,  Wv, vA, vB,  Wp, pA, pB,
        wh, wl, wph, wpl, xh, xl);

    // launch 1: fused qkv projection (bf16x3 + ldmatrix), N = 3072
    dim3 gqkv(QKVD/TBN, BT/TBM);
    bf16x3gemm_kernel<QKVD, DIM><<<gqkv, 128, GSMEM>>>(xh, xl, wh, wl, qkv);

    // launch 2: fused normrope->fp16 + V transpose
    mid_kernel<<<MID_TOTAL, 256>>>(qkv, qgain, qh, kh2, vth);

    // launch 3: causal flash attention (paired q-tiles, balanced single wave)
    {
        dim3 ga(NQT/2, NH, BSZ);
        attn_mma_kernel<<<ga, 256, ATT_SMEM_H>>>(qh, kh2, vth, y);
    }

    // launch 4: v-projection removal + bf16 split
    {
        int wv_n = BT * NHKV;
        vproj_split_kernel<<<(wv_n*32 + 255)/256, 256>>>(qkv + VOFF, QKVD, y, yh, yl);
    }

    // launch 5: output projection (bf16x3 + ldmatrix)
    dim3 gp(DIM/TBN, BT/TBM);
    bf16x3gemm_kernel<DIM, DIM><<<gp, 128, GSMEM>>>(yh, yl, wph, wpl, out);
}

// round 17
// speedup vs baseline: 1.2293x; 1.1103x over previous
#include <cuda_runtime.h>
#include <cuda_bf16.h>
#include <cuda_fp16.h>
#include <math.h>
#include <math_constants.h>
#include <stdint.h>

// Problem constants
#define BSZ   2
#define TSEQ  2048
#define DIM   2048
#define NH    16
#define NHKV  4
#define HD    128
#define KVDIM (NHKV*HD)     // 512
#define GROUP (NH/NHKV)     // 4
#define RANK  16
#define BT    (BSZ*TSEQ)    // 4096
#define QKVD  (DIM + 2*KVDIM)   // 3072
#define KOFF  DIM               // 2048
#define VOFF  (DIM + KVDIM)     // 2560

// ---------------- scratch (device globals; no allocation allowed) ----------
__device__ __nv_bfloat16 g_WqkvTh[QKVD*DIM], g_WqkvTl[QKVD*DIM];  // [3072][2048]
__device__ __half        g_Wpf[DIM*DIM];                           // proj weight fp16 [N][K]
__device__ __nv_bfloat16 g_xh[BT*DIM],  g_xl[BT*DIM];
__device__ __half        g_yh[BT*DIM],  g_yl[BT*DIM];              // y split fp16 hi/lo
__device__ float  g_qkv[BT*QKVD];
__device__ float  g_y[BT*DIM];
__device__ __half g_qh[BT*DIM];
__device__ __half g_kh[BT*KVDIM];
__device__ __half g_vth[BSZ*NHKV*HD*TSEQ];         // fp16 V transposed [b][kh][hd][t]

__device__ __forceinline__ float fexp2(float x) {
    float y;
    asm("ex2.approx.f32 %0, %1;" : "=f"(y) : "f"(x));
    return y;
}

// ---- fused prologue: effw q/k/v (bf16 hi/lo), Wp (fp16), x-split ----------
#define PRO_EFFW   10240
#define PRO_TOTAL  18432

__global__ __launch_bounds__(256)
void prologue_kernel(const float* __restrict__ x,
                     const float* __restrict__ Wq, const float* __restrict__ qA, const float* __restrict__ qB,
                     const float* __restrict__ Wk, const float* __restrict__ kA, const float* __restrict__ kB,
                     const float* __restrict__ Wv, const float* __restrict__ vA, const float* __restrict__ vB,
                     const float* __restrict__ Wp, const float* __restrict__ pA, const float* __restrict__ pB,
                     __nv_bfloat16* __restrict__ wh,  __nv_bfloat16* __restrict__ wl,
                     __half* __restrict__ wpf,
                     __nv_bfloat16* __restrict__ xh,  __nv_bfloat16* __restrict__ xl)
{
    __shared__ float tile[32][33];
    int bid = blockIdx.x;
    int tid = threadIdx.x;

    if (bid < 6144) {
        const float *W, *A, *Bm;
        __nv_bfloat16 *H, *L;
        int N, local;
        if (bid < 4096)      { W=Wq; A=qA; Bm=qB; H=wh;                  L=wl;                  N=DIM;   local=bid; }
        else if (bid < 5120) { W=Wk; A=kA; Bm=kB; H=wh+(size_t)KOFF*DIM; L=wl+(size_t)KOFF*DIM; N=KVDIM; local=bid-4096; }
        else                 { W=Wv; A=vA; Bm=vB; H=wh+(size_t)VOFF*DIM; L=wl+(size_t)VOFF*DIM; N=KVDIM; local=bid-5120; }
        int nbx = N >> 5;
        int tn = (local % nbx) * 32;
        int tk = (local / nbx) * 32;
        int tx = tid & 31, ty = tid >> 5;   // 32 x 8

        #pragma unroll
        for (int i = 0; i < 4; i++) {
            int k = tk + ty + i*8;
            int n = tn + tx;
            float s = W[(size_t)k * N + n];
            #pragma unroll
            for (int r = 0; r < RANK; r++)
                s += A[k*RANK + r] * Bm[r*N + n];
            tile[ty + i*8][tx] = s;
        }
        __syncthreads();
        #pragma unroll
        for (int i = 0; i < 4; i++) {
            int n = tn + ty + i*8;
            int k = tk + tx;
            float s = tile[tx][ty + i*8];
            __nv_bfloat16 h = __float2bfloat16_rn(s);
            H[(size_t)n * DIM + k] = h;
            L[(size_t)n * DIM + k] = __float2bfloat16_rn(s - __bfloat162float(h));
        }
    } else if (bid < PRO_EFFW) {
        int local = bid - 6144;             // Wp: fp16 single
        int nbx = DIM >> 5;
        int tn = (local % nbx) * 32;
        int tk = (local / nbx) * 32;
        int tx = tid & 31, ty = tid >> 5;

        #pragma unroll
        for (int i = 0; i < 4; i++) {
            int k = tk + ty + i*8;
            int n = tn + tx;
            float s = Wp[(size_t)k * DIM + n];
            #pragma unroll
            for (int r = 0; r < RANK; r++)
                s += pA[k*RANK + r] * pB[r*DIM + n];
            tile[ty + i*8][tx] = s;
        }
        __syncthreads();
        #pragma unroll
        for (int i = 0; i < 4; i++) {
            int n = tn + ty + i*8;
            int k = tk + tx;
            wpf[(size_t)n * DIM + k] = __float2half_rn(tile[tx][ty + i*8]);
        }
    } else {
        int idx = (bid - PRO_EFFW) * 256 + tid;
        float4 v = ((const float4*)x)[idx];
        __nv_bfloat16 h0 = __float2bfloat16_rn(v.x), h1 = __float2bfloat16_rn(v.y);
        __nv_bfloat16 h2 = __float2bfloat16_rn(v.z), h3 = __float2bfloat16_rn(v.w);
        __nv_bfloat162 hh0 = {h0, h1}, hh1 = {h2, h3};
        __nv_bfloat162 ll0 = {__float2bfloat16_rn(v.x - __bfloat162float(h0)),
                              __float2bfloat16_rn(v.y - __bfloat162float(h1))};
        __nv_bfloat162 ll1 = {__float2bfloat16_rn(v.z - __bfloat162float(h2)),
                              __float2bfloat16_rn(v.w - __bfloat162float(h3))};
        ((__nv_bfloat162*)xh)[idx*2]   = hh0;
        ((__nv_bfloat162*)xh)[idx*2+1] = hh1;
        ((__nv_bfloat162*)xl)[idx*2]   = ll0;
        ((__nv_bfloat162*)xl)[idx*2+1] = ll1;
    }
}

// ---------------- GEMM common ------------------------------------------------
#define TBM 128
#define TBN 128
#define TBK 32
#define STR 40

__device__ __forceinline__ void cpa16(uint32_t dst, const void* src) {
    asm volatile("cp.async.cg.shared.global [%0], [%1], 16;\n" :: "r"(dst), "l"(src));
}
__device__ __forceinline__ void cpa_commit() {
    asm volatile("cp.async.commit_group;\n");
}
__device__ __forceinline__ void cpa_wait0() {
    asm volatile("cp.async.wait_group 0;\n");
}
__device__ __forceinline__ void ldsm_x4(uint32_t& r0, uint32_t& r1, uint32_t& r2, uint32_t& r3,
                                        uint32_t addr) {
    asm volatile("ldmatrix.sync.aligned.m8n8.x4.shared.b16 {%0,%1,%2,%3}, [%4];"
                 : "=r"(r0), "=r"(r1), "=r"(r2), "=r"(r3) : "r"(addr));
}
__device__ __forceinline__ void mma_bf16(float& d0, float& d1, float& d2, float& d3,
                                         uint32_t a0, uint32_t a1, uint32_t a2, uint32_t a3,
                                         uint32_t b0, uint32_t b1) {
    asm volatile(
        "mma.sync.aligned.m16n8k16.row.col.f32.bf16.bf16.f32 "
        "{%0,%1,%2,%3}, {%4,%5,%6,%7}, {%8,%9}, {%0,%1,%2,%3};\n"
        : "+f"(d0), "+f"(d1), "+f"(d2), "+f"(d3)
        : "r"(a0), "r"(a1), "r"(a2), "r"(a3), "r"(b0), "r"(b1));
}
__device__ __forceinline__ void mma_f16(float& d0, float& d1, float& d2, float& d3,
                                        uint32_t a0, uint32_t a1, uint32_t a2, uint32_t a3,
                                        uint32_t b0, uint32_t b1) {
    asm volatile(
        "mma.sync.aligned.m16n8k16.row.col.f32.f16.f16.f32 "
        "{%0,%1,%2,%3}, {%4,%5,%6,%7}, {%8,%9}, {%0,%1,%2,%3};\n"
        : "+f"(d0), "+f"(d1), "+f"(d2), "+f"(d3)
        : "r"(a0), "r"(a1), "r"(a2), "r"(a3), "r"(b0), "r"(b1));
}

// ---------------- bf16x3 GEMM (QKV projection) ------------------------------
template<int N, int K>
__global__ __launch_bounds__(128)
void bf16x3gemm_kernel(const __nv_bfloat16* __restrict__ Ah,
                       const __nv_bfloat16* __restrict__ Al,
                       const __nv_bfloat16* __restrict__ Bh,   // [N][K]
                       const __nv_bfloat16* __restrict__ Bl,
                       float* __restrict__ C)
{
    extern __shared__ __nv_bfloat16 smem[];
    __nv_bfloat16* sAh = smem;
    __nv_bfloat16* sAl = sAh + 2*TBM*STR;
    __nv_bfloat16* sBh = sAl + 2*TBM*STR;
    __nv_bfloat16* sBl = sBh + 2*TBN*STR;

    int tid  = threadIdx.x;
    int warp = tid >> 5, lane = tid & 31;
    int warpM = warp >> 1, warpN = warp & 1;
    int gid = lane >> 2, tig = lane & 3;

    const __nv_bfloat16* Ahb = Ah + (size_t)blockIdx.y * TBM * K;
    const __nv_bfloat16* Alb = Al + (size_t)blockIdx.y * TBM * K;
    const __nv_bfloat16* Bhb = Bh + (size_t)blockIdx.x * TBN * K;
    const __nv_bfloat16* Blb = Bl + (size_t)blockIdx.x * TBN * K;
    float* Cb = C + (size_t)blockIdx.y * TBM * N + (size_t)blockIdx.x * TBN;

    int srow = tid >> 2;
    int scol = (tid & 3) * 8;

    uint32_t uAh = (uint32_t)__cvta_generic_to_shared(sAh);
    uint32_t uAl = (uint32_t)__cvta_generic_to_shared(sAl);
    uint32_t uBh = (uint32_t)__cvta_generic_to_shared(sBh);
    uint32_t uBl = (uint32_t)__cvta_generic_to_shared(sBl);

    uint32_t laneA = (uint32_t)(((lane & 15) * STR + (lane >> 4) * 8) * 2);
    uint32_t laneB = (uint32_t)((((lane & 7) + ((lane >> 4) << 3)) * STR) * 2 + ((lane >> 3) & 1) * 16);

    float acc[4][8][4];
    #pragma unroll
    for (int m = 0; m < 4; m++)
        #pragma unroll
        for (int n = 0; n < 8; n++)
            #pragma unroll
            for (int i = 0; i < 4; i++) acc[m][n][i] = 0.0f;

    constexpr int ntiles = K / TBK;

    auto issue = [&](int buf, int kt) {
        uint32_t bofs = (uint32_t)(buf * TBM * STR * 2);
        #pragma unroll
        for (int i = 0; i < 4; i++) {
            int r = srow + i * 32;
            uint32_t dofs = (uint32_t)((r * STR + scol) * 2);
            size_t gofs = (size_t)r * K + (size_t)kt * TBK + scol;
            cpa16(uAh + bofs + dofs, Ahb + gofs);
            cpa16(uAl + bofs + dofs, Alb + gofs);
            cpa16(uBh + bofs + dofs, Bhb + gofs);
            cpa16(uBl + bofs + dofs, Blb + gofs);
        }
        cpa_commit();
    };

    issue(0, 0);
    int buf = 0;

    for (int kt = 0; kt < ntiles; kt++) {
        cpa_wait0();
        __syncthreads();
        if (kt + 1 < ntiles) issue(buf ^ 1, kt + 1);

        uint32_t bufofs = (uint32_t)(buf * TBM * STR * 2);
        uint32_t aH = uAh + bufofs, aL = uAl + bufofs;
        uint32_t bH = uBh + bufofs, bL = uBl + bufofs;

        #pragma unroll
        for (int ks = 0; ks < TBK; ks += 16) {
            uint32_t afh[4][4], afl[4][4];
            #pragma unroll
            for (int mt = 0; mt < 4; mt++) {
                uint32_t ofs = (uint32_t)(((warpM*64 + mt*16) * STR + ks) * 2) + laneA;
                ldsm_x4(afh[mt][0], afh[mt][1], afh[mt][2], afh[mt][3], aH + ofs);
                ldsm_x4(afl[mt][0], afl[mt][1], afl[mt][2], afl[mt][3], aL + ofs);
            }
            uint32_t bfh[8][2], bfl[8][2];
            #pragma unroll
            for (int np = 0; np < 4; np++) {
                uint32_t ofs = (uint32_t)(((warpN*64 + np*16) * STR + ks) * 2) + laneB;
                ldsm_x4(bfh[2*np][0], bfh[2*np][1], bfh[2*np+1][0], bfh[2*np+1][1], bH + ofs);
                ldsm_x4(bfl[2*np][0], bfl[2*np][1], bfl[2*np+1][0], bfl[2*np+1][1], bL + ofs);
            }
            #pragma unroll
            for (int mt = 0; mt < 4; mt++)
                #pragma unroll
                for (int nt = 0; nt < 8; nt++)
                    mma_bf16(acc[mt][nt][0], acc[mt][nt][1], acc[mt][nt][2], acc[mt][nt][3],
                             afh[mt][0], afh[mt][1], afh[mt][2], afh[mt][3],
                             bfh[nt][0], bfh[nt][1]);
            #pragma unroll
            for (int mt = 0; mt < 4; mt++)
                #pragma unroll
                for (int nt = 0; nt < 8; nt++)
                    mma_bf16(acc[mt][nt][0], acc[mt][nt][1], acc[mt][nt][2], acc[mt][nt][3],
                             afh[mt][0], afh[mt][1], afh[mt][2], afh[mt][3],
                             bfl[nt][0], bfl[nt][1]);
            #pragma unroll
            for (int mt = 0; mt < 4; mt++)
                #pragma unroll
                for (int nt = 0; nt < 8; nt++)
                    mma_bf16(acc[mt][nt][0], acc[mt][nt][1], acc[mt][nt][2], acc[mt][nt][3],
                             afl[mt][0], afl[mt][1], afl[mt][2], afl[mt][3],
                             bfh[nt][0], bfh[nt][1]);
        }
        __syncthreads();
        buf ^= 1;
    }

    #pragma unroll
    for (int mt = 0; mt < 4; mt++) {
        int r0 = warpM*64 + mt*16 + gid;
        #pragma unroll
        for (int nt = 0; nt < 8; nt++) {
            int c0 = warpN*64 + nt*8 + tig*2;
            *(float2*)(Cb + (size_t) r0      * N + c0) = make_float2(acc[mt][nt][0], acc[mt][nt][1]);
            *(float2*)(Cb + (size_t)(r0 + 8) * N + c0) = make_float2(acc[mt][nt][2], acc[mt][nt][3]);
        }
    }
}

// ---------------- fp16 2-term GEMM (output projection) ----------------------
// C = (Ah + Al) @ Bf^T, A split exactly into fp16 hi/lo, Bf fp16 [N][K].
template<int N, int K>
__global__ __launch_bounds__(128)
void f16x2gemm_kernel(const __half* __restrict__ Ah,
                      const __half* __restrict__ Al,
                      const __half* __restrict__ Bf,   // [N][K]
                      float* __restrict__ C)
{
    extern __shared__ __half smemh[];
    __half* sAh = smemh;
    __half* sAl = sAh + 2*TBM*STR;
    __half* sB  = sAl + 2*TBM*STR;

    int tid  = threadIdx.x;
    int warp = tid >> 5, lane = tid & 31;
    int warpM = warp >> 1, warpN = warp & 1;
    int gid = lane >> 2, tig = lane & 3;

    const __half* Ahb = Ah + (size_t)blockIdx.y * TBM * K;
    const __half* Alb = Al + (size_t)blockIdx.y * TBM * K;
    const __half* Bb  = Bf + (size_t)blockIdx.x * TBN * K;
    float* Cb = C + (size_t)blockIdx.y * TBM * N + (size_t)blockIdx.x * TBN;

    int srow = tid >> 2;
    int scol = (tid & 3) * 8;

    uint32_t uAh = (uint32_t)__cvta_generic_to_shared(sAh);
    uint32_t uAl = (uint32_t)__cvta_generic_to_shared(sAl);
    uint32_t uB  = (uint32_t)__cvta_generic_to_shared(sB);

    uint32_t laneA = (uint32_t)(((lane & 15) * STR + (lane >> 4) * 8) * 2);
    uint32_t laneB = (uint32_t)((((lane & 7) + ((lane >> 4) << 3)) * STR) * 2 + ((lane >> 3) & 1) * 16);

    float acc[4][8][4];
    #pragma unroll
    for (int m = 0; m < 4; m++)
        #pragma unroll
        for (int n = 0; n < 8; n++)
            #pragma unroll
            for (int i = 0; i < 4; i++) acc[m][n][i] = 0.0f;

    constexpr int ntiles = K / TBK;

    auto issue = [&](int buf, int kt) {
        uint32_t bofs = (uint32_t)(buf * TBM * STR * 2);
        #pragma unroll
        for (int i = 0; i < 4; i++) {
            int r = srow + i * 32;
            uint32_t dofs = (uint32_t)((r * STR + scol) * 2);
            size_t gofs = (size_t)r * K + (size_t)kt * TBK + scol;
            cpa16(uAh + bofs + dofs, Ahb + gofs);
            cpa16(uAl + bofs + dofs, Alb + gofs);
            cpa16(uB  + bofs + dofs, Bb  + gofs);
        }
        cpa_commit();
    };

    issue(0, 0);
    int buf = 0;

    for (int kt = 0; kt < ntiles; kt++) {
        cpa_wait0();
        __syncthreads();
        if (kt + 1 < ntiles) issue(buf ^ 1, kt + 1);

        uint32_t bufofs = (uint32_t)(buf * TBM * STR * 2);
        uint32_t aH = uAh + bufofs, aL = uAl + bufofs;
        uint32_t bB = uB + bufofs;

        #pragma unroll
        for (int ks = 0; ks < TBK; ks += 16) {
            uint32_t afh[4][4], afl[4][4];
            #pragma unroll
            for (int mt = 0; mt < 4; mt++) {
                uint32_t ofs = (uint32_t)(((warpM*64 + mt*16) * STR + ks) * 2) + laneA;
                ldsm_x4(afh[mt][0], afh[mt][1], afh[mt][2], afh[mt][3], aH + ofs);
                ldsm_x4(afl[mt][0], afl[mt][1], afl[mt][2], afl[mt][3], aL + ofs);
            }
            uint32_t bf[8][2];
            #pragma unroll
            for (int np = 0; np < 4; np++) {
                uint32_t ofs = (uint32_t)(((warpN*64 + np*16) * STR + ks) * 2) + laneB;
                ldsm_x4(bf[2*np][0], bf[2*np][1], bf[2*np+1][0], bf[2*np+1][1], bB + ofs);
            }
            #pragma unroll
            for (int mt = 0; mt < 4; mt++)
                #pragma unroll
                for (int nt = 0; nt < 8; nt++)
                    mma_f16(acc[mt][nt][0], acc[mt][nt][1], acc[mt][nt][2], acc[mt][nt][3],
                            afh[mt][0], afh[mt][1], afh[mt][2], afh[mt][3],
                            bf[nt][0], bf[nt][1]);
            #pragma unroll
            for (int mt = 0; mt < 4; mt++)
                #pragma unroll
                for (int nt = 0; nt < 8; nt++)
                    mma_f16(acc[mt][nt][0], acc[mt][nt][1], acc[mt][nt][2], acc[mt][nt][3],
                            afl[mt][0], afl[mt][1], afl[mt][2], afl[mt][3],
                            bf[nt][0], bf[nt][1]);
        }
        __syncthreads();
        buf ^= 1;
    }

    #pragma unroll
    for (int mt = 0; mt < 4; mt++) {
        int r0 = warpM*64 + mt*16 + gid;
        #pragma unroll
        for (int nt = 0; nt < 8; nt++) {
            int c0 = warpN*64 + nt*8 + tig*2;
            *(float2*)(Cb + (size_t) r0      * N + c0) = make_float2(acc[mt][nt][0], acc[mt][nt][1]);
            *(float2*)(Cb + (size_t)(r0 + 8) * N + c0) = make_float2(acc[mt][nt][2], acc[mt][nt][3]);
        }
    }
}

// ---- fused mid: normrope (fp16 q/k) + V transpose, one grid ---------------
#define MID_NR    10240
#define MID_TOTAL 12288

__global__ __launch_bounds__(256)
void mid_kernel(const float* __restrict__ QKV,
                const float* __restrict__ gain,
                __half* __restrict__ Qh,
                __half* __restrict__ Kh,
                __half* __restrict__ Vt)
{
    __shared__ float tile[32][33];
    int bid = blockIdx.x;
    int tid = threadIdx.x;

    if (bid < MID_NR) {
        int gthr = bid * 256 + tid;
        int w    = gthr >> 5;
        int lane = gthr & 31;

        const float* src;
        __half* dst;
        float g = 1.0f;
        int bt;
        if (w < BT * NH) {
            bt = w / NH;
            int hh = w % NH;
            src = QKV + (size_t)bt * QKVD + hh * HD;
            dst = Qh  + (size_t)bt * DIM  + hh * HD;
            g = gain[hh];
        } else {
            int w2 = w - BT * NH;
            bt = w2 / NHKV;
            int hh = w2 % NHKV;
            src = QKV + (size_t)bt * QKVD + KOFF + hh * HD;
            dst = Kh  + (size_t)bt * KVDIM + hh * HD;
        }
        int t = bt % TSEQ;

        float v0 = src[lane], v1 = src[lane+32], v2 = src[lane+64], v3 = src[lane+96];
        float ss = v0*v0 + v1*v1 + v2*v2 + v3*v3;
        #pragma unroll
        for (int o = 16; o; o >>= 1) ss += __shfl_xor_sync(0xffffffffu, ss, o);

        float f = rsqrtf(ss * (1.0f/128.0f) + 1.1920929e-7f) * g;

        float invfreq = powf(10000.0f, -(float)lane * (1.0f/32.0f));
        float ang = (float)t * invfreq;
        float s, c;
        sincosf(ang, &s, &c);

        dst[lane]    = __float2half(( v0*c + v1*s) * f);
        dst[lane+32] = __float2half((-v0*s + v1*c) * f);
        dst[lane+64] = __float2half(v2 * f);
        dst[lane+96] = __float2half(v3 * f);
    } else {
        int local = bid - MID_NR;
        int t0 = (local & 63) * 32;
        int c0 = ((local >> 6) & 3) * 32;
        int bk = local >> 8;
        int b  = bk / NHKV, kh = bk % NHKV;
        int tx = tid & 31, ty = tid >> 5;

        #pragma unroll
        for (int i = 0; i < 4; i++) {
            int t = t0 + ty + i*8;
            tile[ty + i*8][tx] = QKV[(size_t)(b*TSEQ + t) * QKVD + VOFF + kh*HD + c0 + tx];
        }
        __syncthreads();
        #pragma unroll
        for (int i = 0; i < 4; i++) {
            int c = c0 + ty + i*8;
            Vt[((size_t)bk * HD + c) * TSEQ + t0 + tx] = __float2half(tile[tx][ty + i*8]);
        }
    }
}

// -------- fp16 tensor-core causal flash attention (paired q-tiles) ---------
#define AQ   128
#define AK   64
#define NQT  (TSEQ/AQ)   // 16
#define QSTR 136
#define KSTR 136
#define VSTR 72
#define K_TILE_B  (AK*KSTR*2)   // 17408
#define V_TILE_B  (HD*VSTR*2)   // 18432
#define ATT_SMEM_H (AQ*QSTR*2 + 2*K_TILE_B + 2*V_TILE_B)   // 106496 bytes

__global__ __launch_bounds__(256)
void attn_mma_kernel(const __half* __restrict__ Qh,
                     const __half* __restrict__ Kh,
                     const __half* __restrict__ Vth,
                     float* __restrict__ Y)
{
    extern __shared__ __half smh[];
    __half* Qs  = smh;                    // [AQ][QSTR]
    __half* Ksm = Qs + AQ*QSTR;           // 2 x [AK][KSTR]
    __half* Vsm = Ksm + 2*AK*KSTR;        // 2 x [HD][VSTR]

    int bx = blockIdx.x, h = blockIdx.y, b = blockIdx.z;
    int kh = h / GROUP;
    int tid = threadIdx.x;
    int warp = tid >> 5, lane = tid & 31;
    int gid = lane >> 2, tig = lane & 3;
    int wr = warp * 16;

    const float scale = 0.08838834764831845f * 1.4426950408889634f;

    uint32_t uK = (uint32_t)__cvta_generic_to_shared(Ksm);
    uint32_t uV = (uint32_t)__cvta_generic_to_shared(Vsm);

    const __half* Kbase = Kh  + (size_t)(b*TSEQ)*KVDIM + kh*HD;
    const __half* Vbase = Vth + ((size_t)(b*NHKV + kh))*HD*TSEQ;

    int kr  = tid >> 2;
    int kcb = (tid & 3) * 4;
    int vr  = tid >> 1;
    int vcb = (tid & 1) * 4;
    auto prefetch = [&](int s, int kt) {
        int s0 = kt * AK;
        uint32_t kd = uK + (uint32_t)s * K_TILE_B;
        const __half* ksrc = Kbase + (size_t)(s0 + kr) * KVDIM;
        #pragma unroll
        for (int j = 0; j < 4; j++)
            cpa16(kd + (uint32_t)(kr*KSTR + (kcb+j)*8)*2, ksrc + (kcb+j)*8);
        uint32_t vd = uV + (uint32_t)s * V_TILE_B;
        const __half* vsrc = Vbase + (size_t)vr * TSEQ + s0;
        #pragma unroll
        for (int j = 0; j < 4; j++)
            cpa16(vd + (uint32_t)(vr*VSTR + (vcb+j)*8)*2, vsrc + (vcb+j)*8);
        cpa_commit();
    };

    #pragma unroll 1
    for (int sub = 0; sub < 2; sub++) {
        int qt = sub ? (NQT - 1 - bx) : bx;
        int q0 = qt * AQ;

        __syncthreads();

        for (int e = tid; e < AQ*16; e += 256) {
            int r = e >> 4, c = e & 15;
            *(uint4*)(Qs + r*QSTR + c*8) =
                *(const uint4*)(Qh + (size_t)(b*TSEQ + q0 + r)*DIM + h*HD + c*8);
        }

        float m0 = -CUDART_INF_F, m1 = -CUDART_INF_F;
        float l0 = 0.0f, l1 = 0.0f;
        float o[16][4];
        #pragma unroll
        for (int on = 0; on < 16; on++)
            #pragma unroll
            for (int i = 0; i < 4; i++) o[on][i] = 0.0f;

        int nkt = 2*qt + 2;
        prefetch(0, 0);

        for (int kt = 0; kt < nkt; kt++) {
            int s0 = kt * AK;
            cpa_wait0();
            __syncthreads();
            if (kt + 1 < nkt) prefetch((kt + 1) & 1, kt + 1);

            const __half* Ks = Ksm + (kt & 1) * AK*KSTR;
            const __half* Vt = Vsm + (kt & 1) * HD*VSTR;

            float sacc[8][4];
            #pragma unroll
            for (int nt = 0; nt < 8; nt++)
                #pragma unroll
                for (int i = 0; i < 4; i++) sacc[nt][i] = 0.0f;

            #pragma unroll
            for (int ks = 0; ks < 8; ks++) {
                const __half* qb = Qs + (wr + gid)*QSTR + ks*16 + 2*tig;
                uint32_t a0 = *(const uint32_t*)(qb);
                uint32_t a1 = *(const uint32_t*)(qb + 8*QSTR);
                uint32_t a2 = *(const uint32_t*)(qb + 8);
                uint32_t a3 = *(const uint32_t*)(qb + 8*QSTR + 8);
                #pragma unroll
                for (int nt = 0; nt < 8; nt++) {
                    const __half* kb = Ks + (nt*8 + gid)*KSTR + ks*16 + 2*tig;
                    uint32_t b0 = *(const uint32_t*)(kb);
                    uint32_t b1 = *(const uint32_t*)(kb + 8);
                    mma_f16(sacc[nt][0], sacc[nt][1], sacc[nt][2], sacc[nt][3],
                            a0, a1, a2, a3, b0, b1);
                }
            }

            #pragma unroll
            for (int nt = 0; nt < 8; nt++)
                #pragma unroll
                for (int i = 0; i < 4; i++) sacc[nt][i] *= scale;

            if (s0 + AK - 1 > q0 + wr) {
                int r0g = q0 + wr + gid;
                #pragma unroll
                for (int nt = 0; nt < 8; nt++) {
                    int sb = s0 + nt*8 + 2*tig;
                    if (sb     > r0g)     sacc[nt][0] = -CUDART_INF_F;
                    if (sb + 1 > r0g)     sacc[nt][1] = -CUDART_INF_F;
                    if (sb     > r0g + 8) sacc[nt][2] = -CUDART_INF_F;
                    if (sb + 1 > r0g + 8) sacc[nt][3] = -CUDART_INF_F;
                }
            }

            float mx0 = -CUDART_INF_F, mx1 = -CUDART_INF_F;
            #pragma unroll
            for (int nt = 0; nt < 8; nt++) {
                mx0 = fmaxf(mx0, fmaxf(sacc[nt][0], sacc[nt][1]));
                mx1 = fmaxf(mx1, fmaxf(sacc[nt][2], sacc[nt][3]));
            }
            #pragma unroll
            for (int off = 1; off <= 2; off <<= 1) {
                mx0 = fmaxf(mx0, __shfl_xor_sync(0xffffffffu, mx0, off));
                mx1 = fmaxf(mx1, __shfl_xor_sync(0xffffffffu, mx1, off));
            }
            float mn0 = fmaxf(m0, mx0), mn1 = fmaxf(m1, mx1);
            float corr0 = fexp2(m0 - mn0), corr1 = fexp2(m1 - mn1);
            m0 = mn0; m1 = mn1;

            float sum0 = 0.0f, sum1 = 0.0f;
            #pragma unroll
            for (int nt = 0; nt < 8; nt++) {
                sacc[nt][0] = fexp2(sacc[nt][0] - mn0);
                sacc[nt][1] = fexp2(sacc[nt][1] - mn0);
                sacc[nt][2] = fexp2(sacc[nt][2] - mn1);
                sacc[nt][3] = fexp2(sacc[nt][3] - mn1);
                sum0 += sacc[nt][0] + sacc[nt][1];
                sum1 += sacc[nt][2] + sacc[nt][3];
            }
            #pragma unroll
            for (int off = 1; off <= 2; off <<= 1) {
                sum0 += __shfl_xor_sync(0xffffffffu, sum0, off);
                sum1 += __shfl_xor_sync(0xffffffffu, sum1, off);
            }
            l0 = l0 * corr0 + sum0;
            l1 = l1 * corr1 + sum1;

            // skip O-rescale when no lane's max advanced (corr == 1 exactly)
            if (__any_sync(0xffffffffu, (corr0 < 1.0f) || (corr1 < 1.0f))) {
                #pragma unroll
                for (int on = 0; on < 16; on++) {
                    o[on][0] *= corr0; o[on][1] *= corr0;
                    o[on][2] *= corr1; o[on][3] *= corr1;
                }
            }

            #pragma unroll
            for (int ks2 = 0; ks2 < 4; ks2++) {
                __half2 pa0 = __floats2half2_rn(sacc[2*ks2][0],   sacc[2*ks2][1]);
                __half2 pa1 = __floats2half2_rn(sacc[2*ks2][2],   sacc[2*ks2][3]);
                __half2 pa2 = __floats2half2_rn(sacc[2*ks2+1][0], sacc[2*ks2+1][1]);
                __half2 pa3 = __floats2half2_rn(sacc[2*ks2+1][2], sacc[2*ks2+1][3]);
                uint32_t a0 = *reinterpret_cast<uint32_t*>(&pa0);
                uint32_t a1 = *reinterpret_cast<uint32_t*>(&pa1);
                uint32_t a2 = *reinterpret_cast<uint32_t*>(&pa2);
                uint32_t a3 = *reinterpret_cast<uint32_t*>(&pa3);
                #pragma unroll
                for (int on = 0; on < 16; on++) {
                    const __half* vb = Vt + (on*8 + gid)*VSTR + ks2*16 + 2*tig;
                    uint32_t b0 = *(const uint32_t*)(vb);
                    uint32_t b1 = *(const uint32_t*)(vb + 8);
                    mma_f16(o[on][0], o[on][1], o[on][2], o[on][3],
                            a0, a1, a2, a3, b0, b1);
                }
            }
        }

        float il0 = 1.0f / l0, il1 = 1.0f / l1;
        int r0 = q0 + wr + gid;
        #pragma unroll
        for (int on = 0; on < 16; on++) {
            int c0 = h*HD + on*8 + 2*tig;
            *(float2*)(Y + (size_t)(b*TSEQ + r0)     * DIM + c0) = make_float2(o[on][0]*il0, o[on][1]*il0);
            *(float2*)(Y + (size_t)(b*TSEQ + r0 + 8) * DIM + c0) = make_float2(o[on][2]*il1, o[on][3]*il1);
        }
    }
}

// ---- v-direction projection removal, fused with fp16 hi/lo split ----------
__global__ void vproj_split_kernel(const float* __restrict__ V, int vstride,
                                   const float* __restrict__ Yin,
                                   __half* __restrict__ YH,
                                   __half* __restrict__ YL)
{
    int gthr = blockIdx.x * blockDim.x + threadIdx.x;
    int w    = gthr >> 5;
    int lane = gthr & 31;
    if (w >= BT * NHKV) return;
    int bt = w / NHKV, kh = w % NHKV;

    const float* vrow = V + (size_t)bt * vstride + kh * HD;
    float v0 = vrow[lane], v1 = vrow[lane+32], v2 = vrow[lane+64], v3 = vrow[lane+96];
    float ss = v0*v0 + v1*v1 + v2*v2 + v3*v3;
    #pragma unroll
    for (int o = 16; o; o >>= 1) ss += __shfl_xor_sync(0xffffffffu, ss, o);
    float norm = sqrtf(ss);
    float inv = 1.0f / fmaxf(norm, 1e-12f);
    float n0 = v0*inv, n1 = v1*inv, n2 = v2*inv, n3 = v3*inv;

    #pragma unroll
    for (int g = 0; g < GROUP; g++) {
        int hh = kh * GROUP + g;
        size_t base = (size_t)bt * DIM + hh * HD;
        const float* yrow = Yin + base;
        float y0 = yrow[lane], y1 = yrow[lane+32], y2 = yrow[lane+64], y3 = yrow[lane+96];
        float d = y0*n0 + y1*n1 + y2*n2 + y3*n3;
        #pragma unroll
        for (int o = 16; o; o >>= 1) d += __shfl_xor_sync(0xffffffffu, d, o);
        float r0 = y0 - d*n0, r1 = y1 - d*n1, r2 = y2 - d*n2, r3 = y3 - d*n3;

        __half h0 = __float2half_rn(r0), h1 = __float2half_rn(r1);
        __half h2 = __float2half_rn(r2), h3 = __float2half_rn(r3);
        YH[base + lane]    = h0;  YL[base + lane]    = __float2half_rn(r0 - __half2float(h0));
        YH[base + lane+32] = h1;  YL[base + lane+32] = __float2half_rn(r1 - __half2float(h1));
        YH[base + lane+64] = h2;  YL[base + lane+64] = __float2half_rn(r2 - __half2float(h2));
        YH[base + lane+96] = h3;  YL[base + lane+96] = __float2half_rn(r3 - __half2float(h3));
    }
}

// ---------------- launcher --------------------------------------------------
extern "C" void kernel_launch(void* const* d_in, const int* in_sizes, int n_in,
                              void* d_out, int out_size)
{
    const float* x     = (const float*)d_in[0];
    const float* Wq    = (const float*)d_in[1];
    const float* Wk    = (const float*)d_in[2];
    const float* Wv    = (const float*)d_in[3];
    const float* Wp    = (const float*)d_in[4];
    const float* qgain = (const float*)d_in[5];
    const float* qA    = (const float*)d_in[6];
    const float* qB    = (const float*)d_in[7];
    const float* kA    = (const float*)d_in[8];
    const float* kB    = (const float*)d_in[9];
    const float* vA    = (const float*)d_in[10];
    const float* vB    = (const float*)d_in[11];
    const float* pA    = (const float*)d_in[12];
    const float* pB    = (const float*)d_in[13];
    float* out = (float*)d_out;

    __nv_bfloat16 *wh, *wl, *xh, *xl;
    __half *wpf, *yh, *yl, *qh, *kh2, *vth;
    float *qkv, *y;
    cudaGetSymbolAddress((void**)&wh,  g_WqkvTh); cudaGetSymbolAddress((void**)&wl,  g_WqkvTl);
    cudaGetSymbolAddress((void**)&wpf, g_Wpf);
    cudaGetSymbolAddress((void**)&xh,  g_xh);     cudaGetSymbolAddress((void**)&xl,  g_xl);
    cudaGetSymbolAddress((void**)&yh,  g_yh);     cudaGetSymbolAddress((void**)&yl,  g_yl);
    cudaGetSymbolAddress((void**)&qkv, g_qkv);
    cudaGetSymbolAddress((void**)&y,   g_y);
    cudaGetSymbolAddress((void**)&qh,  g_qh);
    cudaGetSymbolAddress((void**)&kh2, g_kh);
    cudaGetSymbolAddress((void**)&vth, g_vth);

    const int GSMEM  = (8*TBM*STR) * (int)sizeof(__nv_bfloat16);   // 81920
    const int GSMEM2 = (6*TBM*STR) * (int)sizeof(__half);          // 61440
    cudaFuncSetAttribute(bf16x3gemm_kernel<QKVD, DIM>, cudaFuncAttributeMaxDynamicSharedMemorySize, GSMEM);
    cudaFuncSetAttribute(f16x2gemm_kernel<DIM, DIM>,   cudaFuncAttributeMaxDynamicSharedMemorySize, GSMEM2);
    cudaFuncSetAttribute(attn_mma_kernel, cudaFuncAttributeMaxDynamicSharedMemorySize, ATT_SMEM_H);

    // launch 0: fused prologue (effw q/k/v bf16 split, Wp fp16, x-split)
    prologue_kernel<<<PRO_TOTAL, 256>>>(
        x,
        Wq, qA, qB,  Wk, kA, kB,  Wv, vA, vB,  Wp, pA, pB,
        wh, wl, wpf, xh, xl);

    // launch 1: fused qkv projection (bf16x3 + ldmatrix), N = 3072
    dim3 gqkv(QKVD/TBN, BT/TBM);
    bf16x3gemm_kernel<QKVD, DIM><<<gqkv, 128, GSMEM>>>(xh, xl, wh, wl, qkv);

    // launch 2: fused normrope->fp16 + V transpose
    mid_kernel<<<MID_TOTAL, 256>>>(qkv, qgain, qh, kh2, vth);

    // launch 3: causal flash attention (paired q-tiles, rescale-skip)
    {
        dim3 ga(NQT/2, NH, BSZ);
        attn_mma_kernel<<<ga, 256, ATT_SMEM_H>>>(qh, kh2, vth, y);
    }

    // launch 4: v-projection removal + fp16 split
    {
        int wv_n = BT * NHKV;
        vproj_split_kernel<<<(wv_n*32 + 255)/256, 256>>>(qkv + VOFF, QKVD, y, yh, yl);
    }

    // launch 5: output projection (fp16 2-term: exact-A x fp16-B)
    dim3 gp(DIM/TBN, BT/TBM);
    f16x2gemm_kernel<DIM, DIM><<<gp, 128, GSMEM2>>>(yh, yl, wpf, out);
}